// round 5
// baseline (speedup 1.0000x reference)
#include <cuda_runtime.h>
#include <math.h>

#define BB   2
#define SSL  1024
#define NTOK 2048
#define DD   512
#define HHN  8
#define DHH  64
#define HHI  4
#define DII  64
#define FFD  2048
#define EE   8
#define VV   32000
#define KTOP 256
#define NEGV (-1e9f)
#define EPSV 1e-5f
#define LLN  2
#define SCALE 0.125f

// ---------------- scratch ----------------
__device__ float g_x  [NTOK*DD];
__device__ float g_h  [NTOK*DD];
__device__ float g_m  [NTOK*DD];
__device__ float g_q  [NTOK*DD];
__device__ float g_k  [NTOK*DD];
__device__ float g_v  [NTOK*DD];
__device__ float g_ao [NTOK*DD];
__device__ float g_moe[NTOK*DD];
__device__ float g_qi [NTOK*HHI*DII];
__device__ float g_ki [NTOK*HHI*DII];
__device__ float g_mask[(size_t)BB*SSL*SSL];
__device__ float g_probs[NTOK*EE];
__device__ int   g_ecount[EE];
__device__ int   g_elist[EE*NTOK];
__device__ float g_egate[EE*NTOK];
__device__ float g_h1[(size_t)EE*NTOK*FFD];

__device__ __forceinline__ float gelu_tanh(float x){
    float x3 = x*x*x;
    return 0.5f*x*(1.f + tanhf(0.7978845608028654f*(x + 0.044715f*x3)));
}

__global__ void k_zerof(float* p, int n){
    int i = blockIdx.x*blockDim.x + threadIdx.x;
    if(i<n) p[i]=0.f;
}
__global__ void k_zeroi(int* p, int n){
    int i = threadIdx.x;
    if(i<n) p[i]=0;
}
__global__ void k_add(float* x, const float* y, int n){
    int i = blockIdx.x*blockDim.x + threadIdx.x;
    if(i<n) x[i]+=y[i];
}

// ---------------- embedding ----------------
__global__ void k_embed(const int* __restrict__ ids,
                        const float* __restrict__ tok,
                        const float* __restrict__ pos){
    int n = blockIdx.x; int t = threadIdx.x;
    int id = ids[n];
    int s  = n % SSL;
    g_x[(size_t)n*DD + t] = tok[(size_t)id*DD + t] + pos[(size_t)s*DD + t];
}

// ---------------- layernorm ----------------
__global__ __launch_bounds__(256) void k_ln(const float* __restrict__ in,
                                            const float* __restrict__ g,
                                            const float* __restrict__ b,
                                            float* __restrict__ out){
    int r = blockIdx.x; int t = threadIdx.x;
    __shared__ float red[256];
    float v0 = in[(size_t)r*DD + t];
    float v1 = in[(size_t)r*DD + t + 256];
    red[t] = v0 + v1;
    __syncthreads();
    for(int s=128;s>0;s>>=1){ if(t<s) red[t]+=red[t+s]; __syncthreads(); }
    float mu = red[0] * (1.0f/DD);
    __syncthreads();
    float d0 = v0-mu, d1 = v1-mu;
    red[t] = d0*d0 + d1*d1;
    __syncthreads();
    for(int s=128;s>0;s>>=1){ if(t<s) red[t]+=red[t+s]; __syncthreads(); }
    float rs = rsqrtf(red[0]*(1.0f/DD) + EPSV);
    out[(size_t)r*DD + t]       = d0*rs*g[t]     + b[t];
    out[(size_t)r*DD + t + 256] = d1*rs*g[t+256] + b[t+256];
}

// ========== high-throughput 128x128 SGEMM core (M%128==0, N%128==0, K%8==0) ==========
// 256 threads, 8x8 microtile, BK=8, double buffered, float4 global + shared.
struct B3 {
    const float *B0, *B1, *B2;
    const float *c0, *c1, *c2;
    float *C0, *C1, *C2;
};

__device__ __forceinline__ void gemm128_body(
    const float* __restrict__ A, const float* __restrict__ B,
    const float* __restrict__ bias, const float* __restrict__ res,
    float* __restrict__ C, int N, int K)
{
    __shared__ float As[2][8][132];
    __shared__ float Bs[2][8][128];
    int tid = threadIdx.x;
    int row0 = blockIdx.y*128, col0 = blockIdx.x*128;
    int arow = tid>>1,  acol = (tid&1)*4;
    int brow = tid>>5,  bcol = (tid&31)*4;
    const float* Aptr = A + (size_t)(row0+arow)*K + acol;
    const float* Bptr = B + (size_t)brow*N + col0 + bcol;

    float4 a4 = *(const float4*)Aptr;
    float4 b4 = *(const float4*)Bptr;
    As[0][acol+0][arow]=a4.x; As[0][acol+1][arow]=a4.y;
    As[0][acol+2][arow]=a4.z; As[0][acol+3][arow]=a4.w;
    *(float4*)&Bs[0][brow][bcol] = b4;
    __syncthreads();

    int tx = tid&15, ty = tid>>4;
    float acc[8][8] = {};
    int buf = 0;
    for(int k0=8;k0<=K;k0+=8){
        if(k0<K){
            a4 = *(const float4*)(Aptr + k0);
            b4 = *(const float4*)(Bptr + (size_t)k0*N);
        }
        #pragma unroll
        for(int kk=0;kk<8;kk++){
            float4 a0 = *(const float4*)&As[buf][kk][ty*8];
            float4 a1 = *(const float4*)&As[buf][kk][ty*8+4];
            float4 b0 = *(const float4*)&Bs[buf][kk][tx*8];
            float4 b1 = *(const float4*)&Bs[buf][kk][tx*8+4];
            float av[8]={a0.x,a0.y,a0.z,a0.w,a1.x,a1.y,a1.z,a1.w};
            float bv[8]={b0.x,b0.y,b0.z,b0.w,b1.x,b1.y,b1.z,b1.w};
            #pragma unroll
            for(int i=0;i<8;i++)
                #pragma unroll
                for(int j=0;j<8;j++)
                    acc[i][j] += av[i]*bv[j];
        }
        if(k0<K){
            buf ^= 1;
            As[buf][acol+0][arow]=a4.x; As[buf][acol+1][arow]=a4.y;
            As[buf][acol+2][arow]=a4.z; As[buf][acol+3][arow]=a4.w;
            *(float4*)&Bs[buf][brow][bcol] = b4;
            __syncthreads();
        }
    }
    #pragma unroll
    for(int i=0;i<8;i++){
        int r = row0 + ty*8 + i;
        #pragma unroll
        for(int j=0;j<8;j+=4){
            int c = col0 + tx*8 + j;
            float4 v = {acc[i][j],acc[i][j+1],acc[i][j+2],acc[i][j+3]};
            if(bias){
                float4 bb = *(const float4*)&bias[c];
                v.x+=bb.x; v.y+=bb.y; v.z+=bb.z; v.w+=bb.w;
            }
            if(res){
                float4 rr = *(const float4*)&res[(size_t)r*N + c];
                v.x+=rr.x; v.y+=rr.y; v.z+=rr.z; v.w+=rr.w;
            }
            *(float4*)&C[(size_t)r*N + c] = v;
        }
    }
}

__global__ __launch_bounds__(256) void k_gemm128(const float* __restrict__ A,
                                                 const float* __restrict__ B,
                                                 const float* __restrict__ bias,
                                                 const float* __restrict__ res,
                                                 float* __restrict__ C,
                                                 int N, int K){
    gemm128_body(A,B,bias,res,C,N,K);
}

__global__ __launch_bounds__(256) void k_gemm128b3(const float* __restrict__ A,
                                                   B3 p, int N, int K){
    const float *B, *bias; float *C;
    if(blockIdx.z==0){ B=p.B0; bias=p.c0; C=p.C0; }
    else if(blockIdx.z==1){ B=p.B1; bias=p.c1; C=p.C1; }
    else { B=p.B2; bias=p.c2; C=p.C2; }
    gemm128_body(A,B,bias,nullptr,C,N,K);
}

// ---------------- MoE GEMM1: gathered rows + GELU epilogue ----------------
// grid (FFD/128, NTOK/128, E)
__global__ __launch_bounds__(256) void k_moe1(const float* __restrict__ W1,
                                              const float* __restrict__ B1){
    int e = blockIdx.z;
    int cnt = g_ecount[e];
    int row0 = blockIdx.y*128;
    if(row0 >= cnt) return;
    int col0 = blockIdx.x*128;
    const float* W   = W1 + (size_t)e*DD*FFD;
    const float* bia = B1 + (size_t)e*FFD;
    __shared__ int trow[128];
    __shared__ float As[2][8][132];
    __shared__ float Bs[2][8][128];
    int tid = threadIdx.x;
    if(tid<128){
        int r = row0 + tid;
        trow[tid] = (r<cnt)? g_elist[e*NTOK + r] : g_elist[e*NTOK];
    }
    __syncthreads();
    int arow = tid>>1, acol = (tid&1)*4;
    int brow = tid>>5, bcol = (tid&31)*4;
    const float* Aptr = g_m + (size_t)trow[arow]*DD + acol;
    const float* Bptr = W + (size_t)brow*FFD + col0 + bcol;

    float4 a4 = *(const float4*)Aptr;
    float4 b4 = *(const float4*)Bptr;
    As[0][acol+0][arow]=a4.x; As[0][acol+1][arow]=a4.y;
    As[0][acol+2][arow]=a4.z; As[0][acol+3][arow]=a4.w;
    *(float4*)&Bs[0][brow][bcol] = b4;
    __syncthreads();

    int tx = tid&15, ty = tid>>4;
    float acc[8][8] = {};
    int buf = 0;
    for(int k0=8;k0<=DD;k0+=8){
        if(k0<DD){
            a4 = *(const float4*)(Aptr + k0);
            b4 = *(const float4*)(Bptr + (size_t)k0*FFD);
        }
        #pragma unroll
        for(int kk=0;kk<8;kk++){
            float4 a0 = *(const float4*)&As[buf][kk][ty*8];
            float4 a1 = *(const float4*)&As[buf][kk][ty*8+4];
            float4 b0 = *(const float4*)&Bs[buf][kk][tx*8];
            float4 b1 = *(const float4*)&Bs[buf][kk][tx*8+4];
            float av[8]={a0.x,a0.y,a0.z,a0.w,a1.x,a1.y,a1.z,a1.w};
            float bv[8]={b0.x,b0.y,b0.z,b0.w,b1.x,b1.y,b1.z,b1.w};
            #pragma unroll
            for(int i=0;i<8;i++)
                #pragma unroll
                for(int j=0;j<8;j++)
                    acc[i][j] += av[i]*bv[j];
        }
        if(k0<DD){
            buf ^= 1;
            As[buf][acol+0][arow]=a4.x; As[buf][acol+1][arow]=a4.y;
            As[buf][acol+2][arow]=a4.z; As[buf][acol+3][arow]=a4.w;
            *(float4*)&Bs[buf][brow][bcol] = b4;
            __syncthreads();
        }
    }
    float* H = g_h1 + (size_t)e*NTOK*FFD;
    #pragma unroll
    for(int i=0;i<8;i++){
        int r = row0 + ty*8 + i;
        if(r>=cnt) continue;
        #pragma unroll
        for(int j=0;j<8;j++){
            int c = col0 + tx*8 + j;
            H[(size_t)r*FFD + c] = gelu_tanh(acc[i][j] + bia[c]);
        }
    }
}

// ---------------- MoE GEMM2: split-K=2, gated atomic scatter ----------------
// grid (DD/128, NTOK/128, E*2)
__global__ __launch_bounds__(256) void k_moe2(const float* __restrict__ W2,
                                              const float* __restrict__ B2){
    int e = blockIdx.z >> 1;
    int s = blockIdx.z & 1;
    int cnt = g_ecount[e];
    int row0 = blockIdx.y*128;
    if(row0 >= cnt) return;
    int col0 = blockIdx.x*128;
    int kbeg = s * (FFD/2);
    const float* A  = g_h1 + (size_t)e*NTOK*FFD;
    const float* W  = W2 + (size_t)e*FFD*DD;
    const float* b2 = B2 + (size_t)e*DD;
    __shared__ float As[2][8][132];
    __shared__ float Bs[2][8][128];
    int tid = threadIdx.x;
    int arow = tid>>1, acol = (tid&1)*4;
    int brow = tid>>5, bcol = (tid&31)*4;
    const float* Aptr = A + (size_t)(row0+arow)*FFD + kbeg + acol;
    const float* Bptr = W + (size_t)(kbeg+brow)*DD + col0 + bcol;

    float4 a4 = *(const float4*)Aptr;
    float4 b4 = *(const float4*)Bptr;
    As[0][acol+0][arow]=a4.x; As[0][acol+1][arow]=a4.y;
    As[0][acol+2][arow]=a4.z; As[0][acol+3][arow]=a4.w;
    *(float4*)&Bs[0][brow][bcol] = b4;
    __syncthreads();

    int tx = tid&15, ty = tid>>4;
    float acc[8][8] = {};
    int buf = 0;
    const int KK = FFD/2;
    for(int k0=8;k0<=KK;k0+=8){
        if(k0<KK){
            a4 = *(const float4*)(Aptr + k0);
            b4 = *(const float4*)(Bptr + (size_t)k0*DD);
        }
        #pragma unroll
        for(int kk=0;kk<8;kk++){
            float4 a0 = *(const float4*)&As[buf][kk][ty*8];
            float4 a1 = *(const float4*)&As[buf][kk][ty*8+4];
            float4 b0 = *(const float4*)&Bs[buf][kk][tx*8];
            float4 b1 = *(const float4*)&Bs[buf][kk][tx*8+4];
            float av[8]={a0.x,a0.y,a0.z,a0.w,a1.x,a1.y,a1.z,a1.w};
            float bv[8]={b0.x,b0.y,b0.z,b0.w,b1.x,b1.y,b1.z,b1.w};
            #pragma unroll
            for(int i=0;i<8;i++)
                #pragma unroll
                for(int j=0;j<8;j++)
                    acc[i][j] += av[i]*bv[j];
        }
        if(k0<KK){
            buf ^= 1;
            As[buf][acol+0][arow]=a4.x; As[buf][acol+1][arow]=a4.y;
            As[buf][acol+2][arow]=a4.z; As[buf][acol+3][arow]=a4.w;
            *(float4*)&Bs[buf][brow][bcol] = b4;
            __syncthreads();
        }
    }
    #pragma unroll
    for(int i=0;i<8;i++){
        int r = row0 + ty*8 + i;
        if(r>=cnt) continue;
        int tok = g_elist[e*NTOK + r];
        float gv = g_egate[e*NTOK + r];
        #pragma unroll
        for(int j=0;j<8;j++){
            int c = col0 + tx*8 + j;
            float v = acc[i][j];
            if(s==0) v += b2[c];
            atomicAdd(&g_moe[(size_t)tok*DD + c], gv*v);
        }
    }
}

// ---------------- small SGEMM (router only, N=8) ----------------
__global__ __launch_bounds__(256) void k_sgemm(const float* __restrict__ A,
                                               const float* __restrict__ Bm,
                                               const float* __restrict__ bias,
                                               float* __restrict__ C,
                                               int M, int N, int Kd){
    __shared__ float As[16][64];
    __shared__ float Bs[16][64];
    int tx = threadIdx.x & 15, ty = threadIdx.x >> 4;
    int row0 = blockIdx.y*64, col0 = blockIdx.x*64;
    float acc[4][4] = {};
    for(int k0=0;k0<Kd;k0+=16){
        #pragma unroll
        for(int i=threadIdx.x;i<1024;i+=256){
            int m=i>>4, kk=i&15; int r=row0+m;
            As[kk][m] = (r<M)? A[(size_t)r*Kd + k0+kk] : 0.f;
        }
        #pragma unroll
        for(int i=threadIdx.x;i<1024;i+=256){
            int kk=i>>6, c=i&63; int cc=col0+c;
            Bs[kk][c] = (cc<N)? Bm[(size_t)(k0+kk)*N + cc] : 0.f;
        }
        __syncthreads();
        #pragma unroll
        for(int kk=0;kk<16;kk++){
            float4 a4 = *(const float4*)&As[kk][ty*4];
            float4 b4 = *(const float4*)&Bs[kk][tx*4];
            float a[4]={a4.x,a4.y,a4.z,a4.w};
            float b[4]={b4.x,b4.y,b4.z,b4.w};
            #pragma unroll
            for(int i=0;i<4;i++)
                #pragma unroll
                for(int j=0;j<4;j++)
                    acc[i][j] += a[i]*b[j];
        }
        __syncthreads();
    }
    #pragma unroll
    for(int i=0;i<4;i++){
        int r=row0+ty*4+i; if(r>=M) continue;
        #pragma unroll
        for(int j=0;j<4;j++){
            int c=col0+tx*4+j; if(c>=N) continue;
            C[(size_t)r*N + c] = acc[i][j] + bias[c];
        }
    }
}

// ---------------- lightning indexer scores ----------------
__global__ __launch_bounds__(256) void k_idxscore(const float* __restrict__ hw){
    int kt=blockIdx.x, qt=blockIdx.y, b=blockIdx.z;
    int tx=threadIdx.x&15, ty=threadIdx.x>>4;
    __shared__ float Qs[64][65];
    __shared__ float Ks[64][65];
    float acc[4][4] = {};
    for(int h=0;h<HHI;h++){
        for(int i=threadIdx.x;i<4096;i+=256){
            int r=i>>6, d=i&63;
            Qs[r][d] = g_qi[(size_t)(b*SSL + qt*64 + r)*(HHI*DII) + h*64 + d];
            Ks[r][d] = g_ki[(size_t)(b*SSL + kt*64 + r)*(HHI*DII) + h*64 + d];
        }
        __syncthreads();
        float w = hw[h];
        float dot[4][4] = {};
        #pragma unroll 16
        for(int d=0;d<64;d++){
            float a[4], bb[4];
            #pragma unroll
            for(int i=0;i<4;i++) a[i]=Qs[ty*4+i][d];
            #pragma unroll
            for(int j=0;j<4;j++) bb[j]=Ks[tx*4+j][d];
            #pragma unroll
            for(int i=0;i<4;i++)
                #pragma unroll
                for(int j=0;j<4;j++)
                    dot[i][j]+=a[i]*bb[j];
        }
        #pragma unroll
        for(int i=0;i<4;i++)
            #pragma unroll
            for(int j=0;j<4;j++)
                acc[i][j] += fmaxf(dot[i][j],0.f)*w;
        __syncthreads();
    }
    #pragma unroll
    for(int i=0;i<4;i++){
        int q = qt*64 + ty*4 + i;
        #pragma unroll
        for(int j=0;j<4;j++){
            int k = kt*64 + tx*4 + j;
            g_mask[((size_t)b*SSL + q)*SSL + k] = acc[i][j] + ((k<=q)?0.f:NEGV);
        }
    }
}

// ---------------- exact top-K threshold + final additive mask ----------------
__global__ __launch_bounds__(512) void k_topk(){
    int q=blockIdx.x, b=blockIdx.y, t=threadIdx.x;
    __shared__ float s[1024];
    size_t base = ((size_t)b*SSL + q)*SSL;
    s[t]     = g_mask[base+t];
    s[t+512] = g_mask[base+t+512];
    __syncthreads();
    for(int size=2;size<=1024;size<<=1){
        for(int stride=size>>1;stride>0;stride>>=1){
            int lo = 2*stride*(t/stride) + (t%stride);
            int hi = lo + stride;
            bool desc = ((lo & size)==0);
            float a=s[lo], bv=s[hi];
            if((a<bv)==desc){ s[lo]=bv; s[hi]=a; }
            __syncthreads();
        }
    }
    float thr = s[KTOP-1];
    for(int k=t;k<SSL;k+=512){
        float v = g_mask[base+k];
        g_mask[base+k] = (k<=q && v>=thr)? 0.f : NEGV;
    }
}

// ---------------- attention: 16 queries/block, fully-parallel online softmax ----------------
// grid (S/16, H, B), block 256; thread = (row = t>>4, cg = t&15)
__global__ __launch_bounds__(256) void k_attn(){
    int qt=blockIdx.x, h=blockIdx.y, b=blockIdx.z;
    int t=threadIdx.x;
    int row = t>>4;
    int cg  = t&15;
    __shared__ float qs[16][65];
    __shared__ float Ks[64][65];
    __shared__ float Vs[64][65];
    __shared__ float Sc[16][65];
    __shared__ float mrow[16], lrow[16];
    int q0 = qt*16;
    for(int i=t;i<16*64;i+=256){
        int r=i>>6, d=i&63;
        qs[r][d] = g_q[(size_t)(b*SSL + q0 + r)*DD + h*64 + d];
    }
    if(t<16){ mrow[t]=-1e30f; lrow[t]=0.f; }
    float oacc[4] = {0.f,0.f,0.f,0.f};
    __syncthreads();
    const float* maskrow = g_mask + ((size_t)b*SSL + (q0+row))*SSL;
    for(int k0=0;k0<SSL;k0+=64){
        for(int i=t;i<4096;i+=256){
            int r=i>>6, d=i&63;
            Ks[r][d] = g_k[(size_t)(b*SSL + k0 + r)*DD + h*64 + d];
            Vs[r][d] = g_v[(size_t)(b*SSL + k0 + r)*DD + h*64 + d];
        }
        __syncthreads();
        // QK: thread computes 4 score columns
        float sv[4];
        #pragma unroll
        for(int j=0;j<4;j++){
            int kc = cg*4 + j;
            float acc = 0.f;
            #pragma unroll 16
            for(int d=0;d<64;d++) acc += qs[row][d]*Ks[kc][d];
            sv[j] = acc*SCALE + maskrow[k0 + kc];
        }
        // online softmax, parallel over 16 lanes per row
        float mold = mrow[row];
        float lold = lrow[row];
        float tmax = fmaxf(fmaxf(sv[0],sv[1]), fmaxf(sv[2],sv[3]));
        tmax = fmaxf(tmax, mold);
        #pragma unroll
        for(int off=8;off>0;off>>=1)
            tmax = fmaxf(tmax, __shfl_xor_sync(0xffffffffu, tmax, off, 16));
        float c = __expf(mold - tmax);
        float lsum = 0.f;
        #pragma unroll
        for(int j=0;j<4;j++){
            float p = __expf(sv[j]-tmax);
            Sc[row][cg*4+j] = p;
            lsum += p;
        }
        #pragma unroll
        for(int off=8;off>0;off>>=1)
            lsum += __shfl_xor_sync(0xffffffffu, lsum, off, 16);
        if(cg==0){ mrow[row]=tmax; lrow[row]=lold*c + lsum; }
        __syncwarp();
        // PV: thread computes 4 output dims
        #pragma unroll
        for(int j=0;j<4;j++){
            int d = cg*4 + j;
            float a = oacc[j]*c;
            #pragma unroll 16
            for(int k=0;k<64;k++) a += Sc[row][k]*Vs[k][d];
            oacc[j] = a;
        }
        __syncthreads();
    }
    float linv = 1.0f/lrow[row];
    #pragma unroll
    for(int j=0;j<4;j++){
        int d = cg*4 + j;
        g_ao[(size_t)(b*SSL + q0 + row)*DD + h*64 + d] = oacc[j]*linv;
    }
}

// ---------------- router gating ----------------
__global__ void k_gate(){
    int n = blockIdx.x*blockDim.x + threadIdx.x;
    if(n>=NTOK) return;
    float p[EE]; float mx=-1e30f;
    for(int e=0;e<EE;e++){ p[e]=g_probs[n*EE+e]; mx=fmaxf(mx,p[e]); }
    for(int e=0;e<EE;e++) p[e]=__expf(p[e]-mx);
    int e1=0;
    for(int e=1;e<EE;e++) if(p[e]>p[e1]) e1=e;
    int e2=-1;
    for(int e=0;e<EE;e++) if(e!=e1 && (e2<0 || p[e]>p[e2])) e2=e;
    float den = p[e1]+p[e2];
    float w1 = p[e1]/den, w2 = p[e2]/den;
    int pos = atomicAdd(&g_ecount[e1],1);
    g_elist[e1*NTOK+pos]=n; g_egate[e1*NTOK+pos]=w1;
    pos = atomicAdd(&g_ecount[e2],1);
    g_elist[e2*NTOK+pos]=n; g_egate[e2*NTOK+pos]=w2;
}

// ================================ host ================================
extern "C" void kernel_launch(void* const* d_in, const int* in_sizes, int n_in,
                              void* d_out, int out_size){
    (void)in_sizes; (void)n_in; (void)out_size;
    const int*   ids  = (const int*)  d_in[0];
    const float* tok  = (const float*)d_in[1];
    const float* pos  = (const float*)d_in[2];
    const float* ln1g = (const float*)d_in[3];
    const float* ln1b = (const float*)d_in[4];
    const float* iqw  = (const float*)d_in[5];
    const float* iqb  = (const float*)d_in[6];
    const float* ikw  = (const float*)d_in[7];
    const float* ikb  = (const float*)d_in[8];
    const float* ihw  = (const float*)d_in[9];
    const float* wq   = (const float*)d_in[10];
    const float* bq   = (const float*)d_in[11];
    const float* wk   = (const float*)d_in[12];
    const float* bk   = (const float*)d_in[13];
    const float* wv   = (const float*)d_in[14];
    const float* bv   = (const float*)d_in[15];
    const float* wo   = (const float*)d_in[16];
    const float* bo   = (const float*)d_in[17];
    const float* ln2g = (const float*)d_in[18];
    const float* ln2b = (const float*)d_in[19];
    const float* rw   = (const float*)d_in[20];
    const float* rb   = (const float*)d_in[21];
    const float* ew1  = (const float*)d_in[22];
    const float* eb1  = (const float*)d_in[23];
    const float* ew2  = (const float*)d_in[24];
    const float* eb2  = (const float*)d_in[25];
    const float* lnfg = (const float*)d_in[26];
    const float* lnfb = (const float*)d_in[27];
    const float* ow   = (const float*)d_in[28];
    const float* ob   = (const float*)d_in[29];
    float* out = (float*)d_out;

    float *px,*ph,*pm,*pq,*pk,*pv,*pao,*pqi,*pki,*pprobs,*pmoe;
    int *pec;
    cudaGetSymbolAddress((void**)&px,  g_x);
    cudaGetSymbolAddress((void**)&ph,  g_h);
    cudaGetSymbolAddress((void**)&pm,  g_m);
    cudaGetSymbolAddress((void**)&pq,  g_q);
    cudaGetSymbolAddress((void**)&pk,  g_k);
    cudaGetSymbolAddress((void**)&pv,  g_v);
    cudaGetSymbolAddress((void**)&pao, g_ao);
    cudaGetSymbolAddress((void**)&pqi, g_qi);
    cudaGetSymbolAddress((void**)&pki, g_ki);
    cudaGetSymbolAddress((void**)&pprobs, g_probs);
    cudaGetSymbolAddress((void**)&pmoe, g_moe);
    cudaGetSymbolAddress((void**)&pec, g_ecount);

    k_embed<<<NTOK,512>>>(ids, tok, pos);

    for(int l=0;l<LLN;l++){
        // --- attention block ---
        k_ln<<<NTOK,256>>>(px, ln1g + l*DD, ln1b + l*DD, ph);
        {   // indexer q/k projections, batched (N=256)
            B3 p;
            p.B0 = iqw + (size_t)l*DD*HHI*DII; p.c0 = iqb + l*HHI*DII; p.C0 = pqi;
            p.B1 = ikw + (size_t)l*DD*HHI*DII; p.c1 = ikb + l*HHI*DII; p.C1 = pki;
            p.B2 = p.B0; p.c2 = p.c0; p.C2 = pqi;
            k_gemm128b3<<<dim3(2,16,2),256>>>(ph, p, HHI*DII, DD);
        }
        k_idxscore<<<dim3(SSL/64, SSL/64, BB),256>>>(ihw + l*HHI);
        k_topk<<<dim3(SSL, BB),512>>>();
        {   // QKV batched (N=512)
            B3 p;
            p.B0 = wq + (size_t)l*DD*DD; p.c0 = bq + l*DD; p.C0 = pq;
            p.B1 = wk + (size_t)l*DD*DD; p.c1 = bk + l*DD; p.C1 = pk;
            p.B2 = wv + (size_t)l*DD*DD; p.c2 = bv + l*DD; p.C2 = pv;
            k_gemm128b3<<<dim3(4,16,3),256>>>(ph, p, DD, DD);
        }
        k_attn<<<dim3(SSL/16, HHN, BB),256>>>();
        // x = x + ao @ wo + bo
        k_gemm128<<<dim3(4,16),256>>>(pao, wo + (size_t)l*DD*DD, bo + l*DD, px, px, DD, DD);

        // --- MoE block ---
        k_ln<<<NTOK,256>>>(px, ln2g + l*DD, ln2b + l*DD, pm);
        k_sgemm<<<dim3(1,32),256>>>(pm, rw + (size_t)l*DD*EE, rb + l*EE, pprobs, NTOK, EE, DD);
        k_zeroi<<<1,32>>>(pec, EE);
        k_gate<<<NTOK/256,256>>>();
        k_zerof<<<(NTOK*DD)/256,256>>>(pmoe, NTOK*DD);
        k_moe1<<<dim3(FFD/128, NTOK/128, EE),256>>>(ew1 + (size_t)l*EE*DD*FFD, eb1 + (size_t)l*EE*FFD);
        k_moe2<<<dim3(DD/128, NTOK/128, EE*2),256>>>(ew2 + (size_t)l*EE*FFD*DD, eb2 + (size_t)l*EE*DD);
        k_add<<<(NTOK*DD)/256,256>>>(px, pmoe, NTOK*DD);
    }

    // --- final LN + vocab projection ---
    k_ln<<<NTOK,256>>>(px, lnfg, lnfb, ph);
    k_gemm128<<<dim3(VV/128, NTOK/128),256>>>(ph, ow, ob, nullptr, out, VV, DD);
}

// round 7
// speedup vs baseline: 1.2084x; 1.2084x over previous
#include <cuda_runtime.h>
#include <cuda_bf16.h>
#include <math.h>
#include <stdint.h>

#define BB 2
#define SSL 1024
#define NTOK 2048
#define DD 512
#define HHN 8
#define HHI 4
#define DII 64
#define FFD 2048
#define EE 8
#define VV 32000
#define KTOP 256
#define NEGV (-1e9f)
#define EPSV 1e-5f
#define LLN 2
#define SCALE 0.125f

__device__ float g_x[NTOK*DD];
__device__ float g_h[NTOK*DD];
__device__ float g_m[NTOK*DD];
__device__ float g_q[NTOK*DD];
__device__ float g_k[NTOK*DD];
__device__ float g_v[NTOK*DD];
__device__ float g_ao[NTOK*DD];
__device__ float g_moe[NTOK*DD];
__device__ float g_qi[NTOK*HHI*DII];
__device__ float g_ki[NTOK*HHI*DII];
__device__ float g_mask[(size_t)BB*SSL*SSL];
__device__ float g_probs[NTOK*EE];
__device__ int g_ecount[EE];
__device__ int g_elist[EE*NTOK];
__device__ float g_egate[EE*NTOK];
__device__ alignas(16) __nv_bfloat16 g_hhi[NTOK*DD];
__device__ alignas(16) __nv_bfloat16 g_hlo[NTOK*DD];
__device__ alignas(16) __nv_bfloat16 g_mhi[NTOK*DD];
__device__ alignas(16) __nv_bfloat16 g_mlo[NTOK*DD];
__device__ alignas(16) __nv_bfloat16 g_owThi[(size_t)VV*DD];
__device__ alignas(16) __nv_bfloat16 g_owTlo[(size_t)VV*DD];
__device__ alignas(16) __nv_bfloat16 g_w1Thi[(size_t)LLN*EE*FFD*DD];
__device__ alignas(16) __nv_bfloat16 g_w1Tlo[(size_t)LLN*EE*FFD*DD];
__device__ alignas(16) __nv_bfloat16 g_w2Thi[(size_t)LLN*EE*DD*FFD];
__device__ alignas(16) __nv_bfloat16 g_w2Tlo[(size_t)LLN*EE*DD*FFD];
__device__ alignas(16) __nv_bfloat16 g_h1hi[(size_t)EE*NTOK*FFD];
__device__ alignas(16) __nv_bfloat16 g_h1lo[(size_t)EE*NTOK*FFD];

__device__ __forceinline__ float gelu_tanh(float x){
    float x3 = x*x*x;
    return 0.5f*x*(1.f + tanhf(0.7978845608028654f*(x + 0.044715f*x3)));
}
__global__ void k_zerof(float* p, int n){ int i=blockIdx.x*blockDim.x+threadIdx.x; if(i<n)p[i]=0.f; }
__global__ void k_zeroi(int* p, int n){ int i=threadIdx.x; if(i<n)p[i]=0; }
__global__ void k_add(float* x, const float* y, int n){ int i=blockIdx.x*blockDim.x+threadIdx.x; if(i<n)x[i]+=y[i]; }

__global__ void k_embed(const int* __restrict__ ids, const float* __restrict__ tok, const float* __restrict__ pos){
    int n=blockIdx.x, t=threadIdx.x;
    g_x[(size_t)n*DD+t] = tok[(size_t)ids[n]*DD+t] + pos[(size_t)(n%SSL)*DD+t];
}

__global__ __launch_bounds__(256) void k_ln(const float* __restrict__ in, const float* __restrict__ g,
                                            const float* __restrict__ b, float* __restrict__ out){
    int r=blockIdx.x, t=threadIdx.x;
    __shared__ float red[256];
    float v0=in[(size_t)r*DD+t], v1=in[(size_t)r*DD+t+256];
    red[t]=v0+v1; __syncthreads();
    for(int s=128;s>0;s>>=1){ if(t<s)red[t]+=red[t+s]; __syncthreads(); }
    float mu=red[0]*(1.0f/DD); __syncthreads();
    float d0=v0-mu, d1=v1-mu;
    red[t]=d0*d0+d1*d1; __syncthreads();
    for(int s=128;s>0;s>>=1){ if(t<s)red[t]+=red[t+s]; __syncthreads(); }
    float rs=rsqrtf(red[0]*(1.0f/DD)+EPSV);
    out[(size_t)r*DD+t]=d0*rs*g[t]+b[t];
    out[(size_t)r*DD+t+256]=d1*rs*g[t+256]+b[t+256];
}

// fp32 -> bf16 hi/lo split
__global__ void k_cvt(const float* __restrict__ x, __nv_bfloat16* __restrict__ hi,
                      __nv_bfloat16* __restrict__ lo, int n){
    int i=blockIdx.x*blockDim.x+threadIdx.x;
    if(i<n){
        float v=x[i];
        __nv_bfloat16 h=__float2bfloat16(v);
        hi[i]=h; lo[i]=__float2bfloat16(v-__bfloat162float(h));
    }
}
// batched: W[z][K][N] fp32 -> T[z][N][K] bf16 hi/lo
__global__ __launch_bounds__(256) void k_transcvtB(const float* __restrict__ W,
        __nv_bfloat16* __restrict__ Thi, __nv_bfloat16* __restrict__ Tlo, int K, int N){
    int z=blockIdx.z;
    W   += (size_t)z*K*N;
    Thi += (size_t)z*N*K;
    Tlo += (size_t)z*N*K;
    __shared__ float t[32][33];
    int n0=blockIdx.x*32, k0=blockIdx.y*32;
    int tx=threadIdx.x&31, ty=threadIdx.x>>5;
    for(int i=ty;i<32;i+=8) t[i][tx]=W[(size_t)(k0+i)*N + n0+tx];
    __syncthreads();
    for(int i=ty;i<32;i+=8){
        float v=t[tx][i];
        __nv_bfloat16 h=__float2bfloat16(v);
        size_t o=(size_t)(n0+i)*K + k0+tx;
        Thi[o]=h; Tlo[o]=__float2bfloat16(v-__bfloat162float(h));
    }
}

// ================= HMMA bf16-split GEMM core =================
__device__ __forceinline__ uint32_t smem_u32(const void* p){
    uint32_t a;
    asm("{ .reg .u64 t; cvta.to.shared.u64 t, %1; cvt.u32.u64 %0, t; }" : "=r"(a) : "l"(p));
    return a;
}
__device__ __forceinline__ void ldsm4(uint32_t (&r)[4], uint32_t a){
    asm volatile("ldmatrix.sync.aligned.m8n8.x4.shared.b16 {%0,%1,%2,%3}, [%4];"
        : "=r"(r[0]),"=r"(r[1]),"=r"(r[2]),"=r"(r[3]) : "r"(a));
}
__device__ __forceinline__ void ldsm2(uint32_t (&r)[2], uint32_t a){
    asm volatile("ldmatrix.sync.aligned.m8n8.x2.shared.b16 {%0,%1}, [%2];"
        : "=r"(r[0]),"=r"(r[1]) : "r"(a));
}
__device__ __forceinline__ void mma16816(float (&c)[4], const uint32_t (&a)[4], const uint32_t (&b)[2]){
    asm volatile("mma.sync.aligned.m16n8k16.row.col.f32.bf16.bf16.f32 "
        "{%0,%1,%2,%3}, {%4,%5,%6,%7}, {%8,%9}, {%0,%1,%2,%3};"
        : "+f"(c[0]),"+f"(c[1]),"+f"(c[2]),"+f"(c[3])
        : "r"(a[0]),"r"(a[1]),"r"(a[2]),"r"(a[3]), "r"(b[0]),"r"(b[1]));
}
// smem layout: [2 bufs][4 tiles][128 rows * 48B]; rowidx at +49152
#define HS_BUF 24576
#define HS_TILE 6144
#define HS_TOTAL 49664

// block computes C[128 x 128] at (row0 via rowidx, col0); A,B split bf16, K-major stride sA/sB
__device__ __forceinline__ void hmma_main(char* sm, const int* rowidx,
    const __nv_bfloat16* __restrict__ Ahi, const __nv_bfloat16* __restrict__ Alo, int sA,
    const __nv_bfloat16* __restrict__ Bhi, const __nv_bfloat16* __restrict__ Blo, int sB,
    int col0, int K, float (&acc)[4][4][4])
{
    int tid=threadIdx.x, lane=tid&31, warp=tid>>5;
    int wm=warp>>2, wn=warp&3;
    uint32_t smb = smem_u32(sm);
    #pragma unroll
    for(int i=0;i<4;i++)
        #pragma unroll
        for(int j=0;j<4;j++)
            #pragma unroll
            for(int q=0;q<4;q++) acc[i][j][q]=0.f;

    int ltile[4], lrow[4], lhalf[4];
    #pragma unroll
    for(int t=0;t<4;t++){
        int i = tid + t*256;
        ltile[t]=i>>8; lrow[t]=(i&255)>>1; lhalf[t]=(i&1)*8;
    }
    uint4 pre[4];
    const int NS = K>>4;
    // address offsets for ldmatrix
    int lb = lane&15;
    uint32_t boff = (uint32_t)((wn*32 + (lb&7))*48 + ((lb&8)?16:0));
    uint32_t aoff = (uint32_t)((wm*64 + (lane&7) + ((lane&8)?8:0))*48 + ((lane&16)?16:0));

    auto ldg = [&](int s){
        int k0 = s<<4;
        #pragma unroll
        for(int t=0;t<4;t++){
            const __nv_bfloat16* src;
            int row=lrow[t];
            if(ltile[t]==0)      src = Ahi + (size_t)rowidx[row]*sA;
            else if(ltile[t]==1) src = Alo + (size_t)rowidx[row]*sA;
            else if(ltile[t]==2) src = Bhi + (size_t)(col0+row)*sB;
            else                 src = Blo + (size_t)(col0+row)*sB;
            pre[t] = *(const uint4*)(src + k0 + lhalf[t]);
        }
    };
    auto sts = [&](int b){
        #pragma unroll
        for(int t=0;t<4;t++)
            *(uint4*)(sm + b*HS_BUF + ltile[t]*HS_TILE + lrow[t]*48 + lhalf[t]*2) = pre[t];
    };
    ldg(0); sts(0);
    __syncthreads();
    for(int s=0;s<NS;s++){
        int b=s&1;
        if(s+1<NS) ldg(s+1);
        uint32_t base = smb + b*HS_BUF;
        uint32_t bh[4][2], bl[4][2];
        #pragma unroll
        for(int j=0;j<4;j++){
            ldsm2(bh[j], base + 2*HS_TILE + boff + j*8*48);
            ldsm2(bl[j], base + 3*HS_TILE + boff + j*8*48);
        }
        #pragma unroll
        for(int i=0;i<4;i++){
            uint32_t a[4];
            ldsm4(a, base + aoff + i*16*48);
            #pragma unroll
            for(int j=0;j<4;j++){ mma16816(acc[i][j], a, bh[j]); mma16816(acc[i][j], a, bl[j]); }
            ldsm4(a, base + HS_TILE + aoff + i*16*48);
            #pragma unroll
            for(int j=0;j<4;j++) mma16816(acc[i][j], a, bh[j]);
        }
        if(s+1<NS) sts(b^1);
        __syncthreads();
    }
}

// ---- vocab: out = h(split) @ owT^T + ob ----
__global__ __launch_bounds__(256,1) void k_hmma_vocab(const float* __restrict__ ob, float* __restrict__ out){
    extern __shared__ char sm[];
    int* rowidx = (int*)(sm + 2*HS_BUF);
    int tid=threadIdx.x;
    int row0=blockIdx.y*128, col0=blockIdx.x*128;
    if(tid<128) rowidx[tid]=row0+tid;
    __syncthreads();
    float acc[4][4][4];
    hmma_main(sm, rowidx, g_hhi, g_hlo, DD, g_owThi, g_owTlo, DD, col0, DD, acc);
    int lane=tid&31, warp=tid>>5, wm=warp>>2, wn=warp&3;
    #pragma unroll
    for(int i=0;i<4;i++){
        int r0 = row0 + wm*64 + i*16 + (lane>>2);
        #pragma unroll
        for(int j=0;j<4;j++){
            int c = col0 + wn*32 + j*8 + (lane&3)*2;
            float b0=ob[c], b1=ob[c+1];
            out[(size_t)r0*VV + c]       = acc[i][j][0] + b0;
            out[(size_t)r0*VV + c+1]     = acc[i][j][1] + b1;
            out[(size_t)(r0+8)*VV + c]   = acc[i][j][2] + b0;
            out[(size_t)(r0+8)*VV + c+1] = acc[i][j][3] + b1;
        }
    }
}

// ---- MoE1: h1 = gelu(gather(m) @ w1T^T + b1), output split bf16 ----
__global__ __launch_bounds__(256,1) void k_hmma_moe1(const __nv_bfloat16* __restrict__ Whi,
        const __nv_bfloat16* __restrict__ Wlo, const float* __restrict__ B1){
    int e=blockIdx.z, cnt=g_ecount[e], row0=blockIdx.y*128;
    if(row0>=cnt) return;
    extern __shared__ char sm[];
    int* rowidx = (int*)(sm + 2*HS_BUF);
    int tid=threadIdx.x;
    int col0=blockIdx.x*128;
    if(tid<128){
        int r=row0+tid;
        rowidx[tid] = (r<cnt)? g_elist[e*NTOK+r] : g_elist[e*NTOK];
    }
    __syncthreads();
    float acc[4][4][4];
    hmma_main(sm, rowidx, g_mhi, g_mlo, DD,
              Whi+(size_t)e*FFD*DD, Wlo+(size_t)e*FFD*DD, DD, col0, DD, acc);
    const float* bia = B1 + (size_t)e*FFD;
    int lane=tid&31, warp=tid>>5, wm=warp>>2, wn=warp&3;
    #pragma unroll
    for(int i=0;i<4;i++){
        int r0 = row0 + wm*64 + i*16 + (lane>>2);
        #pragma unroll
        for(int j=0;j<4;j++){
            int c = col0 + wn*32 + j*8 + (lane&3)*2;
            float b0=bia[c], b1=bia[c+1];
            #pragma unroll
            for(int q=0;q<4;q++){
                int r = r0 + (q>=2?8:0);
                if(r>=cnt) continue;
                int cc = c + (q&1);
                float v = gelu_tanh(acc[i][j][q] + ((q&1)?b1:b0));
                __nv_bfloat16 h=__float2bfloat16(v);
                size_t o = ((size_t)e*NTOK + r)*FFD + cc;
                g_h1hi[o]=h; g_h1lo[o]=__float2bfloat16(v-__bfloat162float(h));
            }
        }
    }
}

// ---- MoE2: moe[tok] += gv*(h1(split) @ w2T^T + b2) ----
__global__ __launch_bounds__(256,1) void k_hmma_moe2(const __nv_bfloat16* __restrict__ Whi,
        const __nv_bfloat16* __restrict__ Wlo, const float* __restrict__ B2){
    int e=blockIdx.z, cnt=g_ecount[e], row0=blockIdx.y*128;
    if(row0>=cnt) return;
    extern __shared__ char sm[];
    int* rowidx = (int*)(sm + 2*HS_BUF);
    int tid=threadIdx.x;
    int col0=blockIdx.x*128;
    if(tid<128) rowidx[tid] = e*NTOK + row0 + tid;
    __syncthreads();
    float acc[4][4][4];
    hmma_main(sm, rowidx, g_h1hi, g_h1lo, FFD,
              Whi+(size_t)e*DD*FFD, Wlo+(size_t)e*DD*FFD, FFD, col0, FFD, acc);
    const float* bia = B2 + (size_t)e*DD;
    int lane=tid&31, warp=tid>>5, wm=warp>>2, wn=warp&3;
    #pragma unroll
    for(int i=0;i<4;i++){
        int r0 = row0 + wm*64 + i*16 + (lane>>2);
        #pragma unroll
        for(int j=0;j<4;j++){
            int c = col0 + wn*32 + j*8 + (lane&3)*2;
            float b0=bia[c], b1=bia[c+1];
            #pragma unroll
            for(int q=0;q<4;q++){
                int r = r0 + (q>=2?8:0);
                if(r>=cnt) continue;
                int tok=g_elist[e*NTOK+r];
                float gv=g_egate[e*NTOK+r];
                int cc = c + (q&1);
                atomicAdd(&g_moe[(size_t)tok*DD+cc], gv*(acc[i][j][q] + ((q&1)?b1:b0)));
            }
        }
    }
}

// ===== fp32 128x128 SGEMM (projections) =====
struct B3 { const float *B0,*B1,*B2; const float *c0,*c1,*c2; float *C0,*C1,*C2; };
__device__ __forceinline__ void gemm128_body(const float* __restrict__ A, const float* __restrict__ B,
    const float* __restrict__ bias, const float* __restrict__ res, float* __restrict__ C, int N, int K){
    __shared__ float As[2][8][132];
    __shared__ float Bs[2][8][128];
    int tid=threadIdx.x;
    int row0=blockIdx.y*128, col0=blockIdx.x*128;
    int arow=tid>>1, acol=(tid&1)*4;
    int brow=tid>>5, bcol=(tid&31)*4;
    const float* Aptr=A+(size_t)(row0+arow)*K+acol;
    const float* Bptr=B+(size_t)brow*N+col0+bcol;
    float4 a4=*(const float4*)Aptr;
    float4 b4=*(const float4*)Bptr;
    As[0][acol+0][arow]=a4.x; As[0][acol+1][arow]=a4.y; As[0][acol+2][arow]=a4.z; As[0][acol+3][arow]=a4.w;
    *(float4*)&Bs[0][brow][bcol]=b4;
    __syncthreads();
    int tx=tid&15, ty=tid>>4;
    float acc[8][8]={};
    int buf=0;
    for(int k0=8;k0<=K;k0+=8){
        if(k0<K){ a4=*(const float4*)(Aptr+k0); b4=*(const float4*)(Bptr+(size_t)k0*N); }
        #pragma unroll
        for(int kk=0;kk<8;kk++){
            float4 a0=*(const float4*)&As[buf][kk][ty*8];
            float4 a1=*(const float4*)&As[buf][kk][ty*8+4];
            float4 b0=*(const float4*)&Bs[buf][kk][tx*8];
            float4 b1=*(const float4*)&Bs[buf][kk][tx*8+4];
            float av[8]={a0.x,a0.y,a0.z,a0.w,a1.x,a1.y,a1.z,a1.w};
            float bv[8]={b0.x,b0.y,b0.z,b0.w,b1.x,b1.y,b1.z,b1.w};
            #pragma unroll
            for(int i=0;i<8;i++)
                #pragma unroll
                for(int j=0;j<8;j++) acc[i][j]+=av[i]*bv[j];
        }
        if(k0<K){
            buf^=1;
            As[buf][acol+0][arow]=a4.x; As[buf][acol+1][arow]=a4.y; As[buf][acol+2][arow]=a4.z; As[buf][acol+3][arow]=a4.w;
            *(float4*)&Bs[buf][brow][bcol]=b4;
            __syncthreads();
        }
    }
    #pragma unroll
    for(int i=0;i<8;i++){
        int r=row0+ty*8+i;
        #pragma unroll
        for(int j=0;j<8;j+=4){
            int c=col0+tx*8+j;
            float4 v={acc[i][j],acc[i][j+1],acc[i][j+2],acc[i][j+3]};
            if(bias){ float4 bb=*(const float4*)&bias[c]; v.x+=bb.x;v.y+=bb.y;v.z+=bb.z;v.w+=bb.w; }
            if(res){ float4 rr=*(const float4*)&res[(size_t)r*N+c]; v.x+=rr.x;v.y+=rr.y;v.z+=rr.z;v.w+=rr.w; }
            *(float4*)&C[(size_t)r*N+c]=v;
        }
    }
}
__global__ __launch_bounds__(256) void k_gemm128(const float* __restrict__ A, const float* __restrict__ B,
    const float* __restrict__ bias, const float* __restrict__ res, float* __restrict__ C, int N, int K){
    gemm128_body(A,B,bias,res,C,N,K);
}
__global__ __launch_bounds__(256) void k_gemm128b3(const float* __restrict__ A, B3 p, int N, int K){
    const float *B,*bias; float *C;
    if(blockIdx.z==0){B=p.B0;bias=p.c0;C=p.C0;}
    else if(blockIdx.z==1){B=p.B1;bias=p.c1;C=p.C1;}
    else {B=p.B2;bias=p.c2;C=p.C2;}
    gemm128_body(A,B,bias,nullptr,C,N,K);
}

// ===== router small GEMM =====
__global__ __launch_bounds__(256) void k_sgemm(const float* __restrict__ A, const float* __restrict__ Bm,
    const float* __restrict__ bias, float* __restrict__ C, int M, int N, int Kd){
    __shared__ float As[16][64];
    __shared__ float Bs[16][64];
    int tx=threadIdx.x&15, ty=threadIdx.x>>4;
    int row0=blockIdx.y*64, col0=blockIdx.x*64;
    float acc[4][4]={};
    for(int k0=0;k0<Kd;k0+=16){
        for(int i=threadIdx.x;i<1024;i+=256){
            int m=i>>4, kk=i&15; int r=row0+m;
            As[kk][m]=(r<M)?A[(size_t)r*Kd+k0+kk]:0.f;
        }
        for(int i=threadIdx.x;i<1024;i+=256){
            int kk=i>>6, c=i&63; int cc=col0+c;
            Bs[kk][c]=(cc<N)?Bm[(size_t)(k0+kk)*N+cc]:0.f;
        }
        __syncthreads();
        #pragma unroll
        for(int kk=0;kk<16;kk++){
            float4 a4=*(const float4*)&As[kk][ty*4];
            float4 b4=*(const float4*)&Bs[kk][tx*4];
            float a[4]={a4.x,a4.y,a4.z,a4.w};
            float b[4]={b4.x,b4.y,b4.z,b4.w};
            #pragma unroll
            for(int i=0;i<4;i++)
                #pragma unroll
                for(int j=0;j<4;j++) acc[i][j]+=a[i]*b[j];
        }
        __syncthreads();
    }
    #pragma unroll
    for(int i=0;i<4;i++){
        int r=row0+ty*4+i; if(r>=M) continue;
        #pragma unroll
        for(int j=0;j<4;j++){
            int c=col0+tx*4+j; if(c>=N) continue;
            C[(size_t)r*N+c]=acc[i][j]+bias[c];
        }
    }
}

// ===== indexer scores (transposed smem, float4 microtile) =====
__global__ __launch_bounds__(256) void k_idxscore(const float* __restrict__ hw){
    int kt=blockIdx.x, qt=blockIdx.y, b=blockIdx.z;
    int tx=threadIdx.x&15, ty=threadIdx.x>>4;
    __shared__ float Qs[64][68];
    __shared__ float Ks[64][68];
    float acc[4][4]={};
    for(int h=0;h<HHI;h++){
        for(int i=threadIdx.x;i<4096;i+=256){
            int r=i>>6, d=i&63;
            Qs[d][r]=g_qi[(size_t)(b*SSL+qt*64+r)*(HHI*DII)+h*64+d];
            Ks[d][r]=g_ki[(size_t)(b*SSL+kt*64+r)*(HHI*DII)+h*64+d];
        }
        __syncthreads();
        float w=hw[h];
        float dot[4][4]={};
        #pragma unroll 8
        for(int d=0;d<64;d++){
            float4 a4=*(const float4*)&Qs[d][ty*4];
            float4 b4=*(const float4*)&Ks[d][tx*4];
            float a[4]={a4.x,a4.y,a4.z,a4.w};
            float bb[4]={b4.x,b4.y,b4.z,b4.w};
            #pragma unroll
            for(int i=0;i<4;i++)
                #pragma unroll
                for(int j=0;j<4;j++) dot[i][j]+=a[i]*bb[j];
        }
        #pragma unroll
        for(int i=0;i<4;i++)
            #pragma unroll
            for(int j=0;j<4;j++) acc[i][j]+=fmaxf(dot[i][j],0.f)*w;
        __syncthreads();
    }
    #pragma unroll
    for(int i=0;i<4;i++){
        int q=qt*64+ty*4+i;
        #pragma unroll
        for(int j=0;j<4;j++){
            int k=kt*64+tx*4+j;
            g_mask[((size_t)b*SSL+q)*SSL+k]=acc[i][j]+((k<=q)?0.f:NEGV);
        }
    }
}

// ===== top-K bitonic =====
__global__ __launch_bounds__(512) void k_topk(){
    int q=blockIdx.x, b=blockIdx.y, t=threadIdx.x;
    __shared__ float s[1024];
    size_t base=((size_t)b*SSL+q)*SSL;
    s[t]=g_mask[base+t];
    s[t+512]=g_mask[base+t+512];
    __syncthreads();
    for(int size=2;size<=1024;size<<=1){
        for(int stride=size>>1;stride>0;stride>>=1){
            int lo=2*stride*(t/stride)+(t%stride);
            int hi=lo+stride;
            bool desc=((lo&size)==0);
            float a=s[lo], bv=s[hi];
            if((a<bv)==desc){ s[lo]=bv; s[hi]=a; }
            __syncthreads();
        }
    }
    float thr=s[KTOP-1];
    for(int k=t;k<SSL;k+=512){
        float v=g_mask[base+k];
        g_mask[base+k]=(k<=q && v>=thr)?0.f:NEGV;
    }
}

// ===== attention =====
__global__ __launch_bounds__(256) void k_attn(){
    int qt=blockIdx.x, h=blockIdx.y, b=blockIdx.z;
    int t=threadIdx.x, row=t>>4, cg=t&15;
    __shared__ float qs[16][65];
    __shared__ float Ks[64][65];
    __shared__ float Vs[64][65];
    __shared__ float Sc[16][65];
    __shared__ float mrow[16], lrow[16];
    int q0=qt*16;
    for(int i=t;i<16*64;i+=256){
        int r=i>>6, d=i&63;
        qs[r][d]=g_q[(size_t)(b*SSL+q0+r)*DD+h*64+d];
    }
    if(t<16){ mrow[t]=-1e30f; lrow[t]=0.f; }
    float oacc[4]={0.f,0.f,0.f,0.f};
    __syncthreads();
    const float* maskrow=g_mask+((size_t)b*SSL+(q0+row))*SSL;
    for(int k0=0;k0<SSL;k0+=64){
        for(int i=t;i<4096;i+=256){
            int r=i>>6, d=i&63;
            Ks[r][d]=g_k[(size_t)(b*SSL+k0+r)*DD+h*64+d];
            Vs[r][d]=g_v[(size_t)(b*SSL+k0+r)*DD+h*64+d];
        }
        __syncthreads();
        float sv[4];
        #pragma unroll
        for(int j=0;j<4;j++){
            int kc=cg*4+j;
            float acc=0.f;
            #pragma unroll 16
            for(int d=0;d<64;d++) acc+=qs[row][d]*Ks[kc][d];
            sv[j]=acc*SCALE+maskrow[k0+kc];
        }
        float mold=mrow[row], lold=lrow[row];
        float tmax=fmaxf(fmaxf(sv[0],sv[1]),fmaxf(sv[2],sv[3]));
        tmax=fmaxf(tmax,mold);
        #pragma unroll
        for(int off=8;off>0;off>>=1) tmax=fmaxf(tmax,__shfl_xor_sync(0xffffffffu,tmax,off,16));
        float c=__expf(mold-tmax);
        float lsum=0.f;
        #pragma unroll
        for(int j=0;j<4;j++){
            float p=__expf(sv[j]-tmax);
            Sc[row][cg*4+j]=p;
            lsum+=p;
        }
        #pragma unroll
        for(int off=8;off>0;off>>=1) lsum+=__shfl_xor_sync(0xffffffffu,lsum,off,16);
        if(cg==0){ mrow[row]=tmax; lrow[row]=lold*c+lsum; }
        __syncwarp();
        #pragma unroll
        for(int j=0;j<4;j++){
            int d=cg*4+j;
            float a=oacc[j]*c;
            #pragma unroll 16
            for(int k=0;k<64;k++) a+=Sc[row][k]*Vs[k][d];
            oacc[j]=a;
        }
        __syncthreads();
    }
    float linv=1.0f/lrow[row];
    #pragma unroll
    for(int j=0;j<4;j++){
        int d=cg*4+j;
        g_ao[(size_t)(b*SSL+q0+row)*DD+h*64+d]=oacc[j]*linv;
    }
}

// ===== router gating =====
__global__ void k_gate(){
    int n=blockIdx.x*blockDim.x+threadIdx.x;
    if(n>=NTOK) return;
    float p[EE]; float mx=-1e30f;
    for(int e=0;e<EE;e++){ p[e]=g_probs[n*EE+e]; mx=fmaxf(mx,p[e]); }
    for(int e=0;e<EE;e++) p[e]=__expf(p[e]-mx);
    int e1=0;
    for(int e=1;e<EE;e++) if(p[e]>p[e1]) e1=e;
    int e2=-1;
    for(int e=0;e<EE;e++) if(e!=e1 && (e2<0 || p[e]>p[e2])) e2=e;
    float den=p[e1]+p[e2];
    int pos=atomicAdd(&g_ecount[e1],1);
    g_elist[e1*NTOK+pos]=n; g_egate[e1*NTOK+pos]=p[e1]/den;
    pos=atomicAdd(&g_ecount[e2],1);
    g_elist[e2*NTOK+pos]=n; g_egate[e2*NTOK+pos]=p[e2]/den;
}

// ===== host =====
extern "C" void kernel_launch(void* const* d_in, const int* in_sizes, int n_in,
                              void* d_out, int out_size){
    (void)in_sizes; (void)n_in; (void)out_size;
    const int*   ids  = (const int*)  d_in[0];
    const float* tok  = (const float*)d_in[1];
    const float* pos  = (const float*)d_in[2];
    const float* ln1g = (const float*)d_in[3];
    const float* ln1b = (const float*)d_in[4];
    const float* iqw  = (const float*)d_in[5];
    const float* iqb  = (const float*)d_in[6];
    const float* ikw  = (const float*)d_in[7];
    const float* ikb  = (const float*)d_in[8];
    const float* ihw  = (const float*)d_in[9];
    const float* wq   = (const float*)d_in[10];
    const float* bq   = (const float*)d_in[11];
    const float* wk   = (const float*)d_in[12];
    const float* bk   = (const float*)d_in[13];
    const float* wv   = (const float*)d_in[14];
    const float* bv   = (const float*)d_in[15];
    const float* wo   = (const float*)d_in[16];
    const float* bo   = (const float*)d_in[17];
    const float* ln2g = (const float*)d_in[18];
    const float* ln2b = (const float*)d_in[19];
    const float* rw   = (const float*)d_in[20];
    const float* rb   = (const float*)d_in[21];
    const float* ew1  = (const float*)d_in[22];
    const float* eb1  = (const float*)d_in[23];
    const float* ew2  = (const float*)d_in[24];
    const float* eb2  = (const float*)d_in[25];
    const float* lnfg = (const float*)d_in[26];
    const float* lnfb = (const float*)d_in[27];
    const float* ow   = (const float*)d_in[28];
    const float* ob   = (const float*)d_in[29];
    float* out = (float*)d_out;

    float *px,*ph,*pm,*pq,*pk,*pv,*pao,*pqi,*pki,*pprobs,*pmoe;
    int *pec;
    __nv_bfloat16 *phhi,*phlo,*pmhi,*pmlo,*powThi,*powTlo,*pw1Thi,*pw1Tlo,*pw2Thi,*pw2Tlo;
    cudaGetSymbolAddress((void**)&px,g_x);
    cudaGetSymbolAddress((void**)&ph,g_h);
    cudaGetSymbolAddress((void**)&pm,g_m);
    cudaGetSymbolAddress((void**)&pq,g_q);
    cudaGetSymbolAddress((void**)&pk,g_k);
    cudaGetSymbolAddress((void**)&pv,g_v);
    cudaGetSymbolAddress((void**)&pao,g_ao);
    cudaGetSymbolAddress((void**)&pqi,g_qi);
    cudaGetSymbolAddress((void**)&pki,g_ki);
    cudaGetSymbolAddress((void**)&pprobs,g_probs);
    cudaGetSymbolAddress((void**)&pmoe,g_moe);
    cudaGetSymbolAddress((void**)&pec,g_ecount);
    cudaGetSymbolAddress((void**)&phhi,g_hhi);
    cudaGetSymbolAddress((void**)&phlo,g_hlo);
    cudaGetSymbolAddress((void**)&pmhi,g_mhi);
    cudaGetSymbolAddress((void**)&pmlo,g_mlo);
    cudaGetSymbolAddress((void**)&powThi,g_owThi);
    cudaGetSymbolAddress((void**)&powTlo,g_owTlo);
    cudaGetSymbolAddress((void**)&pw1Thi,g_w1Thi);
    cudaGetSymbolAddress((void**)&pw1Tlo,g_w1Tlo);
    cudaGetSymbolAddress((void**)&pw2Thi,g_w2Thi);
    cudaGetSymbolAddress((void**)&pw2Tlo,g_w2Tlo);

    cudaFuncSetAttribute(k_hmma_vocab, cudaFuncAttributeMaxDynamicSharedMemorySize, HS_TOTAL);
    cudaFuncSetAttribute(k_hmma_moe1,  cudaFuncAttributeMaxDynamicSharedMemorySize, HS_TOTAL);
    cudaFuncSetAttribute(k_hmma_moe2,  cudaFuncAttributeMaxDynamicSharedMemorySize, HS_TOTAL);

    // one-time weight transposes + bf16 splits
    k_transcvtB<<<dim3(VV/32, DD/32, 1),256>>>(ow, powThi, powTlo, DD, VV);
    k_transcvtB<<<dim3(FFD/32, DD/32, LLN*EE),256>>>(ew1, pw1Thi, pw1Tlo, DD, FFD);
    k_transcvtB<<<dim3(DD/32, FFD/32, LLN*EE),256>>>(ew2, pw2Thi, pw2Tlo, FFD, DD);

    k_embed<<<NTOK,512>>>(ids, tok, pos);

    for(int l=0;l<LLN;l++){
        k_ln<<<NTOK,256>>>(px, ln1g+l*DD, ln1b+l*DD, ph);
        {   B3 p;
            p.B0=iqw+(size_t)l*DD*HHI*DII; p.c0=iqb+l*HHI*DII; p.C0=pqi;
            p.B1=ikw+(size_t)l*DD*HHI*DII; p.c1=ikb+l*HHI*DII; p.C1=pki;
            p.B2=p.B0; p.c2=p.c0; p.C2=pqi;
            k_gemm128b3<<<dim3(2,16,2),256>>>(ph, p, HHI*DII, DD);
        }
        k_idxscore<<<dim3(SSL/64,SSL/64,BB),256>>>(ihw+l*HHI);
        k_topk<<<dim3(SSL,BB),512>>>();
        {   B3 p;
            p.B0=wq+(size_t)l*DD*DD; p.c0=bq+l*DD; p.C0=pq;
            p.B1=wk+(size_t)l*DD*DD; p.c1=bk+l*DD; p.C1=pk;
            p.B2=wv+(size_t)l*DD*DD; p.c2=bv+l*DD; p.C2=pv;
            k_gemm128b3<<<dim3(4,16,3),256>>>(ph, p, DD, DD);
        }
        k_attn<<<dim3(SSL/16,HHN,BB),256>>>();
        k_gemm128<<<dim3(4,16),256>>>(pao, wo+(size_t)l*DD*DD, bo+l*DD, px, px, DD, DD);

        k_ln<<<NTOK,256>>>(px, ln2g+l*DD, ln2b+l*DD, pm);
        k_sgemm<<<dim3(1,32),256>>>(pm, rw+(size_t)l*DD*EE, rb+l*EE, pprobs, NTOK, EE, DD);
        k_zeroi<<<1,32>>>(pec, EE);
        k_gate<<<NTOK/256,256>>>();
        k_cvt<<<(NTOK*DD)/256,256>>>(pm, pmhi, pmlo, NTOK*DD);
        k_zerof<<<(NTOK*DD)/256,256>>>(pmoe, NTOK*DD);
        k_hmma_moe1<<<dim3(FFD/128, NTOK/128, EE),256,HS_TOTAL>>>(
            pw1Thi+(size_t)l*EE*FFD*DD, pw1Tlo+(size_t)l*EE*FFD*DD, eb1+(size_t)l*EE*FFD);
        k_hmma_moe2<<<dim3(DD/128, NTOK/128, EE),256,HS_TOTAL>>>(
            pw2Thi+(size_t)l*EE*DD*FFD, pw2Tlo+(size_t)l*EE*DD*FFD, eb2+(size_t)l*EE*DD);
        k_add<<<(NTOK*DD)/256,256>>>(px, pmoe, NTOK*DD);
    }

    k_ln<<<NTOK,256>>>(px, lnfg, lnfb, ph);
    k_cvt<<<(NTOK*DD)/256,256>>>(ph, phhi, phlo, NTOK*DD);
    k_hmma_vocab<<<dim3(VV/128, NTOK/128),256,HS_TOTAL>>>(ob, out);
}

// round 8
// speedup vs baseline: 1.5832x; 1.3101x over previous
#include <cuda_runtime.h>
#include <cuda_bf16.h>
#include <math.h>
#include <stdint.h>

#define BB 2
#define SSL 1024
#define NTOK 2048
#define DD 512
#define HHN 8
#define HHI 4
#define DII 64
#define FFD 2048
#define EE 8
#define VV 32000
#define KTOP 256
#define NEGV (-1e9f)
#define EPSV 1e-5f
#define LLN 2
#define SCALE 0.125f

__device__ float g_x[NTOK*DD];
__device__ float g_h[NTOK*DD];
__device__ float g_m[NTOK*DD];
__device__ float g_q[NTOK*DD];
__device__ float g_k[NTOK*DD];
__device__ float g_v[NTOK*DD];
__device__ float g_ao[NTOK*DD];
__device__ float g_moe[NTOK*DD];
__device__ float g_qi[NTOK*HHI*DII];
__device__ float g_ki[NTOK*HHI*DII];
__device__ float g_mask[(size_t)BB*SSL*SSL];
__device__ int g_ecount[EE];
__device__ int g_elist[EE*NTOK];
__device__ float g_egate[EE*NTOK];
__device__ alignas(16) __nv_bfloat16 g_hhi[NTOK*DD];
__device__ alignas(16) __nv_bfloat16 g_hlo[NTOK*DD];
__device__ alignas(16) __nv_bfloat16 g_mhi[NTOK*DD];
__device__ alignas(16) __nv_bfloat16 g_mlo[NTOK*DD];
__device__ alignas(16) __nv_bfloat16 g_owThi[(size_t)VV*DD];
__device__ alignas(16) __nv_bfloat16 g_owTlo[(size_t)VV*DD];
__device__ alignas(16) __nv_bfloat16 g_w1Thi[(size_t)LLN*EE*FFD*DD];
__device__ alignas(16) __nv_bfloat16 g_w1Tlo[(size_t)LLN*EE*FFD*DD];
__device__ alignas(16) __nv_bfloat16 g_w2Thi[(size_t)LLN*EE*DD*FFD];
__device__ alignas(16) __nv_bfloat16 g_w2Tlo[(size_t)LLN*EE*DD*FFD];
__device__ alignas(16) __nv_bfloat16 g_h1hi[(size_t)EE*NTOK*FFD];
__device__ alignas(16) __nv_bfloat16 g_h1lo[(size_t)EE*NTOK*FFD];

__device__ __forceinline__ float gelu_tanh(float x){
    float x3 = x*x*x;
    return 0.5f*x*(1.f + tanhf(0.7978845608028654f*(x + 0.044715f*x3)));
}
__global__ void k_zerof(float* p, int n){ int i=blockIdx.x*blockDim.x+threadIdx.x; if(i<n)p[i]=0.f; }
__global__ void k_zeroi(int* p, int n){ int i=threadIdx.x; if(i<n)p[i]=0; }
__global__ void k_add(float* x, const float* y, int n){ int i=blockIdx.x*blockDim.x+threadIdx.x; if(i<n)x[i]+=y[i]; }

__global__ void k_embed(const int* __restrict__ ids, const float* __restrict__ tok, const float* __restrict__ pos){
    int n=blockIdx.x, t=threadIdx.x;
    g_x[(size_t)n*DD+t] = tok[(size_t)ids[n]*DD+t] + pos[(size_t)(n%SSL)*DD+t];
}

// layernorm; optionally emits bf16 hi/lo split of the output
__global__ __launch_bounds__(256) void k_ln(const float* __restrict__ in, const float* __restrict__ g,
        const float* __restrict__ b, float* __restrict__ out,
        __nv_bfloat16* __restrict__ hi, __nv_bfloat16* __restrict__ lo){
    int r=blockIdx.x, t=threadIdx.x;
    __shared__ float red[256];
    float v0=in[(size_t)r*DD+t], v1=in[(size_t)r*DD+t+256];
    red[t]=v0+v1; __syncthreads();
    for(int s=128;s>0;s>>=1){ if(t<s)red[t]+=red[t+s]; __syncthreads(); }
    float mu=red[0]*(1.0f/DD); __syncthreads();
    float d0=v0-mu, d1=v1-mu;
    red[t]=d0*d0+d1*d1; __syncthreads();
    for(int s=128;s>0;s>>=1){ if(t<s)red[t]+=red[t+s]; __syncthreads(); }
    float rs=rsqrtf(red[0]*(1.0f/DD)+EPSV);
    float o0=d0*rs*g[t]+b[t];
    float o1=d1*rs*g[t+256]+b[t+256];
    out[(size_t)r*DD+t]=o0;
    out[(size_t)r*DD+t+256]=o1;
    if(hi){
        __nv_bfloat16 h0=__float2bfloat16(o0), h1=__float2bfloat16(o1);
        hi[(size_t)r*DD+t]=h0;
        hi[(size_t)r*DD+t+256]=h1;
        lo[(size_t)r*DD+t]=__float2bfloat16(o0-__bfloat162float(h0));
        lo[(size_t)r*DD+t+256]=__float2bfloat16(o1-__bfloat162float(h1));
    }
}

// batched: W[z][K][N] fp32 -> T[z][N][K] bf16 hi/lo
__global__ __launch_bounds__(256) void k_transcvtB(const float* __restrict__ W,
        __nv_bfloat16* __restrict__ Thi, __nv_bfloat16* __restrict__ Tlo, int K, int N){
    int z=blockIdx.z;
    W   += (size_t)z*K*N;
    Thi += (size_t)z*N*K;
    Tlo += (size_t)z*N*K;
    __shared__ float t[32][33];
    int n0=blockIdx.x*32, k0=blockIdx.y*32;
    int tx=threadIdx.x&31, ty=threadIdx.x>>5;
    for(int i=ty;i<32;i+=8) t[i][tx]=W[(size_t)(k0+i)*N + n0+tx];
    __syncthreads();
    for(int i=ty;i<32;i+=8){
        float v=t[tx][i];
        __nv_bfloat16 h=__float2bfloat16(v);
        size_t o=(size_t)(n0+i)*K + k0+tx;
        Thi[o]=h; Tlo[o]=__float2bfloat16(v-__bfloat162float(h));
    }
}

// ================= HMMA bf16-split GEMM core =================
__device__ __forceinline__ uint32_t smem_u32(const void* p){
    uint32_t a;
    asm("{ .reg .u64 t; cvta.to.shared.u64 t, %1; cvt.u32.u64 %0, t; }" : "=r"(a) : "l"(p));
    return a;
}
__device__ __forceinline__ void ldsm4(uint32_t (&r)[4], uint32_t a){
    asm volatile("ldmatrix.sync.aligned.m8n8.x4.shared.b16 {%0,%1,%2,%3}, [%4];"
        : "=r"(r[0]),"=r"(r[1]),"=r"(r[2]),"=r"(r[3]) : "r"(a));
}
__device__ __forceinline__ void ldsm2(uint32_t (&r)[2], uint32_t a){
    asm volatile("ldmatrix.sync.aligned.m8n8.x2.shared.b16 {%0,%1}, [%2];"
        : "=r"(r[0]),"=r"(r[1]) : "r"(a));
}
__device__ __forceinline__ void mma16816(float (&c)[4], const uint32_t (&a)[4], const uint32_t (&b)[2]){
    asm volatile("mma.sync.aligned.m16n8k16.row.col.f32.bf16.bf16.f32 "
        "{%0,%1,%2,%3}, {%4,%5,%6,%7}, {%8,%9}, {%0,%1,%2,%3};"
        : "+f"(c[0]),"+f"(c[1]),"+f"(c[2]),"+f"(c[3])
        : "r"(a[0]),"r"(a[1]),"r"(a[2]),"r"(a[3]), "r"(b[0]),"r"(b[1]));
}
#define HS_BUF 24576
#define HS_TILE 6144
#define HS_TOTAL 49664

__device__ __forceinline__ void hmma_main(char* sm, const int* rowidx,
    const __nv_bfloat16* __restrict__ Ahi, const __nv_bfloat16* __restrict__ Alo, int sA,
    const __nv_bfloat16* __restrict__ Bhi, const __nv_bfloat16* __restrict__ Blo, int sB,
    int col0, int K, float (&acc)[4][4][4])
{
    int tid=threadIdx.x, lane=tid&31, warp=tid>>5;
    int wm=warp>>2, wn=warp&3;
    uint32_t smb = smem_u32(sm);
    #pragma unroll
    for(int i=0;i<4;i++)
        #pragma unroll
        for(int j=0;j<4;j++)
            #pragma unroll
            for(int q=0;q<4;q++) acc[i][j][q]=0.f;

    int ltile[4], lrow[4], lhalf[4];
    #pragma unroll
    for(int t=0;t<4;t++){
        int i = tid + t*256;
        ltile[t]=i>>8; lrow[t]=(i&255)>>1; lhalf[t]=(i&1)*8;
    }
    uint4 pre[4];
    const int NS = K>>4;
    int lb = lane&15;
    uint32_t boff = (uint32_t)((wn*32 + (lb&7))*48 + ((lb&8)?16:0));
    uint32_t aoff = (uint32_t)((wm*64 + (lane&7) + ((lane&8)?8:0))*48 + ((lane&16)?16:0));

    auto ldg = [&](int s){
        int k0 = s<<4;
        #pragma unroll
        for(int t=0;t<4;t++){
            const __nv_bfloat16* src;
            int row=lrow[t];
            if(ltile[t]==0)      src = Ahi + (size_t)rowidx[row]*sA;
            else if(ltile[t]==1) src = Alo + (size_t)rowidx[row]*sA;
            else if(ltile[t]==2) src = Bhi + (size_t)(col0+row)*sB;
            else                 src = Blo + (size_t)(col0+row)*sB;
            pre[t] = *(const uint4*)(src + k0 + lhalf[t]);
        }
    };
    auto sts = [&](int b){
        #pragma unroll
        for(int t=0;t<4;t++)
            *(uint4*)(sm + b*HS_BUF + ltile[t]*HS_TILE + lrow[t]*48 + lhalf[t]*2) = pre[t];
    };
    ldg(0); sts(0);
    __syncthreads();
    for(int s=0;s<NS;s++){
        int b=s&1;
        if(s+1<NS) ldg(s+1);
        uint32_t base = smb + b*HS_BUF;
        uint32_t bh[4][2], bl[4][2];
        #pragma unroll
        for(int j=0;j<4;j++){
            ldsm2(bh[j], base + 2*HS_TILE + boff + j*8*48);
            ldsm2(bl[j], base + 3*HS_TILE + boff + j*8*48);
        }
        #pragma unroll
        for(int i=0;i<4;i++){
            uint32_t a[4];
            ldsm4(a, base + aoff + i*16*48);
            #pragma unroll
            for(int j=0;j<4;j++){ mma16816(acc[i][j], a, bh[j]); mma16816(acc[i][j], a, bl[j]); }
            ldsm4(a, base + HS_TILE + aoff + i*16*48);
            #pragma unroll
            for(int j=0;j<4;j++) mma16816(acc[i][j], a, bh[j]);
        }
        if(s+1<NS) sts(b^1);
        __syncthreads();
    }
}

// ---- vocab: out = h(split) @ owT^T + ob ----
__global__ __launch_bounds__(256,1) void k_hmma_vocab(const float* __restrict__ ob, float* __restrict__ out){
    extern __shared__ char sm[];
    int* rowidx = (int*)(sm + 2*HS_BUF);
    int tid=threadIdx.x;
    int row0=blockIdx.y*128, col0=blockIdx.x*128;
    if(tid<128) rowidx[tid]=row0+tid;
    __syncthreads();
    float acc[4][4][4];
    hmma_main(sm, rowidx, g_hhi, g_hlo, DD, g_owThi, g_owTlo, DD, col0, DD, acc);
    int lane=tid&31, warp=tid>>5, wm=warp>>2, wn=warp&3;
    #pragma unroll
    for(int i=0;i<4;i++){
        int r0 = row0 + wm*64 + i*16 + (lane>>2);
        #pragma unroll
        for(int j=0;j<4;j++){
            int c = col0 + wn*32 + j*8 + (lane&3)*2;
            float b0=ob[c], b1=ob[c+1];
            out[(size_t)r0*VV + c]       = acc[i][j][0] + b0;
            out[(size_t)r0*VV + c+1]     = acc[i][j][1] + b1;
            out[(size_t)(r0+8)*VV + c]   = acc[i][j][2] + b0;
            out[(size_t)(r0+8)*VV + c+1] = acc[i][j][3] + b1;
        }
    }
}

// ---- MoE1 ----
__global__ __launch_bounds__(256,1) void k_hmma_moe1(const __nv_bfloat16* __restrict__ Whi,
        const __nv_bfloat16* __restrict__ Wlo, const float* __restrict__ B1){
    int e=blockIdx.z, cnt=g_ecount[e], row0=blockIdx.y*128;
    if(row0>=cnt) return;
    extern __shared__ char sm[];
    int* rowidx = (int*)(sm + 2*HS_BUF);
    int tid=threadIdx.x;
    int col0=blockIdx.x*128;
    if(tid<128){
        int r=row0+tid;
        rowidx[tid] = (r<cnt)? g_elist[e*NTOK+r] : g_elist[e*NTOK];
    }
    __syncthreads();
    float acc[4][4][4];
    hmma_main(sm, rowidx, g_mhi, g_mlo, DD,
              Whi+(size_t)e*FFD*DD, Wlo+(size_t)e*FFD*DD, DD, col0, DD, acc);
    const float* bia = B1 + (size_t)e*FFD;
    int lane=tid&31, warp=tid>>5, wm=warp>>2, wn=warp&3;
    #pragma unroll
    for(int i=0;i<4;i++){
        int r0 = row0 + wm*64 + i*16 + (lane>>2);
        #pragma unroll
        for(int j=0;j<4;j++){
            int c = col0 + wn*32 + j*8 + (lane&3)*2;
            float b0=bia[c], b1=bia[c+1];
            #pragma unroll
            for(int q=0;q<4;q++){
                int r = r0 + (q>=2?8:0);
                if(r>=cnt) continue;
                int cc = c + (q&1);
                float v = gelu_tanh(acc[i][j][q] + ((q&1)?b1:b0));
                __nv_bfloat16 h=__float2bfloat16(v);
                size_t o = ((size_t)e*NTOK + r)*FFD + cc;
                g_h1hi[o]=h; g_h1lo[o]=__float2bfloat16(v-__bfloat162float(h));
            }
        }
    }
}

// ---- MoE2 ----
__global__ __launch_bounds__(256,1) void k_hmma_moe2(const __nv_bfloat16* __restrict__ Whi,
        const __nv_bfloat16* __restrict__ Wlo, const float* __restrict__ B2){
    int e=blockIdx.z, cnt=g_ecount[e], row0=blockIdx.y*128;
    if(row0>=cnt) return;
    extern __shared__ char sm[];
    int* rowidx = (int*)(sm + 2*HS_BUF);
    int tid=threadIdx.x;
    int col0=blockIdx.x*128;
    if(tid<128) rowidx[tid] = e*NTOK + row0 + tid;
    __syncthreads();
    float acc[4][4][4];
    hmma_main(sm, rowidx, g_h1hi, g_h1lo, FFD,
              Whi+(size_t)e*DD*FFD, Wlo+(size_t)e*DD*FFD, FFD, col0, FFD, acc);
    const float* bia = B2 + (size_t)e*DD;
    int lane=tid&31, warp=tid>>5, wm=warp>>2, wn=warp&3;
    #pragma unroll
    for(int i=0;i<4;i++){
        int r0 = row0 + wm*64 + i*16 + (lane>>2);
        #pragma unroll
        for(int j=0;j<4;j++){
            int c = col0 + wn*32 + j*8 + (lane&3)*2;
            float b0=bia[c], b1=bia[c+1];
            #pragma unroll
            for(int q=0;q<4;q++){
                int r = r0 + (q>=2?8:0);
                if(r>=cnt) continue;
                int tok=g_elist[e*NTOK+r];
                float gv=g_egate[e*NTOK+r];
                int cc = c + (q&1);
                atomicAdd(&g_moe[(size_t)tok*DD+cc], gv*(acc[i][j][q] + ((q&1)?b1:b0)));
            }
        }
    }
}

// ===== fp32 128x128 SGEMM (projections) =====
struct B3 { const float *B0,*B1,*B2; const float *c0,*c1,*c2; float *C0,*C1,*C2; };
__device__ __forceinline__ void gemm128_body(const float* __restrict__ A, const float* __restrict__ B,
    const float* __restrict__ bias, const float* __restrict__ res, float* __restrict__ C, int N, int K){
    __shared__ float As[2][8][132];
    __shared__ float Bs[2][8][128];
    int tid=threadIdx.x;
    int row0=blockIdx.y*128, col0=blockIdx.x*128;
    int arow=tid>>1, acol=(tid&1)*4;
    int brow=tid>>5, bcol=(tid&31)*4;
    const float* Aptr=A+(size_t)(row0+arow)*K+acol;
    const float* Bptr=B+(size_t)brow*N+col0+bcol;
    float4 a4=*(const float4*)Aptr;
    float4 b4=*(const float4*)Bptr;
    As[0][acol+0][arow]=a4.x; As[0][acol+1][arow]=a4.y; As[0][acol+2][arow]=a4.z; As[0][acol+3][arow]=a4.w;
    *(float4*)&Bs[0][brow][bcol]=b4;
    __syncthreads();
    int tx=tid&15, ty=tid>>4;
    float acc[8][8]={};
    int buf=0;
    for(int k0=8;k0<=K;k0+=8){
        if(k0<K){ a4=*(const float4*)(Aptr+k0); b4=*(const float4*)(Bptr+(size_t)k0*N); }
        #pragma unroll
        for(int kk=0;kk<8;kk++){
            float4 a0=*(const float4*)&As[buf][kk][ty*8];
            float4 a1=*(const float4*)&As[buf][kk][ty*8+4];
            float4 b0=*(const float4*)&Bs[buf][kk][tx*8];
            float4 b1=*(const float4*)&Bs[buf][kk][tx*8+4];
            float av[8]={a0.x,a0.y,a0.z,a0.w,a1.x,a1.y,a1.z,a1.w};
            float bv[8]={b0.x,b0.y,b0.z,b0.w,b1.x,b1.y,b1.z,b1.w};
            #pragma unroll
            for(int i=0;i<8;i++)
                #pragma unroll
                for(int j=0;j<8;j++) acc[i][j]+=av[i]*bv[j];
        }
        if(k0<K){
            buf^=1;
            As[buf][acol+0][arow]=a4.x; As[buf][acol+1][arow]=a4.y; As[buf][acol+2][arow]=a4.z; As[buf][acol+3][arow]=a4.w;
            *(float4*)&Bs[buf][brow][bcol]=b4;
            __syncthreads();
        }
    }
    #pragma unroll
    for(int i=0;i<8;i++){
        int r=row0+ty*8+i;
        #pragma unroll
        for(int j=0;j<8;j+=4){
            int c=col0+tx*8+j;
            float4 v={acc[i][j],acc[i][j+1],acc[i][j+2],acc[i][j+3]};
            if(bias){ float4 bb=*(const float4*)&bias[c]; v.x+=bb.x;v.y+=bb.y;v.z+=bb.z;v.w+=bb.w; }
            if(res){ float4 rr=*(const float4*)&res[(size_t)r*N+c]; v.x+=rr.x;v.y+=rr.y;v.z+=rr.z;v.w+=rr.w; }
            *(float4*)&C[(size_t)r*N+c]=v;
        }
    }
}
__global__ __launch_bounds__(256) void k_gemm128(const float* __restrict__ A, const float* __restrict__ B,
    const float* __restrict__ bias, const float* __restrict__ res, float* __restrict__ C, int N, int K){
    gemm128_body(A,B,bias,res,C,N,K);
}
__global__ __launch_bounds__(256) void k_gemm128b3(const float* __restrict__ A, B3 p, int N, int K){
    const float *B,*bias; float *C;
    if(blockIdx.z==0){B=p.B0;bias=p.c0;C=p.C0;}
    else if(blockIdx.z==1){B=p.B1;bias=p.c1;C=p.C1;}
    else {B=p.B2;bias=p.c2;C=p.C2;}
    gemm128_body(A,B,bias,nullptr,C,N,K);
}

// ===== indexer scores =====
__global__ __launch_bounds__(256) void k_idxscore(const float* __restrict__ hw){
    int kt=blockIdx.x, qt=blockIdx.y, b=blockIdx.z;
    int tx=threadIdx.x&15, ty=threadIdx.x>>4;
    __shared__ float Qs[64][68];
    __shared__ float Ks[64][68];
    float acc[4][4]={};
    for(int h=0;h<HHI;h++){
        for(int i=threadIdx.x;i<4096;i+=256){
            int r=i>>6, d=i&63;
            Qs[d][r]=g_qi[(size_t)(b*SSL+qt*64+r)*(HHI*DII)+h*64+d];
            Ks[d][r]=g_ki[(size_t)(b*SSL+kt*64+r)*(HHI*DII)+h*64+d];
        }
        __syncthreads();
        float w=hw[h];
        float dot[4][4]={};
        #pragma unroll 8
        for(int d=0;d<64;d++){
            float4 a4=*(const float4*)&Qs[d][ty*4];
            float4 b4=*(const float4*)&Ks[d][tx*4];
            float a[4]={a4.x,a4.y,a4.z,a4.w};
            float bb[4]={b4.x,b4.y,b4.z,b4.w};
            #pragma unroll
            for(int i=0;i<4;i++)
                #pragma unroll
                for(int j=0;j<4;j++) dot[i][j]+=a[i]*bb[j];
        }
        #pragma unroll
        for(int i=0;i<4;i++)
            #pragma unroll
            for(int j=0;j<4;j++) acc[i][j]+=fmaxf(dot[i][j],0.f)*w;
        __syncthreads();
    }
    #pragma unroll
    for(int i=0;i<4;i++){
        int q=qt*64+ty*4+i;
        #pragma unroll
        for(int j=0;j<4;j++){
            int k=kt*64+tx*4+j;
            g_mask[((size_t)b*SSL+q)*SSL+k]=acc[i][j]+((k<=q)?0.f:NEGV);
        }
    }
}

// ===== top-K bitonic =====
__global__ __launch_bounds__(512) void k_topk(){
    int q=blockIdx.x, b=blockIdx.y, t=threadIdx.x;
    __shared__ float s[1024];
    size_t base=((size_t)b*SSL+q)*SSL;
    s[t]=g_mask[base+t];
    s[t+512]=g_mask[base+t+512];
    __syncthreads();
    for(int size=2;size<=1024;size<<=1){
        for(int stride=size>>1;stride>0;stride>>=1){
            int lo=2*stride*(t/stride)+(t%stride);
            int hi=lo+stride;
            bool desc=((lo&size)==0);
            float a=s[lo], bv=s[hi];
            if((a<bv)==desc){ s[lo]=bv; s[hi]=a; }
            __syncthreads();
        }
    }
    float thr=s[KTOP-1];
    for(int k=t;k<SSL;k+=512){
        float v=g_mask[base+k];
        g_mask[base+k]=(k<=q && v>=thr)?0.f:NEGV;
    }
}

// ===== attention: conflict-free float4 inner loops =====
// thread = (row = t>>4, cg = t&15); QK cols kc=j*16+cg; PV dims d=cg*4+j
__global__ __launch_bounds__(256) void k_attn(){
    int qt=blockIdx.x, h=blockIdx.y, b=blockIdx.z;
    int t=threadIdx.x, row=t>>4, cg=t&15;
    __shared__ float qs[16][68];
    __shared__ float Ks[64][68];
    __shared__ float Vs[64][68];
    __shared__ float Sc[16][68];
    __shared__ float mrow[16], lrow[16];
    int q0=qt*16;
    for(int i=t;i<16*64;i+=256){
        int r=i>>6, d=i&63;
        qs[r][d]=g_q[(size_t)(b*SSL+q0+r)*DD+h*64+d];
    }
    if(t<16){ mrow[t]=-1e30f; lrow[t]=0.f; }
    float oacc[4]={0.f,0.f,0.f,0.f};
    __syncthreads();
    const float* maskrow=g_mask+((size_t)b*SSL+(q0+row))*SSL;
    for(int k0=0;k0<SSL;k0+=64){
        for(int i=t;i<4096;i+=256){
            int r=i>>6, d=i&63;
            Ks[r][d]=g_k[(size_t)(b*SSL+k0+r)*DD+h*64+d];
            Vs[r][d]=g_v[(size_t)(b*SSL+k0+r)*DD+h*64+d];
        }
        __syncthreads();
        // QK with float4 over d; kc = j*16+cg (conflict-free, broadcast across half-warps)
        float sv[4]={0.f,0.f,0.f,0.f};
        #pragma unroll
        for(int d0=0;d0<64;d0+=4){
            float4 q4=*(const float4*)&qs[row][d0];
            #pragma unroll
            for(int j=0;j<4;j++){
                float4 k4=*(const float4*)&Ks[j*16+cg][d0];
                sv[j]+=q4.x*k4.x+q4.y*k4.y+q4.z*k4.z+q4.w*k4.w;
            }
        }
        #pragma unroll
        for(int j=0;j<4;j++) sv[j]=sv[j]*SCALE+maskrow[k0+j*16+cg];
        // online softmax (parallel over 16 lanes per row)
        float mold=mrow[row], lold=lrow[row];
        float tmax=fmaxf(fmaxf(sv[0],sv[1]),fmaxf(sv[2],sv[3]));
        tmax=fmaxf(tmax,mold);
        #pragma unroll
        for(int off=8;off>0;off>>=1) tmax=fmaxf(tmax,__shfl_xor_sync(0xffffffffu,tmax,off,16));
        float c=__expf(mold-tmax);
        float lsum=0.f;
        #pragma unroll
        for(int j=0;j<4;j++){
            float p=__expf(sv[j]-tmax);
            Sc[row][j*16+cg]=p;
            lsum+=p;
        }
        #pragma unroll
        for(int off=8;off>0;off>>=1) lsum+=__shfl_xor_sync(0xffffffffu,lsum,off,16);
        if(cg==0){ mrow[row]=tmax; lrow[row]=lold*c+lsum; }
        __syncwarp();
        // PV: dims d = cg*4+j via float4 on Vs rows
        #pragma unroll
        for(int j=0;j<4;j++) oacc[j]*=c;
        #pragma unroll
        for(int k=0;k<64;k++){
            float s=Sc[row][k];
            float4 v4=*(const float4*)&Vs[k][cg*4];
            oacc[0]+=s*v4.x; oacc[1]+=s*v4.y; oacc[2]+=s*v4.z; oacc[3]+=s*v4.w;
        }
        __syncthreads();
    }
    float linv=1.0f/lrow[row];
    float4 o4={oacc[0]*linv,oacc[1]*linv,oacc[2]*linv,oacc[3]*linv};
    *(float4*)&g_ao[(size_t)(b*SSL+q0+row)*DD+h*64+cg*4]=o4;
}

// ===== fused router: dot products + softmax + top-2 + bucketing =====
__global__ __launch_bounds__(256) void k_router(const float* __restrict__ rw, const float* __restrict__ rb){
    int n=blockIdx.x;
    int t=threadIdx.x, e=t>>5, lane=t&31;
    __shared__ float ms[DD];
    __shared__ float pe[EE];
    for(int i=t;i<DD;i+=256) ms[i]=g_m[(size_t)n*DD+i];
    __syncthreads();
    float s=0.f;
    for(int k=lane;k<DD;k+=32) s+=ms[k]*rw[k*EE+e];
    #pragma unroll
    for(int off=16;off>0;off>>=1) s+=__shfl_xor_sync(0xffffffffu,s,off);
    if(lane==0) pe[e]=s+rb[e];
    __syncthreads();
    if(t==0){
        float p[EE]; float mx=-1e30f;
        #pragma unroll
        for(int i=0;i<EE;i++){ p[i]=pe[i]; mx=fmaxf(mx,p[i]); }
        #pragma unroll
        for(int i=0;i<EE;i++) p[i]=__expf(p[i]-mx);
        int e1=0;
        for(int i=1;i<EE;i++) if(p[i]>p[e1]) e1=i;
        int e2=-1;
        for(int i=0;i<EE;i++) if(i!=e1 && (e2<0 || p[i]>p[e2])) e2=i;
        float den=p[e1]+p[e2];
        int pos=atomicAdd(&g_ecount[e1],1);
        g_elist[e1*NTOK+pos]=n; g_egate[e1*NTOK+pos]=p[e1]/den;
        pos=atomicAdd(&g_ecount[e2],1);
        g_elist[e2*NTOK+pos]=n; g_egate[e2*NTOK+pos]=p[e2]/den;
    }
}

// ===== host =====
extern "C" void kernel_launch(void* const* d_in, const int* in_sizes, int n_in,
                              void* d_out, int out_size){
    (void)in_sizes; (void)n_in; (void)out_size;
    const int*   ids  = (const int*)  d_in[0];
    const float* tok  = (const float*)d_in[1];
    const float* pos  = (const float*)d_in[2];
    const float* ln1g = (const float*)d_in[3];
    const float* ln1b = (const float*)d_in[4];
    const float* iqw  = (const float*)d_in[5];
    const float* iqb  = (const float*)d_in[6];
    const float* ikw  = (const float*)d_in[7];
    const float* ikb  = (const float*)d_in[8];
    const float* ihw  = (const float*)d_in[9];
    const float* wq   = (const float*)d_in[10];
    const float* bq   = (const float*)d_in[11];
    const float* wk   = (const float*)d_in[12];
    const float* bk   = (const float*)d_in[13];
    const float* wv   = (const float*)d_in[14];
    const float* bv   = (const float*)d_in[15];
    const float* wo   = (const float*)d_in[16];
    const float* bo   = (const float*)d_in[17];
    const float* ln2g = (const float*)d_in[18];
    const float* ln2b = (const float*)d_in[19];
    const float* rw   = (const float*)d_in[20];
    const float* rb   = (const float*)d_in[21];
    const float* ew1  = (const float*)d_in[22];
    const float* eb1  = (const float*)d_in[23];
    const float* ew2  = (const float*)d_in[24];
    const float* eb2  = (const float*)d_in[25];
    const float* lnfg = (const float*)d_in[26];
    const float* lnfb = (const float*)d_in[27];
    const float* ow   = (const float*)d_in[28];
    const float* ob   = (const float*)d_in[29];
    float* out = (float*)d_out;

    float *px,*ph,*pm,*pq,*pk,*pv,*pao,*pqi,*pki,*pmoe;
    int *pec;
    __nv_bfloat16 *phhi,*phlo,*pmhi,*pmlo,*powThi,*powTlo,*pw1Thi,*pw1Tlo,*pw2Thi,*pw2Tlo;
    cudaGetSymbolAddress((void**)&px,g_x);
    cudaGetSymbolAddress((void**)&ph,g_h);
    cudaGetSymbolAddress((void**)&pm,g_m);
    cudaGetSymbolAddress((void**)&pq,g_q);
    cudaGetSymbolAddress((void**)&pk,g_k);
    cudaGetSymbolAddress((void**)&pv,g_v);
    cudaGetSymbolAddress((void**)&pao,g_ao);
    cudaGetSymbolAddress((void**)&pqi,g_qi);
    cudaGetSymbolAddress((void**)&pki,g_ki);
    cudaGetSymbolAddress((void**)&pmoe,g_moe);
    cudaGetSymbolAddress((void**)&pec,g_ecount);
    cudaGetSymbolAddress((void**)&phhi,g_hhi);
    cudaGetSymbolAddress((void**)&phlo,g_hlo);
    cudaGetSymbolAddress((void**)&pmhi,g_mhi);
    cudaGetSymbolAddress((void**)&pmlo,g_mlo);
    cudaGetSymbolAddress((void**)&powThi,g_owThi);
    cudaGetSymbolAddress((void**)&powTlo,g_owTlo);
    cudaGetSymbolAddress((void**)&pw1Thi,g_w1Thi);
    cudaGetSymbolAddress((void**)&pw1Tlo,g_w1Tlo);
    cudaGetSymbolAddress((void**)&pw2Thi,g_w2Thi);
    cudaGetSymbolAddress((void**)&pw2Tlo,g_w2Tlo);

    cudaFuncSetAttribute(k_hmma_vocab, cudaFuncAttributeMaxDynamicSharedMemorySize, HS_TOTAL);
    cudaFuncSetAttribute(k_hmma_moe1,  cudaFuncAttributeMaxDynamicSharedMemorySize, HS_TOTAL);
    cudaFuncSetAttribute(k_hmma_moe2,  cudaFuncAttributeMaxDynamicSharedMemorySize, HS_TOTAL);

    // weight transposes + bf16 splits
    k_transcvtB<<<dim3(VV/32, DD/32, 1),256>>>(ow, powThi, powTlo, DD, VV);
    k_transcvtB<<<dim3(FFD/32, DD/32, LLN*EE),256>>>(ew1, pw1Thi, pw1Tlo, DD, FFD);
    k_transcvtB<<<dim3(DD/32, FFD/32, LLN*EE),256>>>(ew2, pw2Thi, pw2Tlo, FFD, DD);

    k_embed<<<NTOK,512>>>(ids, tok, pos);

    for(int l=0;l<LLN;l++){
        k_ln<<<NTOK,256>>>(px, ln1g+l*DD, ln1b+l*DD, ph, nullptr, nullptr);
        {   B3 p;
            p.B0=iqw+(size_t)l*DD*HHI*DII; p.c0=iqb+l*HHI*DII; p.C0=pqi;
            p.B1=ikw+(size_t)l*DD*HHI*DII; p.c1=ikb+l*HHI*DII; p.C1=pki;
            p.B2=p.B0; p.c2=p.c0; p.C2=pqi;
            k_gemm128b3<<<dim3(2,16,2),256>>>(ph, p, HHI*DII, DD);
        }
        k_idxscore<<<dim3(SSL/64,SSL/64,BB),256>>>(ihw+l*HHI);
        k_topk<<<dim3(SSL,BB),512>>>();
        {   B3 p;
            p.B0=wq+(size_t)l*DD*DD; p.c0=bq+l*DD; p.C0=pq;
            p.B1=wk+(size_t)l*DD*DD; p.c1=bk+l*DD; p.C1=pk;
            p.B2=wv+(size_t)l*DD*DD; p.c2=bv+l*DD; p.C2=pv;
            k_gemm128b3<<<dim3(4,16,3),256>>>(ph, p, DD, DD);
        }
        k_attn<<<dim3(SSL/16,HHN,BB),256>>>();
        k_gemm128<<<dim3(4,16),256>>>(pao, wo+(size_t)l*DD*DD, bo+l*DD, px, px, DD, DD);

        k_ln<<<NTOK,256>>>(px, ln2g+l*DD, ln2b+l*DD, pm, pmhi, pmlo);
        k_zeroi<<<1,32>>>(pec, EE);
        k_router<<<NTOK,256>>>(rw+(size_t)l*DD*EE, rb+l*EE);
        k_zerof<<<(NTOK*DD)/256,256>>>(pmoe, NTOK*DD);
        k_hmma_moe1<<<dim3(FFD/128, NTOK/128, EE),256,HS_TOTAL>>>(
            pw1Thi+(size_t)l*EE*FFD*DD, pw1Tlo+(size_t)l*EE*FFD*DD, eb1+(size_t)l*EE*FFD);
        k_hmma_moe2<<<dim3(DD/128, NTOK/128, EE),256,HS_TOTAL>>>(
            pw2Thi+(size_t)l*EE*DD*FFD, pw2Tlo+(size_t)l*EE*DD*FFD, eb2+(size_t)l*EE*DD);
        k_add<<<(NTOK*DD)/256,256>>>(px, pmoe, NTOK*DD);
    }

    k_ln<<<NTOK,256>>>(px, lnfg, lnfb, ph, phhi, phlo);
    k_hmma_vocab<<<dim3(VV/128, NTOK/128),256,HS_TOTAL>>>(ob, out);
}

// round 9
// speedup vs baseline: 1.8244x; 1.1523x over previous
#include <cuda_runtime.h>
#include <cuda_bf16.h>
#include <math.h>
#include <stdint.h>

#define BB 2
#define SSL 1024
#define NTOK 2048
#define DD 512
#define HHN 8
#define HHI 4
#define DII 64
#define FFD 2048
#define EE 8
#define VV 32000
#define KTOP 256
#define NEGV (-1e9f)
#define EPSV 1e-5f
#define LLN 2
#define SCALE 0.125f

__device__ float g_x[NTOK*DD];
__device__ float g_h[NTOK*DD];
__device__ float g_m[NTOK*DD];
__device__ float g_q[NTOK*DD];
__device__ float g_k[NTOK*DD];
__device__ float g_v[NTOK*DD];
__device__ float g_ao[NTOK*DD];
__device__ float g_moe[NTOK*DD];
__device__ float g_mask[(size_t)BB*SSL*SSL];
__device__ int g_ecount[EE];
__device__ int g_elist[EE*NTOK];
__device__ float g_egate[EE*NTOK];
__device__ alignas(16) __nv_bfloat16 g_hhi[NTOK*DD];
__device__ alignas(16) __nv_bfloat16 g_hlo[NTOK*DD];
__device__ alignas(16) __nv_bfloat16 g_mhi[NTOK*DD];
__device__ alignas(16) __nv_bfloat16 g_mlo[NTOK*DD];
__device__ alignas(16) float g_qi[NTOK*HHI*DII];
__device__ alignas(16) float g_ki[NTOK*HHI*DII];
__device__ alignas(16) __nv_bfloat16 g_owThi[(size_t)VV*DD];
__device__ alignas(16) __nv_bfloat16 g_owTlo[(size_t)VV*DD];
__device__ alignas(16) __nv_bfloat16 g_w1Thi[(size_t)LLN*EE*FFD*DD];
__device__ alignas(16) __nv_bfloat16 g_w1Tlo[(size_t)LLN*EE*FFD*DD];
__device__ alignas(16) __nv_bfloat16 g_w2Thi[(size_t)LLN*EE*DD*FFD];
__device__ alignas(16) __nv_bfloat16 g_w2Tlo[(size_t)LLN*EE*DD*FFD];
__device__ alignas(16) __nv_bfloat16 g_h1hi[(size_t)EE*NTOK*FFD];
__device__ alignas(16) __nv_bfloat16 g_h1lo[(size_t)EE*NTOK*FFD];
__device__ alignas(16) __nv_bfloat16 g_wqThi[LLN*DD*DD];
__device__ alignas(16) __nv_bfloat16 g_wqTlo[LLN*DD*DD];
__device__ alignas(16) __nv_bfloat16 g_wkThi[LLN*DD*DD];
__device__ alignas(16) __nv_bfloat16 g_wkTlo[LLN*DD*DD];
__device__ alignas(16) __nv_bfloat16 g_wvThi[LLN*DD*DD];
__device__ alignas(16) __nv_bfloat16 g_wvTlo[LLN*DD*DD];
__device__ alignas(16) __nv_bfloat16 g_iqThi[LLN*HHI*DII*DD];
__device__ alignas(16) __nv_bfloat16 g_iqTlo[LLN*HHI*DII*DD];
__device__ alignas(16) __nv_bfloat16 g_ikThi[LLN*HHI*DII*DD];
__device__ alignas(16) __nv_bfloat16 g_ikTlo[LLN*HHI*DII*DD];

__device__ __forceinline__ float gelu_tanh(float x){
    float x3 = x*x*x;
    return 0.5f*x*(1.f + tanhf(0.7978845608028654f*(x + 0.044715f*x3)));
}
__global__ void k_zerof(float* p, int n){ int i=blockIdx.x*blockDim.x+threadIdx.x; if(i<n)p[i]=0.f; }
__global__ void k_zeroi(int* p, int n){ int i=threadIdx.x; if(i<n)p[i]=0; }
__global__ void k_add(float* x, const float* y, int n){ int i=blockIdx.x*blockDim.x+threadIdx.x; if(i<n)x[i]+=y[i]; }

__global__ void k_embed(const int* __restrict__ ids, const float* __restrict__ tok, const float* __restrict__ pos){
    int n=blockIdx.x, t=threadIdx.x;
    g_x[(size_t)n*DD+t] = tok[(size_t)ids[n]*DD+t] + pos[(size_t)(n%SSL)*DD+t];
}

// layernorm; optionally emits bf16 hi/lo split of the output
__global__ __launch_bounds__(256) void k_ln(const float* __restrict__ in, const float* __restrict__ g,
        const float* __restrict__ b, float* __restrict__ out,
        __nv_bfloat16* __restrict__ hi, __nv_bfloat16* __restrict__ lo){
    int r=blockIdx.x, t=threadIdx.x;
    __shared__ float red[256];
    float v0=in[(size_t)r*DD+t], v1=in[(size_t)r*DD+t+256];
    red[t]=v0+v1; __syncthreads();
    for(int s=128;s>0;s>>=1){ if(t<s)red[t]+=red[t+s]; __syncthreads(); }
    float mu=red[0]*(1.0f/DD); __syncthreads();
    float d0=v0-mu, d1=v1-mu;
    red[t]=d0*d0+d1*d1; __syncthreads();
    for(int s=128;s>0;s>>=1){ if(t<s)red[t]+=red[t+s]; __syncthreads(); }
    float rs=rsqrtf(red[0]*(1.0f/DD)+EPSV);
    float o0=d0*rs*g[t]+b[t];
    float o1=d1*rs*g[t+256]+b[t+256];
    out[(size_t)r*DD+t]=o0;
    out[(size_t)r*DD+t+256]=o1;
    if(hi){
        __nv_bfloat16 h0=__float2bfloat16(o0), h1=__float2bfloat16(o1);
        hi[(size_t)r*DD+t]=h0;
        hi[(size_t)r*DD+t+256]=h1;
        lo[(size_t)r*DD+t]=__float2bfloat16(o0-__bfloat162float(h0));
        lo[(size_t)r*DD+t+256]=__float2bfloat16(o1-__bfloat162float(h1));
    }
}

// batched: W[z][K][N] fp32 -> T[z][N][K] bf16 hi/lo
__global__ __launch_bounds__(256) void k_transcvtB(const float* __restrict__ W,
        __nv_bfloat16* __restrict__ Thi, __nv_bfloat16* __restrict__ Tlo, int K, int N){
    int z=blockIdx.z;
    W   += (size_t)z*K*N;
    Thi += (size_t)z*N*K;
    Tlo += (size_t)z*N*K;
    __shared__ float t[32][33];
    int n0=blockIdx.x*32, k0=blockIdx.y*32;
    int tx=threadIdx.x&31, ty=threadIdx.x>>5;
    for(int i=ty;i<32;i+=8) t[i][tx]=W[(size_t)(k0+i)*N + n0+tx];
    __syncthreads();
    for(int i=ty;i<32;i+=8){
        float v=t[tx][i];
        __nv_bfloat16 h=__float2bfloat16(v);
        size_t o=(size_t)(n0+i)*K + k0+tx;
        Thi[o]=h; Tlo[o]=__float2bfloat16(v-__bfloat162float(h));
    }
}

// ================= HMMA bf16-split GEMM core =================
__device__ __forceinline__ uint32_t smem_u32(const void* p){
    uint32_t a;
    asm("{ .reg .u64 t; cvta.to.shared.u64 t, %1; cvt.u32.u64 %0, t; }" : "=r"(a) : "l"(p));
    return a;
}
__device__ __forceinline__ void ldsm4(uint32_t (&r)[4], uint32_t a){
    asm volatile("ldmatrix.sync.aligned.m8n8.x4.shared.b16 {%0,%1,%2,%3}, [%4];"
        : "=r"(r[0]),"=r"(r[1]),"=r"(r[2]),"=r"(r[3]) : "r"(a));
}
__device__ __forceinline__ void ldsm2(uint32_t (&r)[2], uint32_t a){
    asm volatile("ldmatrix.sync.aligned.m8n8.x2.shared.b16 {%0,%1}, [%2];"
        : "=r"(r[0]),"=r"(r[1]) : "r"(a));
}
__device__ __forceinline__ void mma16816(float (&c)[4], const uint32_t (&a)[4], const uint32_t (&b)[2]){
    asm volatile("mma.sync.aligned.m16n8k16.row.col.f32.bf16.bf16.f32 "
        "{%0,%1,%2,%3}, {%4,%5,%6,%7}, {%8,%9}, {%0,%1,%2,%3};"
        : "+f"(c[0]),"+f"(c[1]),"+f"(c[2]),"+f"(c[3])
        : "r"(a[0]),"r"(a[1]),"r"(a[2]),"r"(a[3]), "r"(b[0]),"r"(b[1]));
}
#define HS_BUF 24576
#define HS_TILE 6144
#define HS_TOTAL 49664

__device__ __forceinline__ void hmma_main(char* sm, const int* rowidx,
    const __nv_bfloat16* __restrict__ Ahi, const __nv_bfloat16* __restrict__ Alo, int sA,
    const __nv_bfloat16* __restrict__ Bhi, const __nv_bfloat16* __restrict__ Blo, int sB,
    int col0, int K, float (&acc)[4][4][4])
{
    int tid=threadIdx.x, lane=tid&31, warp=tid>>5;
    int wm=warp>>2, wn=warp&3;
    uint32_t smb = smem_u32(sm);
    #pragma unroll
    for(int i=0;i<4;i++)
        #pragma unroll
        for(int j=0;j<4;j++)
            #pragma unroll
            for(int q=0;q<4;q++) acc[i][j][q]=0.f;

    int ltile[4], lrow[4], lhalf[4];
    #pragma unroll
    for(int t=0;t<4;t++){
        int i = tid + t*256;
        ltile[t]=i>>8; lrow[t]=(i&255)>>1; lhalf[t]=(i&1)*8;
    }
    uint4 pre[4];
    const int NS = K>>4;
    int lb = lane&15;
    uint32_t boff = (uint32_t)((wn*32 + (lb&7))*48 + ((lb&8)?16:0));
    uint32_t aoff = (uint32_t)((wm*64 + (lane&7) + ((lane&8)?8:0))*48 + ((lane&16)?16:0));

    auto ldg = [&](int s){
        int k0 = s<<4;
        #pragma unroll
        for(int t=0;t<4;t++){
            const __nv_bfloat16* src;
            int row=lrow[t];
            if(ltile[t]==0)      src = Ahi + (size_t)rowidx[row]*sA;
            else if(ltile[t]==1) src = Alo + (size_t)rowidx[row]*sA;
            else if(ltile[t]==2) src = Bhi + (size_t)(col0+row)*sB;
            else                 src = Blo + (size_t)(col0+row)*sB;
            pre[t] = *(const uint4*)(src + k0 + lhalf[t]);
        }
    };
    auto sts = [&](int b){
        #pragma unroll
        for(int t=0;t<4;t++)
            *(uint4*)(sm + b*HS_BUF + ltile[t]*HS_TILE + lrow[t]*48 + lhalf[t]*2) = pre[t];
    };
    ldg(0); sts(0);
    __syncthreads();
    for(int s=0;s<NS;s++){
        int b=s&1;
        if(s+1<NS) ldg(s+1);
        uint32_t base = smb + b*HS_BUF;
        uint32_t bh[4][2], bl[4][2];
        #pragma unroll
        for(int j=0;j<4;j++){
            ldsm2(bh[j], base + 2*HS_TILE + boff + j*8*48);
            ldsm2(bl[j], base + 3*HS_TILE + boff + j*8*48);
        }
        #pragma unroll
        for(int i=0;i<4;i++){
            uint32_t a[4];
            ldsm4(a, base + aoff + i*16*48);
            #pragma unroll
            for(int j=0;j<4;j++){ mma16816(acc[i][j], a, bh[j]); mma16816(acc[i][j], a, bl[j]); }
            ldsm4(a, base + HS_TILE + aoff + i*16*48);
            #pragma unroll
            for(int j=0;j<4;j++) mma16816(acc[i][j], a, bh[j]);
        }
        if(s+1<NS) sts(b^1);
        __syncthreads();
    }
}

// ---- vocab: out = h(split) @ owT^T + ob ----
__global__ __launch_bounds__(256,1) void k_hmma_vocab(const float* __restrict__ ob, float* __restrict__ out){
    extern __shared__ char sm[];
    int* rowidx = (int*)(sm + 2*HS_BUF);
    int tid=threadIdx.x;
    int row0=blockIdx.y*128, col0=blockIdx.x*128;
    if(tid<128) rowidx[tid]=row0+tid;
    __syncthreads();
    float acc[4][4][4];
    hmma_main(sm, rowidx, g_hhi, g_hlo, DD, g_owThi, g_owTlo, DD, col0, DD, acc);
    int lane=tid&31, warp=tid>>5, wm=warp>>2, wn=warp&3;
    #pragma unroll
    for(int i=0;i<4;i++){
        int r0 = row0 + wm*64 + i*16 + (lane>>2);
        #pragma unroll
        for(int j=0;j<4;j++){
            int c = col0 + wn*32 + j*8 + (lane&3)*2;
            float b0=ob[c], b1=ob[c+1];
            out[(size_t)r0*VV + c]       = acc[i][j][0] + b0;
            out[(size_t)r0*VV + c+1]     = acc[i][j][1] + b1;
            out[(size_t)(r0+8)*VV + c]   = acc[i][j][2] + b0;
            out[(size_t)(r0+8)*VV + c+1] = acc[i][j][3] + b1;
        }
    }
}

// ---- generic projection: out[r,c] = hsplit @ WT^T + bias, fp32 out, 3-way batched ----
struct H3 {
    const __nv_bfloat16 *h0,*l0,*h1,*l1,*h2,*l2;
    const float *c0,*c1,*c2;
    float *o0,*o1,*o2;
};
__global__ __launch_bounds__(256,1) void k_hmma_proj(H3 p, int N){
    extern __shared__ char sm[];
    int* rowidx = (int*)(sm + 2*HS_BUF);
    int tid=threadIdx.x;
    int row0=blockIdx.y*128, col0=blockIdx.x*128;
    const __nv_bfloat16 *Bh,*Bl; const float* bias; float* out;
    if(blockIdx.z==0){Bh=p.h0;Bl=p.l0;bias=p.c0;out=p.o0;}
    else if(blockIdx.z==1){Bh=p.h1;Bl=p.l1;bias=p.c1;out=p.o1;}
    else {Bh=p.h2;Bl=p.l2;bias=p.c2;out=p.o2;}
    if(tid<128) rowidx[tid]=row0+tid;
    __syncthreads();
    float acc[4][4][4];
    hmma_main(sm, rowidx, g_hhi, g_hlo, DD, Bh, Bl, DD, col0, DD, acc);
    int lane=tid&31, warp=tid>>5, wm=warp>>2, wn=warp&3;
    #pragma unroll
    for(int i=0;i<4;i++){
        int r0 = row0 + wm*64 + i*16 + (lane>>2);
        #pragma unroll
        for(int j=0;j<4;j++){
            int c = col0 + wn*32 + j*8 + (lane&3)*2;
            float b0=bias[c], b1=bias[c+1];
            out[(size_t)r0*N + c]       = acc[i][j][0] + b0;
            out[(size_t)r0*N + c+1]     = acc[i][j][1] + b1;
            out[(size_t)(r0+8)*N + c]   = acc[i][j][2] + b0;
            out[(size_t)(r0+8)*N + c+1] = acc[i][j][3] + b1;
        }
    }
}

// ---- MoE1 ----
__global__ __launch_bounds__(256,1) void k_hmma_moe1(const __nv_bfloat16* __restrict__ Whi,
        const __nv_bfloat16* __restrict__ Wlo, const float* __restrict__ B1){
    int e=blockIdx.z, cnt=g_ecount[e], row0=blockIdx.y*128;
    if(row0>=cnt) return;
    extern __shared__ char sm[];
    int* rowidx = (int*)(sm + 2*HS_BUF);
    int tid=threadIdx.x;
    int col0=blockIdx.x*128;
    if(tid<128){
        int r=row0+tid;
        rowidx[tid] = (r<cnt)? g_elist[e*NTOK+r] : g_elist[e*NTOK];
    }
    __syncthreads();
    float acc[4][4][4];
    hmma_main(sm, rowidx, g_mhi, g_mlo, DD,
              Whi+(size_t)e*FFD*DD, Wlo+(size_t)e*FFD*DD, DD, col0, DD, acc);
    const float* bia = B1 + (size_t)e*FFD;
    int lane=tid&31, warp=tid>>5, wm=warp>>2, wn=warp&3;
    #pragma unroll
    for(int i=0;i<4;i++){
        int r0 = row0 + wm*64 + i*16 + (lane>>2);
        #pragma unroll
        for(int j=0;j<4;j++){
            int c = col0 + wn*32 + j*8 + (lane&3)*2;
            float b0=bia[c], b1=bia[c+1];
            #pragma unroll
            for(int q=0;q<4;q++){
                int r = r0 + (q>=2?8:0);
                if(r>=cnt) continue;
                int cc = c + (q&1);
                float v = gelu_tanh(acc[i][j][q] + ((q&1)?b1:b0));
                __nv_bfloat16 h=__float2bfloat16(v);
                size_t o = ((size_t)e*NTOK + r)*FFD + cc;
                g_h1hi[o]=h; g_h1lo[o]=__float2bfloat16(v-__bfloat162float(h));
            }
        }
    }
}

// ---- MoE2 ----
__global__ __launch_bounds__(256,1) void k_hmma_moe2(const __nv_bfloat16* __restrict__ Whi,
        const __nv_bfloat16* __restrict__ Wlo, const float* __restrict__ B2){
    int e=blockIdx.z, cnt=g_ecount[e], row0=blockIdx.y*128;
    if(row0>=cnt) return;
    extern __shared__ char sm[];
    int* rowidx = (int*)(sm + 2*HS_BUF);
    int tid=threadIdx.x;
    int col0=blockIdx.x*128;
    if(tid<128) rowidx[tid] = e*NTOK + row0 + tid;
    __syncthreads();
    float acc[4][4][4];
    hmma_main(sm, rowidx, g_h1hi, g_h1lo, FFD,
              Whi+(size_t)e*DD*FFD, Wlo+(size_t)e*DD*FFD, FFD, col0, FFD, acc);
    const float* bia = B2 + (size_t)e*DD;
    int lane=tid&31, warp=tid>>5, wm=warp>>2, wn=warp&3;
    #pragma unroll
    for(int i=0;i<4;i++){
        int r0 = row0 + wm*64 + i*16 + (lane>>2);
        #pragma unroll
        for(int j=0;j<4;j++){
            int c = col0 + wn*32 + j*8 + (lane&3)*2;
            float b0=bia[c], b1=bia[c+1];
            #pragma unroll
            for(int q=0;q<4;q++){
                int r = r0 + (q>=2?8:0);
                if(r>=cnt) continue;
                int tok=g_elist[e*NTOK+r];
                float gv=g_egate[e*NTOK+r];
                int cc = c + (q&1);
                atomicAdd(&g_moe[(size_t)tok*DD+cc], gv*(acc[i][j][q] + ((q&1)?b1:b0)));
            }
        }
    }
}

// ===== fp32 128x128 SGEMM (O projection w/ residual) =====
__device__ __forceinline__ void gemm128_body(const float* __restrict__ A, const float* __restrict__ B,
    const float* __restrict__ bias, const float* __restrict__ res, float* __restrict__ C, int N, int K){
    __shared__ float As[2][8][132];
    __shared__ float Bs[2][8][128];
    int tid=threadIdx.x;
    int row0=blockIdx.y*128, col0=blockIdx.x*128;
    int arow=tid>>1, acol=(tid&1)*4;
    int brow=tid>>5, bcol=(tid&31)*4;
    const float* Aptr=A+(size_t)(row0+arow)*K+acol;
    const float* Bptr=B+(size_t)brow*N+col0+bcol;
    float4 a4=*(const float4*)Aptr;
    float4 b4=*(const float4*)Bptr;
    As[0][acol+0][arow]=a4.x; As[0][acol+1][arow]=a4.y; As[0][acol+2][arow]=a4.z; As[0][acol+3][arow]=a4.w;
    *(float4*)&Bs[0][brow][bcol]=b4;
    __syncthreads();
    int tx=tid&15, ty=tid>>4;
    float acc[8][8]={};
    int buf=0;
    for(int k0=8;k0<=K;k0+=8){
        if(k0<K){ a4=*(const float4*)(Aptr+k0); b4=*(const float4*)(Bptr+(size_t)k0*N); }
        #pragma unroll
        for(int kk=0;kk<8;kk++){
            float4 a0=*(const float4*)&As[buf][kk][ty*8];
            float4 a1=*(const float4*)&As[buf][kk][ty*8+4];
            float4 b0=*(const float4*)&Bs[buf][kk][tx*8];
            float4 b1=*(const float4*)&Bs[buf][kk][tx*8+4];
            float av[8]={a0.x,a0.y,a0.z,a0.w,a1.x,a1.y,a1.z,a1.w};
            float bv[8]={b0.x,b0.y,b0.z,b0.w,b1.x,b1.y,b1.z,b1.w};
            #pragma unroll
            for(int i=0;i<8;i++)
                #pragma unroll
                for(int j=0;j<8;j++) acc[i][j]+=av[i]*bv[j];
        }
        if(k0<K){
            buf^=1;
            As[buf][acol+0][arow]=a4.x; As[buf][acol+1][arow]=a4.y; As[buf][acol+2][arow]=a4.z; As[buf][acol+3][arow]=a4.w;
            *(float4*)&Bs[buf][brow][bcol]=b4;
            __syncthreads();
        }
    }
    #pragma unroll
    for(int i=0;i<8;i++){
        int r=row0+ty*8+i;
        #pragma unroll
        for(int j=0;j<8;j+=4){
            int c=col0+tx*8+j;
            float4 v={acc[i][j],acc[i][j+1],acc[i][j+2],acc[i][j+3]};
            if(bias){ float4 bb=*(const float4*)&bias[c]; v.x+=bb.x;v.y+=bb.y;v.z+=bb.z;v.w+=bb.w; }
            if(res){ float4 rr=*(const float4*)&res[(size_t)r*N+c]; v.x+=rr.x;v.y+=rr.y;v.z+=rr.z;v.w+=rr.w; }
            *(float4*)&C[(size_t)r*N+c]=v;
        }
    }
}
__global__ __launch_bounds__(256) void k_gemm128(const float* __restrict__ A, const float* __restrict__ B,
    const float* __restrict__ bias, const float* __restrict__ res, float* __restrict__ C, int N, int K){
    gemm128_body(A,B,bias,res,C,N,K);
}

// ===== indexer scores (causal tile-skip) =====
__global__ __launch_bounds__(256) void k_idxscore(const float* __restrict__ hw){
    int kt=blockIdx.x, qt=blockIdx.y, b=blockIdx.z;
    int tx=threadIdx.x&15, ty=threadIdx.x>>4;
    if(kt>qt){
        // entire tile is k>q: pure NEGV
        #pragma unroll
        for(int i=0;i<4;i++){
            int q=qt*64+ty*4+i;
            float4 nv={NEGV,NEGV,NEGV,NEGV};
            *(float4*)&g_mask[((size_t)b*SSL+q)*SSL + kt*64+tx*4]=nv;
        }
        return;
    }
    __shared__ float Qs[64][68];
    __shared__ float Ks[64][68];
    float acc[4][4]={};
    for(int h=0;h<HHI;h++){
        for(int i=threadIdx.x;i<4096;i+=256){
            int r=i>>6, d=i&63;
            Qs[d][r]=g_qi[(size_t)(b*SSL+qt*64+r)*(HHI*DII)+h*64+d];
            Ks[d][r]=g_ki[(size_t)(b*SSL+kt*64+r)*(HHI*DII)+h*64+d];
        }
        __syncthreads();
        float w=hw[h];
        float dot[4][4]={};
        #pragma unroll 8
        for(int d=0;d<64;d++){
            float4 a4=*(const float4*)&Qs[d][ty*4];
            float4 b4=*(const float4*)&Ks[d][tx*4];
            float a[4]={a4.x,a4.y,a4.z,a4.w};
            float bb[4]={b4.x,b4.y,b4.z,b4.w};
            #pragma unroll
            for(int i=0;i<4;i++)
                #pragma unroll
                for(int j=0;j<4;j++) dot[i][j]+=a[i]*bb[j];
        }
        #pragma unroll
        for(int i=0;i<4;i++)
            #pragma unroll
            for(int j=0;j<4;j++) acc[i][j]+=fmaxf(dot[i][j],0.f)*w;
        __syncthreads();
    }
    #pragma unroll
    for(int i=0;i<4;i++){
        int q=qt*64+ty*4+i;
        #pragma unroll
        for(int j=0;j<4;j++){
            int k=kt*64+tx*4+j;
            g_mask[((size_t)b*SSL+q)*SSL+k]=acc[i][j]+((k<=q)?0.f:NEGV);
        }
    }
}

// ===== top-K bitonic =====
__global__ __launch_bounds__(512) void k_topk(){
    int q=blockIdx.x, b=blockIdx.y, t=threadIdx.x;
    __shared__ float s[1024];
    size_t base=((size_t)b*SSL+q)*SSL;
    s[t]=g_mask[base+t];
    s[t+512]=g_mask[base+t+512];
    __syncthreads();
    for(int size=2;size<=1024;size<<=1){
        for(int stride=size>>1;stride>0;stride>>=1){
            int lo=2*stride*(t/stride)+(t%stride);
            int hi=lo+stride;
            bool desc=((lo&size)==0);
            float a=s[lo], bv=s[hi];
            if((a<bv)==desc){ s[lo]=bv; s[hi]=a; }
            __syncthreads();
        }
    }
    float thr=s[KTOP-1];
    for(int k=t;k<SSL;k+=512){
        float v=g_mask[base+k];
        g_mask[base+k]=(k<=q && v>=thr)?0.f:NEGV;
    }
}

// ===== attention: conflict-free float4 + causal tile-skip =====
__global__ __launch_bounds__(256) void k_attn(){
    int qt=blockIdx.x, h=blockIdx.y, b=blockIdx.z;
    int t=threadIdx.x, row=t>>4, cg=t&15;
    __shared__ float qs[16][68];
    __shared__ float Ks[64][68];
    __shared__ float Vs[64][68];
    __shared__ float Sc[16][68];
    __shared__ float mrow[16], lrow[16];
    int q0=qt*16;
    for(int i=t;i<16*64;i+=256){
        int r=i>>6, d=i&63;
        qs[r][d]=g_q[(size_t)(b*SSL+q0+r)*DD+h*64+d];
    }
    if(t<16){ mrow[t]=-1e30f; lrow[t]=0.f; }
    float oacc[4]={0.f,0.f,0.f,0.f};
    __syncthreads();
    const float* maskrow=g_mask+((size_t)b*SSL+(q0+row))*SSL;
    int kmax = q0 + 16;                 // keys beyond q0+15 are fully causal-masked
    for(int k0=0;k0<kmax;k0+=64){
        for(int i=t;i<4096;i+=256){
            int r=i>>6, d=i&63;
            Ks[r][d]=g_k[(size_t)(b*SSL+k0+r)*DD+h*64+d];
            Vs[r][d]=g_v[(size_t)(b*SSL+k0+r)*DD+h*64+d];
        }
        __syncthreads();
        float sv[4]={0.f,0.f,0.f,0.f};
        #pragma unroll
        for(int d0=0;d0<64;d0+=4){
            float4 q4=*(const float4*)&qs[row][d0];
            #pragma unroll
            for(int j=0;j<4;j++){
                float4 k4=*(const float4*)&Ks[j*16+cg][d0];
                sv[j]+=q4.x*k4.x+q4.y*k4.y+q4.z*k4.z+q4.w*k4.w;
            }
        }
        #pragma unroll
        for(int j=0;j<4;j++) sv[j]=sv[j]*SCALE+maskrow[k0+j*16+cg];
        float mold=mrow[row], lold=lrow[row];
        float tmax=fmaxf(fmaxf(sv[0],sv[1]),fmaxf(sv[2],sv[3]));
        tmax=fmaxf(tmax,mold);
        #pragma unroll
        for(int off=8;off>0;off>>=1) tmax=fmaxf(tmax,__shfl_xor_sync(0xffffffffu,tmax,off,16));
        float c=__expf(mold-tmax);
        float lsum=0.f;
        #pragma unroll
        for(int j=0;j<4;j++){
            float p=__expf(sv[j]-tmax);
            Sc[row][j*16+cg]=p;
            lsum+=p;
        }
        #pragma unroll
        for(int off=8;off>0;off>>=1) lsum+=__shfl_xor_sync(0xffffffffu,lsum,off,16);
        if(cg==0){ mrow[row]=tmax; lrow[row]=lold*c+lsum; }
        __syncwarp();
        #pragma unroll
        for(int j=0;j<4;j++) oacc[j]*=c;
        #pragma unroll
        for(int k=0;k<64;k++){
            float s=Sc[row][k];
            float4 v4=*(const float4*)&Vs[k][cg*4];
            oacc[0]+=s*v4.x; oacc[1]+=s*v4.y; oacc[2]+=s*v4.z; oacc[3]+=s*v4.w;
        }
        __syncthreads();
    }
    float linv=1.0f/lrow[row];
    float4 o4={oacc[0]*linv,oacc[1]*linv,oacc[2]*linv,oacc[3]*linv};
    *(float4*)&g_ao[(size_t)(b*SSL+q0+row)*DD+h*64+cg*4]=o4;
}

// ===== fused router =====
__global__ __launch_bounds__(256) void k_router(const float* __restrict__ rw, const float* __restrict__ rb){
    int n=blockIdx.x;
    int t=threadIdx.x, e=t>>5, lane=t&31;
    __shared__ float ms[DD];
    __shared__ float pe[EE];
    for(int i=t;i<DD;i+=256) ms[i]=g_m[(size_t)n*DD+i];
    __syncthreads();
    float s=0.f;
    for(int k=lane;k<DD;k+=32) s+=ms[k]*rw[k*EE+e];
    #pragma unroll
    for(int off=16;off>0;off>>=1) s+=__shfl_xor_sync(0xffffffffu,s,off);
    if(lane==0) pe[e]=s+rb[e];
    __syncthreads();
    if(t==0){
        float p[EE]; float mx=-1e30f;
        #pragma unroll
        for(int i=0;i<EE;i++){ p[i]=pe[i]; mx=fmaxf(mx,p[i]); }
        #pragma unroll
        for(int i=0;i<EE;i++) p[i]=__expf(p[i]-mx);
        int e1=0;
        for(int i=1;i<EE;i++) if(p[i]>p[e1]) e1=i;
        int e2=-1;
        for(int i=0;i<EE;i++) if(i!=e1 && (e2<0 || p[i]>p[e2])) e2=i;
        float den=p[e1]+p[e2];
        int pos=atomicAdd(&g_ecount[e1],1);
        g_elist[e1*NTOK+pos]=n; g_egate[e1*NTOK+pos]=p[e1]/den;
        pos=atomicAdd(&g_ecount[e2],1);
        g_elist[e2*NTOK+pos]=n; g_egate[e2*NTOK+pos]=p[e2]/den;
    }
}

// ===== host =====
extern "C" void kernel_launch(void* const* d_in, const int* in_sizes, int n_in,
                              void* d_out, int out_size){
    (void)in_sizes; (void)n_in; (void)out_size;
    const int*   ids  = (const int*)  d_in[0];
    const float* tok  = (const float*)d_in[1];
    const float* pos  = (const float*)d_in[2];
    const float* ln1g = (const float*)d_in[3];
    const float* ln1b = (const float*)d_in[4];
    const float* iqw  = (const float*)d_in[5];
    const float* iqb  = (const float*)d_in[6];
    const float* ikw  = (const float*)d_in[7];
    const float* ikb  = (const float*)d_in[8];
    const float* ihw  = (const float*)d_in[9];
    const float* wq   = (const float*)d_in[10];
    const float* bq   = (const float*)d_in[11];
    const float* wk   = (const float*)d_in[12];
    const float* bk   = (const float*)d_in[13];
    const float* wv   = (const float*)d_in[14];
    const float* bv   = (const float*)d_in[15];
    const float* wo   = (const float*)d_in[16];
    const float* bo   = (const float*)d_in[17];
    const float* ln2g = (const float*)d_in[18];
    const float* ln2b = (const float*)d_in[19];
    const float* rw   = (const float*)d_in[20];
    const float* rb   = (const float*)d_in[21];
    const float* ew1  = (const float*)d_in[22];
    const float* eb1  = (const float*)d_in[23];
    const float* ew2  = (const float*)d_in[24];
    const float* eb2  = (const float*)d_in[25];
    const float* lnfg = (const float*)d_in[26];
    const float* lnfb = (const float*)d_in[27];
    const float* ow   = (const float*)d_in[28];
    const float* ob   = (const float*)d_in[29];
    float* out = (float*)d_out;

    float *px,*ph,*pm,*pq,*pk,*pv,*pao,*pqi,*pki,*pmoe;
    int *pec;
    __nv_bfloat16 *phhi,*phlo,*pmhi,*pmlo,*powThi,*powTlo,*pw1Thi,*pw1Tlo,*pw2Thi,*pw2Tlo;
    __nv_bfloat16 *pwqh,*pwql,*pwkh,*pwkl,*pwvh,*pwvl,*piqh,*piql,*pikh,*pikl;
    cudaGetSymbolAddress((void**)&px,g_x);
    cudaGetSymbolAddress((void**)&ph,g_h);
    cudaGetSymbolAddress((void**)&pm,g_m);
    cudaGetSymbolAddress((void**)&pq,g_q);
    cudaGetSymbolAddress((void**)&pk,g_k);
    cudaGetSymbolAddress((void**)&pv,g_v);
    cudaGetSymbolAddress((void**)&pao,g_ao);
    cudaGetSymbolAddress((void**)&pqi,g_qi);
    cudaGetSymbolAddress((void**)&pki,g_ki);
    cudaGetSymbolAddress((void**)&pmoe,g_moe);
    cudaGetSymbolAddress((void**)&pec,g_ecount);
    cudaGetSymbolAddress((void**)&phhi,g_hhi);
    cudaGetSymbolAddress((void**)&phlo,g_hlo);
    cudaGetSymbolAddress((void**)&pmhi,g_mhi);
    cudaGetSymbolAddress((void**)&pmlo,g_mlo);
    cudaGetSymbolAddress((void**)&powThi,g_owThi);
    cudaGetSymbolAddress((void**)&powTlo,g_owTlo);
    cudaGetSymbolAddress((void**)&pw1Thi,g_w1Thi);
    cudaGetSymbolAddress((void**)&pw1Tlo,g_w1Tlo);
    cudaGetSymbolAddress((void**)&pw2Thi,g_w2Thi);
    cudaGetSymbolAddress((void**)&pw2Tlo,g_w2Tlo);
    cudaGetSymbolAddress((void**)&pwqh,g_wqThi);
    cudaGetSymbolAddress((void**)&pwql,g_wqTlo);
    cudaGetSymbolAddress((void**)&pwkh,g_wkThi);
    cudaGetSymbolAddress((void**)&pwkl,g_wkTlo);
    cudaGetSymbolAddress((void**)&pwvh,g_wvThi);
    cudaGetSymbolAddress((void**)&pwvl,g_wvTlo);
    cudaGetSymbolAddress((void**)&piqh,g_iqThi);
    cudaGetSymbolAddress((void**)&piql,g_iqTlo);
    cudaGetSymbolAddress((void**)&pikh,g_ikThi);
    cudaGetSymbolAddress((void**)&pikl,g_ikTlo);

    cudaFuncSetAttribute(k_hmma_vocab, cudaFuncAttributeMaxDynamicSharedMemorySize, HS_TOTAL);
    cudaFuncSetAttribute(k_hmma_proj,  cudaFuncAttributeMaxDynamicSharedMemorySize, HS_TOTAL);
    cudaFuncSetAttribute(k_hmma_moe1,  cudaFuncAttributeMaxDynamicSharedMemorySize, HS_TOTAL);
    cudaFuncSetAttribute(k_hmma_moe2,  cudaFuncAttributeMaxDynamicSharedMemorySize, HS_TOTAL);

    // weight transposes + bf16 splits (all batched over layers/experts)
    k_transcvtB<<<dim3(VV/32, DD/32, 1),256>>>(ow, powThi, powTlo, DD, VV);
    k_transcvtB<<<dim3(FFD/32, DD/32, LLN*EE),256>>>(ew1, pw1Thi, pw1Tlo, DD, FFD);
    k_transcvtB<<<dim3(DD/32, FFD/32, LLN*EE),256>>>(ew2, pw2Thi, pw2Tlo, FFD, DD);
    k_transcvtB<<<dim3(DD/32, DD/32, LLN),256>>>(wq, pwqh, pwql, DD, DD);
    k_transcvtB<<<dim3(DD/32, DD/32, LLN),256>>>(wk, pwkh, pwkl, DD, DD);
    k_transcvtB<<<dim3(DD/32, DD/32, LLN),256>>>(wv, pwvh, pwvl, DD, DD);
    k_transcvtB<<<dim3((HHI*DII)/32, DD/32, LLN),256>>>(iqw, piqh, piql, DD, HHI*DII);
    k_transcvtB<<<dim3((HHI*DII)/32, DD/32, LLN),256>>>(ikw, pikh, pikl, DD, HHI*DII);

    k_embed<<<NTOK,512>>>(ids, tok, pos);

    for(int l=0;l<LLN;l++){
        k_ln<<<NTOK,256>>>(px, ln1g+l*DD, ln1b+l*DD, ph, phhi, phlo);
        {   // indexer q/k projections (HMMA, batched z=2)
            H3 p;
            p.h0=piqh+(size_t)l*HHI*DII*DD; p.l0=piql+(size_t)l*HHI*DII*DD; p.c0=iqb+l*HHI*DII; p.o0=pqi;
            p.h1=pikh+(size_t)l*HHI*DII*DD; p.l1=pikl+(size_t)l*HHI*DII*DD; p.c1=ikb+l*HHI*DII; p.o1=pki;
            p.h2=p.h0; p.l2=p.l0; p.c2=p.c0; p.o2=pqi;
            k_hmma_proj<<<dim3((HHI*DII)/128, NTOK/128, 2),256,HS_TOTAL>>>(p, HHI*DII);
        }
        k_idxscore<<<dim3(SSL/64,SSL/64,BB),256>>>(ihw+l*HHI);
        k_topk<<<dim3(SSL,BB),512>>>();
        {   // QKV (HMMA, batched z=3)
            H3 p;
            p.h0=pwqh+(size_t)l*DD*DD; p.l0=pwql+(size_t)l*DD*DD; p.c0=bq+l*DD; p.o0=pq;
            p.h1=pwkh+(size_t)l*DD*DD; p.l1=pwkl+(size_t)l*DD*DD; p.c1=bk+l*DD; p.o1=pk;
            p.h2=pwvh+(size_t)l*DD*DD; p.l2=pwvl+(size_t)l*DD*DD; p.c2=bv+l*DD; p.o2=pv;
            k_hmma_proj<<<dim3(DD/128, NTOK/128, 3),256,HS_TOTAL>>>(p, DD);
        }
        k_attn<<<dim3(SSL/16,HHN,BB),256>>>();
        k_gemm128<<<dim3(4,16),256>>>(pao, wo+(size_t)l*DD*DD, bo+l*DD, px, px, DD, DD);

        k_ln<<<NTOK,256>>>(px, ln2g+l*DD, ln2b+l*DD, pm, pmhi, pmlo);
        k_zeroi<<<1,32>>>(pec, EE);
        k_router<<<NTOK,256>>>(rw+(size_t)l*DD*EE, rb+l*EE);
        k_zerof<<<(NTOK*DD)/256,256>>>(pmoe, NTOK*DD);
        k_hmma_moe1<<<dim3(FFD/128, NTOK/128, EE),256,HS_TOTAL>>>(
            pw1Thi+(size_t)l*EE*FFD*DD, pw1Tlo+(size_t)l*EE*FFD*DD, eb1+(size_t)l*EE*FFD);
        k_hmma_moe2<<<dim3(DD/128, NTOK/128, EE),256,HS_TOTAL>>>(
            pw2Thi+(size_t)l*EE*DD*FFD, pw2Tlo+(size_t)l*EE*DD*FFD, eb2+(size_t)l*EE*DD);
        k_add<<<(NTOK*DD)/256,256>>>(px, pmoe, NTOK*DD);
    }

    k_ln<<<NTOK,256>>>(px, lnfg, lnfb, ph, phhi, phlo);
    k_hmma_vocab<<<dim3(VV/128, NTOK/128),256,HS_TOTAL>>>(ob, out);
}

// round 10
// speedup vs baseline: 1.8614x; 1.0203x over previous
#include <cuda_runtime.h>
#include <cuda_bf16.h>
#include <math.h>
#include <stdint.h>

#define BB 2
#define SSL 1024
#define NTOK 2048
#define DD 512
#define HHN 8
#define HHI 4
#define DII 64
#define FFD 2048
#define EE 8
#define VV 32000
#define KTOP 256
#define NEGV (-1e9f)
#define EPSV 1e-5f
#define LLN 2
#define SCALE 0.125f

__device__ float g_x[NTOK*DD];
__device__ float g_h[NTOK*DD];
__device__ float g_m[NTOK*DD];
__device__ float g_q[NTOK*DD];
__device__ float g_k[NTOK*DD];
__device__ float g_v[NTOK*DD];
__device__ float g_moe[NTOK*DD];
__device__ float g_mask[(size_t)BB*SSL*SSL];
__device__ int g_ecount[EE];
__device__ int g_elist[EE*NTOK];
__device__ float g_egate[EE*NTOK];
__device__ alignas(16) __nv_bfloat16 g_hhi[NTOK*DD];
__device__ alignas(16) __nv_bfloat16 g_hlo[NTOK*DD];
__device__ alignas(16) __nv_bfloat16 g_mhi[NTOK*DD];
__device__ alignas(16) __nv_bfloat16 g_mlo[NTOK*DD];
__device__ alignas(16) __nv_bfloat16 g_aohi[NTOK*DD];
__device__ alignas(16) __nv_bfloat16 g_aolo[NTOK*DD];
__device__ alignas(16) float g_qi[NTOK*HHI*DII];
__device__ alignas(16) float g_ki[NTOK*HHI*DII];
__device__ alignas(16) __nv_bfloat16 g_owThi[(size_t)VV*DD];
__device__ alignas(16) __nv_bfloat16 g_owTlo[(size_t)VV*DD];
__device__ alignas(16) __nv_bfloat16 g_w1Thi[(size_t)LLN*EE*FFD*DD];
__device__ alignas(16) __nv_bfloat16 g_w1Tlo[(size_t)LLN*EE*FFD*DD];
__device__ alignas(16) __nv_bfloat16 g_w2Thi[(size_t)LLN*EE*DD*FFD];
__device__ alignas(16) __nv_bfloat16 g_w2Tlo[(size_t)LLN*EE*DD*FFD];
__device__ alignas(16) __nv_bfloat16 g_h1hi[(size_t)EE*NTOK*FFD];
__device__ alignas(16) __nv_bfloat16 g_h1lo[(size_t)EE*NTOK*FFD];
__device__ alignas(16) __nv_bfloat16 g_wqThi[LLN*DD*DD];
__device__ alignas(16) __nv_bfloat16 g_wqTlo[LLN*DD*DD];
__device__ alignas(16) __nv_bfloat16 g_wkThi[LLN*DD*DD];
__device__ alignas(16) __nv_bfloat16 g_wkTlo[LLN*DD*DD];
__device__ alignas(16) __nv_bfloat16 g_wvThi[LLN*DD*DD];
__device__ alignas(16) __nv_bfloat16 g_wvTlo[LLN*DD*DD];
__device__ alignas(16) __nv_bfloat16 g_woThi[LLN*DD*DD];
__device__ alignas(16) __nv_bfloat16 g_woTlo[LLN*DD*DD];
__device__ alignas(16) __nv_bfloat16 g_iqThi[LLN*HHI*DII*DD];
__device__ alignas(16) __nv_bfloat16 g_iqTlo[LLN*HHI*DII*DD];
__device__ alignas(16) __nv_bfloat16 g_ikThi[LLN*HHI*DII*DD];
__device__ alignas(16) __nv_bfloat16 g_ikTlo[LLN*HHI*DII*DD];

__device__ __forceinline__ float gelu_tanh(float x){
    float x3 = x*x*x;
    return 0.5f*x*(1.f + tanhf(0.7978845608028654f*(x + 0.044715f*x3)));
}

__global__ void k_embed(const int* __restrict__ ids, const float* __restrict__ tok, const float* __restrict__ pos){
    int n=blockIdx.x, t=threadIdx.x;
    g_x[(size_t)n*DD+t] = tok[(size_t)ids[n]*DD+t] + pos[(size_t)(n%SSL)*DD+t];
}

// layernorm; optional fused residual-add (writes back to in), bf16 split emit, ecount zero
__global__ __launch_bounds__(256) void k_ln(float* __restrict__ in, const float* __restrict__ g,
        const float* __restrict__ b, float* __restrict__ out,
        __nv_bfloat16* __restrict__ hi, __nv_bfloat16* __restrict__ lo,
        const float* __restrict__ radd, int* __restrict__ ecz){
    int r=blockIdx.x, t=threadIdx.x;
    if(ecz && r==0 && t<EE) ecz[t]=0;
    __shared__ float red[256];
    float v0=in[(size_t)r*DD+t], v1=in[(size_t)r*DD+t+256];
    if(radd){
        v0 += radd[(size_t)r*DD+t];
        v1 += radd[(size_t)r*DD+t+256];
        in[(size_t)r*DD+t]=v0;
        in[(size_t)r*DD+t+256]=v1;
    }
    red[t]=v0+v1; __syncthreads();
    for(int s=128;s>0;s>>=1){ if(t<s)red[t]+=red[t+s]; __syncthreads(); }
    float mu=red[0]*(1.0f/DD); __syncthreads();
    float d0=v0-mu, d1=v1-mu;
    red[t]=d0*d0+d1*d1; __syncthreads();
    for(int s=128;s>0;s>>=1){ if(t<s)red[t]+=red[t+s]; __syncthreads(); }
    float rs=rsqrtf(red[0]*(1.0f/DD)+EPSV);
    float o0=d0*rs*g[t]+b[t];
    float o1=d1*rs*g[t+256]+b[t+256];
    out[(size_t)r*DD+t]=o0;
    out[(size_t)r*DD+t+256]=o1;
    if(hi){
        __nv_bfloat16 h0=__float2bfloat16(o0), h1=__float2bfloat16(o1);
        hi[(size_t)r*DD+t]=h0;
        hi[(size_t)r*DD+t+256]=h1;
        lo[(size_t)r*DD+t]=__float2bfloat16(o0-__bfloat162float(h0));
        lo[(size_t)r*DD+t+256]=__float2bfloat16(o1-__bfloat162float(h1));
    }
}

// batched: W[z][K][N] fp32 -> T[z][N][K] bf16 hi/lo
__global__ __launch_bounds__(256) void k_transcvtB(const float* __restrict__ W,
        __nv_bfloat16* __restrict__ Thi, __nv_bfloat16* __restrict__ Tlo, int K, int N){
    int z=blockIdx.z;
    W   += (size_t)z*K*N;
    Thi += (size_t)z*N*K;
    Tlo += (size_t)z*N*K;
    __shared__ float t[32][33];
    int n0=blockIdx.x*32, k0=blockIdx.y*32;
    int tx=threadIdx.x&31, ty=threadIdx.x>>5;
    for(int i=ty;i<32;i+=8) t[i][tx]=W[(size_t)(k0+i)*N + n0+tx];
    __syncthreads();
    for(int i=ty;i<32;i+=8){
        float v=t[tx][i];
        __nv_bfloat16 h=__float2bfloat16(v);
        size_t o=(size_t)(n0+i)*K + k0+tx;
        Thi[o]=h; Tlo[o]=__float2bfloat16(v-__bfloat162float(h));
    }
}

// ================= HMMA bf16-split GEMM core =================
__device__ __forceinline__ uint32_t smem_u32(const void* p){
    uint32_t a;
    asm("{ .reg .u64 t; cvta.to.shared.u64 t, %1; cvt.u32.u64 %0, t; }" : "=r"(a) : "l"(p));
    return a;
}
__device__ __forceinline__ void ldsm4(uint32_t (&r)[4], uint32_t a){
    asm volatile("ldmatrix.sync.aligned.m8n8.x4.shared.b16 {%0,%1,%2,%3}, [%4];"
        : "=r"(r[0]),"=r"(r[1]),"=r"(r[2]),"=r"(r[3]) : "r"(a));
}
__device__ __forceinline__ void ldsm2(uint32_t (&r)[2], uint32_t a){
    asm volatile("ldmatrix.sync.aligned.m8n8.x2.shared.b16 {%0,%1}, [%2];"
        : "=r"(r[0]),"=r"(r[1]) : "r"(a));
}
__device__ __forceinline__ void mma16816(float (&c)[4], const uint32_t (&a)[4], const uint32_t (&b)[2]){
    asm volatile("mma.sync.aligned.m16n8k16.row.col.f32.bf16.bf16.f32 "
        "{%0,%1,%2,%3}, {%4,%5,%6,%7}, {%8,%9}, {%0,%1,%2,%3};"
        : "+f"(c[0]),"+f"(c[1]),"+f"(c[2]),"+f"(c[3])
        : "r"(a[0]),"r"(a[1]),"r"(a[2]),"r"(a[3]), "r"(b[0]),"r"(b[1]));
}
#define HS_BUF 24576
#define HS_TILE 6144
#define HS_TOTAL 49664

__device__ __forceinline__ void hmma_main(char* sm, const int* rowidx,
    const __nv_bfloat16* __restrict__ Ahi, const __nv_bfloat16* __restrict__ Alo, int sA,
    const __nv_bfloat16* __restrict__ Bhi, const __nv_bfloat16* __restrict__ Blo, int sB,
    int col0, int K, float (&acc)[4][4][4])
{
    int tid=threadIdx.x, lane=tid&31, warp=tid>>5;
    int wm=warp>>2, wn=warp&3;
    uint32_t smb = smem_u32(sm);
    #pragma unroll
    for(int i=0;i<4;i++)
        #pragma unroll
        for(int j=0;j<4;j++)
            #pragma unroll
            for(int q=0;q<4;q++) acc[i][j][q]=0.f;

    int ltile[4], lrow[4], lhalf[4];
    #pragma unroll
    for(int t=0;t<4;t++){
        int i = tid + t*256;
        ltile[t]=i>>8; lrow[t]=(i&255)>>1; lhalf[t]=(i&1)*8;
    }
    uint4 pre[4];
    const int NS = K>>4;
    int lb = lane&15;
    uint32_t boff = (uint32_t)((wn*32 + (lb&7))*48 + ((lb&8)?16:0));
    uint32_t aoff = (uint32_t)((wm*64 + (lane&7) + ((lane&8)?8:0))*48 + ((lane&16)?16:0));

    auto ldg = [&](int s){
        int k0 = s<<4;
        #pragma unroll
        for(int t=0;t<4;t++){
            const __nv_bfloat16* src;
            int row=lrow[t];
            if(ltile[t]==0)      src = Ahi + (size_t)rowidx[row]*sA;
            else if(ltile[t]==1) src = Alo + (size_t)rowidx[row]*sA;
            else if(ltile[t]==2) src = Bhi + (size_t)(col0+row)*sB;
            else                 src = Blo + (size_t)(col0+row)*sB;
            pre[t] = *(const uint4*)(src + k0 + lhalf[t]);
        }
    };
    auto sts = [&](int b){
        #pragma unroll
        for(int t=0;t<4;t++)
            *(uint4*)(sm + b*HS_BUF + ltile[t]*HS_TILE + lrow[t]*48 + lhalf[t]*2) = pre[t];
    };
    ldg(0); sts(0);
    __syncthreads();
    for(int s=0;s<NS;s++){
        int b=s&1;
        if(s+1<NS) ldg(s+1);
        uint32_t base = smb + b*HS_BUF;
        uint32_t bh[4][2], bl[4][2];
        #pragma unroll
        for(int j=0;j<4;j++){
            ldsm2(bh[j], base + 2*HS_TILE + boff + j*8*48);
            ldsm2(bl[j], base + 3*HS_TILE + boff + j*8*48);
        }
        #pragma unroll
        for(int i=0;i<4;i++){
            uint32_t a[4];
            ldsm4(a, base + aoff + i*16*48);
            #pragma unroll
            for(int j=0;j<4;j++){ mma16816(acc[i][j], a, bh[j]); mma16816(acc[i][j], a, bl[j]); }
            ldsm4(a, base + HS_TILE + aoff + i*16*48);
            #pragma unroll
            for(int j=0;j<4;j++) mma16816(acc[i][j], a, bh[j]);
        }
        if(s+1<NS) sts(b^1);
        __syncthreads();
    }
}

// ---- vocab ----
__global__ __launch_bounds__(256,1) void k_hmma_vocab(const float* __restrict__ ob, float* __restrict__ out){
    extern __shared__ char sm[];
    int* rowidx = (int*)(sm + 2*HS_BUF);
    int tid=threadIdx.x;
    int row0=blockIdx.y*128, col0=blockIdx.x*128;
    if(tid<128) rowidx[tid]=row0+tid;
    __syncthreads();
    float acc[4][4][4];
    hmma_main(sm, rowidx, g_hhi, g_hlo, DD, g_owThi, g_owTlo, DD, col0, DD, acc);
    int lane=tid&31, warp=tid>>5, wm=warp>>2, wn=warp&3;
    #pragma unroll
    for(int i=0;i<4;i++){
        int r0 = row0 + wm*64 + i*16 + (lane>>2);
        #pragma unroll
        for(int j=0;j<4;j++){
            int c = col0 + wn*32 + j*8 + (lane&3)*2;
            float b0=ob[c], b1=ob[c+1];
            out[(size_t)r0*VV + c]       = acc[i][j][0] + b0;
            out[(size_t)r0*VV + c+1]     = acc[i][j][1] + b1;
            out[(size_t)(r0+8)*VV + c]   = acc[i][j][2] + b0;
            out[(size_t)(r0+8)*VV + c+1] = acc[i][j][3] + b1;
        }
    }
}

// ---- generic projection: fp32 out, 3-way batched ----
struct H3 {
    const __nv_bfloat16 *h0,*l0,*h1,*l1,*h2,*l2;
    const float *c0,*c1,*c2;
    float *o0,*o1,*o2;
};
__global__ __launch_bounds__(256,1) void k_hmma_proj(H3 p, int N){
    extern __shared__ char sm[];
    int* rowidx = (int*)(sm + 2*HS_BUF);
    int tid=threadIdx.x;
    int row0=blockIdx.y*128, col0=blockIdx.x*128;
    const __nv_bfloat16 *Bh,*Bl; const float* bias; float* out;
    if(blockIdx.z==0){Bh=p.h0;Bl=p.l0;bias=p.c0;out=p.o0;}
    else if(blockIdx.z==1){Bh=p.h1;Bl=p.l1;bias=p.c1;out=p.o1;}
    else {Bh=p.h2;Bl=p.l2;bias=p.c2;out=p.o2;}
    if(tid<128) rowidx[tid]=row0+tid;
    __syncthreads();
    float acc[4][4][4];
    hmma_main(sm, rowidx, g_hhi, g_hlo, DD, Bh, Bl, DD, col0, DD, acc);
    int lane=tid&31, warp=tid>>5, wm=warp>>2, wn=warp&3;
    #pragma unroll
    for(int i=0;i<4;i++){
        int r0 = row0 + wm*64 + i*16 + (lane>>2);
        #pragma unroll
        for(int j=0;j<4;j++){
            int c = col0 + wn*32 + j*8 + (lane&3)*2;
            float b0=bias[c], b1=bias[c+1];
            out[(size_t)r0*N + c]       = acc[i][j][0] + b0;
            out[(size_t)r0*N + c+1]     = acc[i][j][1] + b1;
            out[(size_t)(r0+8)*N + c]   = acc[i][j][2] + b0;
            out[(size_t)(r0+8)*N + c+1] = acc[i][j][3] + b1;
        }
    }
}

// ---- O projection with residual: x = x + ao@woT^T + bo ----
__global__ __launch_bounds__(256,1) void k_hmma_oproj(const __nv_bfloat16* __restrict__ Whi,
        const __nv_bfloat16* __restrict__ Wlo, const float* __restrict__ bias, float* __restrict__ x){
    extern __shared__ char sm[];
    int* rowidx = (int*)(sm + 2*HS_BUF);
    int tid=threadIdx.x;
    int row0=blockIdx.y*128, col0=blockIdx.x*128;
    if(tid<128) rowidx[tid]=row0+tid;
    __syncthreads();
    float acc[4][4][4];
    hmma_main(sm, rowidx, g_aohi, g_aolo, DD, Whi, Wlo, DD, col0, DD, acc);
    int lane=tid&31, warp=tid>>5, wm=warp>>2, wn=warp&3;
    #pragma unroll
    for(int i=0;i<4;i++){
        int r0 = row0 + wm*64 + i*16 + (lane>>2);
        #pragma unroll
        for(int j=0;j<4;j++){
            int c = col0 + wn*32 + j*8 + (lane&3)*2;
            float b0=bias[c], b1=bias[c+1];
            x[(size_t)r0*DD + c]       += acc[i][j][0] + b0;
            x[(size_t)r0*DD + c+1]     += acc[i][j][1] + b1;
            x[(size_t)(r0+8)*DD + c]   += acc[i][j][2] + b0;
            x[(size_t)(r0+8)*DD + c+1] += acc[i][j][3] + b1;
        }
    }
}

// ---- MoE1 ----
__global__ __launch_bounds__(256,1) void k_hmma_moe1(const __nv_bfloat16* __restrict__ Whi,
        const __nv_bfloat16* __restrict__ Wlo, const float* __restrict__ B1){
    int e=blockIdx.z, cnt=g_ecount[e], row0=blockIdx.y*128;
    if(row0>=cnt) return;
    extern __shared__ char sm[];
    int* rowidx = (int*)(sm + 2*HS_BUF);
    int tid=threadIdx.x;
    int col0=blockIdx.x*128;
    if(tid<128){
        int r=row0+tid;
        rowidx[tid] = (r<cnt)? g_elist[e*NTOK+r] : g_elist[e*NTOK];
    }
    __syncthreads();
    float acc[4][4][4];
    hmma_main(sm, rowidx, g_mhi, g_mlo, DD,
              Whi+(size_t)e*FFD*DD, Wlo+(size_t)e*FFD*DD, DD, col0, DD, acc);
    const float* bia = B1 + (size_t)e*FFD;
    int lane=tid&31, warp=tid>>5, wm=warp>>2, wn=warp&3;
    #pragma unroll
    for(int i=0;i<4;i++){
        int r0 = row0 + wm*64 + i*16 + (lane>>2);
        #pragma unroll
        for(int j=0;j<4;j++){
            int c = col0 + wn*32 + j*8 + (lane&3)*2;
            float b0=bia[c], b1=bia[c+1];
            #pragma unroll
            for(int q=0;q<4;q++){
                int r = r0 + (q>=2?8:0);
                if(r>=cnt) continue;
                int cc = c + (q&1);
                float v = gelu_tanh(acc[i][j][q] + ((q&1)?b1:b0));
                __nv_bfloat16 h=__float2bfloat16(v);
                size_t o = ((size_t)e*NTOK + r)*FFD + cc;
                g_h1hi[o]=h; g_h1lo[o]=__float2bfloat16(v-__bfloat162float(h));
            }
        }
    }
}

// ---- MoE2 ----
__global__ __launch_bounds__(256,1) void k_hmma_moe2(const __nv_bfloat16* __restrict__ Whi,
        const __nv_bfloat16* __restrict__ Wlo, const float* __restrict__ B2){
    int e=blockIdx.z, cnt=g_ecount[e], row0=blockIdx.y*128;
    if(row0>=cnt) return;
    extern __shared__ char sm[];
    int* rowidx = (int*)(sm + 2*HS_BUF);
    int tid=threadIdx.x;
    int col0=blockIdx.x*128;
    if(tid<128) rowidx[tid] = e*NTOK + row0 + tid;
    __syncthreads();
    float acc[4][4][4];
    hmma_main(sm, rowidx, g_h1hi, g_h1lo, FFD,
              Whi+(size_t)e*DD*FFD, Wlo+(size_t)e*DD*FFD, FFD, col0, FFD, acc);
    const float* bia = B2 + (size_t)e*DD;
    int lane=tid&31, warp=tid>>5, wm=warp>>2, wn=warp&3;
    #pragma unroll
    for(int i=0;i<4;i++){
        int r0 = row0 + wm*64 + i*16 + (lane>>2);
        #pragma unroll
        for(int j=0;j<4;j++){
            int c = col0 + wn*32 + j*8 + (lane&3)*2;
            float b0=bia[c], b1=bia[c+1];
            #pragma unroll
            for(int q=0;q<4;q++){
                int r = r0 + (q>=2?8:0);
                if(r>=cnt) continue;
                int tok=g_elist[e*NTOK+r];
                float gv=g_egate[e*NTOK+r];
                int cc = c + (q&1);
                atomicAdd(&g_moe[(size_t)tok*DD+cc], gv*(acc[i][j][q] + ((q&1)?b1:b0)));
            }
        }
    }
}

// ===== indexer scores (causal tile-skip) =====
__global__ __launch_bounds__(256) void k_idxscore(const float* __restrict__ hw){
    int kt=blockIdx.x, qt=blockIdx.y, b=blockIdx.z;
    int tx=threadIdx.x&15, ty=threadIdx.x>>4;
    if(kt>qt){
        #pragma unroll
        for(int i=0;i<4;i++){
            int q=qt*64+ty*4+i;
            float4 nv={NEGV,NEGV,NEGV,NEGV};
            *(float4*)&g_mask[((size_t)b*SSL+q)*SSL + kt*64+tx*4]=nv;
        }
        return;
    }
    __shared__ float Qs[64][68];
    __shared__ float Ks[64][68];
    float acc[4][4]={};
    for(int h=0;h<HHI;h++){
        for(int i=threadIdx.x;i<4096;i+=256){
            int r=i>>6, d=i&63;
            Qs[d][r]=g_qi[(size_t)(b*SSL+qt*64+r)*(HHI*DII)+h*64+d];
            Ks[d][r]=g_ki[(size_t)(b*SSL+kt*64+r)*(HHI*DII)+h*64+d];
        }
        __syncthreads();
        float w=hw[h];
        float dot[4][4]={};
        #pragma unroll 8
        for(int d=0;d<64;d++){
            float4 a4=*(const float4*)&Qs[d][ty*4];
            float4 b4=*(const float4*)&Ks[d][tx*4];
            float a[4]={a4.x,a4.y,a4.z,a4.w};
            float bb[4]={b4.x,b4.y,b4.z,b4.w};
            #pragma unroll
            for(int i=0;i<4;i++)
                #pragma unroll
                for(int j=0;j<4;j++) dot[i][j]+=a[i]*bb[j];
        }
        #pragma unroll
        for(int i=0;i<4;i++)
            #pragma unroll
            for(int j=0;j<4;j++) acc[i][j]+=fmaxf(dot[i][j],0.f)*w;
        __syncthreads();
    }
    #pragma unroll
    for(int i=0;i<4;i++){
        int q=qt*64+ty*4+i;
        #pragma unroll
        for(int j=0;j<4;j++){
            int k=kt*64+tx*4+j;
            g_mask[((size_t)b*SSL+q)*SSL+k]=acc[i][j]+((k<=q)?0.f:NEGV);
        }
    }
}

// ===== top-K bitonic =====
__global__ __launch_bounds__(512) void k_topk(){
    int q=blockIdx.x, b=blockIdx.y, t=threadIdx.x;
    __shared__ float s[1024];
    size_t base=((size_t)b*SSL+q)*SSL;
    s[t]=g_mask[base+t];
    s[t+512]=g_mask[base+t+512];
    __syncthreads();
    for(int size=2;size<=1024;size<<=1){
        for(int stride=size>>1;stride>0;stride>>=1){
            int lo=2*stride*(t/stride)+(t%stride);
            int hi=lo+stride;
            bool desc=((lo&size)==0);
            float a=s[lo], bv=s[hi];
            if((a<bv)==desc){ s[lo]=bv; s[hi]=a; }
            __syncthreads();
        }
    }
    float thr=s[KTOP-1];
    for(int k=t;k<SSL;k+=512){
        float v=g_mask[base+k];
        g_mask[base+k]=(k<=q && v>=thr)?0.f:NEGV;
    }
}

// ===== attention: conflict-free float4 + causal tile-skip; emits bf16-split output =====
__global__ __launch_bounds__(256) void k_attn(){
    int qt=blockIdx.x, h=blockIdx.y, b=blockIdx.z;
    int t=threadIdx.x, row=t>>4, cg=t&15;
    __shared__ float qs[16][68];
    __shared__ float Ks[64][68];
    __shared__ float Vs[64][68];
    __shared__ float Sc[16][68];
    __shared__ float mrow[16], lrow[16];
    int q0=qt*16;
    for(int i=t;i<16*64;i+=256){
        int r=i>>6, d=i&63;
        qs[r][d]=g_q[(size_t)(b*SSL+q0+r)*DD+h*64+d];
    }
    if(t<16){ mrow[t]=-1e30f; lrow[t]=0.f; }
    float oacc[4]={0.f,0.f,0.f,0.f};
    __syncthreads();
    const float* maskrow=g_mask+((size_t)b*SSL+(q0+row))*SSL;
    int kmax = q0 + 16;
    for(int k0=0;k0<kmax;k0+=64){
        for(int i=t;i<4096;i+=256){
            int r=i>>6, d=i&63;
            Ks[r][d]=g_k[(size_t)(b*SSL+k0+r)*DD+h*64+d];
            Vs[r][d]=g_v[(size_t)(b*SSL+k0+r)*DD+h*64+d];
        }
        __syncthreads();
        float sv[4]={0.f,0.f,0.f,0.f};
        #pragma unroll
        for(int d0=0;d0<64;d0+=4){
            float4 q4=*(const float4*)&qs[row][d0];
            #pragma unroll
            for(int j=0;j<4;j++){
                float4 k4=*(const float4*)&Ks[j*16+cg][d0];
                sv[j]+=q4.x*k4.x+q4.y*k4.y+q4.z*k4.z+q4.w*k4.w;
            }
        }
        #pragma unroll
        for(int j=0;j<4;j++) sv[j]=sv[j]*SCALE+maskrow[k0+j*16+cg];
        float mold=mrow[row], lold=lrow[row];
        float tmax=fmaxf(fmaxf(sv[0],sv[1]),fmaxf(sv[2],sv[3]));
        tmax=fmaxf(tmax,mold);
        #pragma unroll
        for(int off=8;off>0;off>>=1) tmax=fmaxf(tmax,__shfl_xor_sync(0xffffffffu,tmax,off,16));
        float c=__expf(mold-tmax);
        float lsum=0.f;
        #pragma unroll
        for(int j=0;j<4;j++){
            float p=__expf(sv[j]-tmax);
            Sc[row][j*16+cg]=p;
            lsum+=p;
        }
        #pragma unroll
        for(int off=8;off>0;off>>=1) lsum+=__shfl_xor_sync(0xffffffffu,lsum,off,16);
        if(cg==0){ mrow[row]=tmax; lrow[row]=lold*c+lsum; }
        __syncwarp();
        #pragma unroll
        for(int j=0;j<4;j++) oacc[j]*=c;
        #pragma unroll
        for(int k=0;k<64;k++){
            float s=Sc[row][k];
            float4 v4=*(const float4*)&Vs[k][cg*4];
            oacc[0]+=s*v4.x; oacc[1]+=s*v4.y; oacc[2]+=s*v4.z; oacc[3]+=s*v4.w;
        }
        __syncthreads();
    }
    float linv=1.0f/lrow[row];
    size_t ob = (size_t)(b*SSL+q0+row)*DD + h*64 + cg*4;
    #pragma unroll
    for(int j=0;j<4;j++){
        float v = oacc[j]*linv;
        __nv_bfloat16 hh=__float2bfloat16(v);
        g_aohi[ob+j]=hh;
        g_aolo[ob+j]=__float2bfloat16(v-__bfloat162float(hh));
    }
}

// ===== fused router: dot products + softmax + top-2 + bucketing + moe-row zero =====
__global__ __launch_bounds__(256) void k_router(const float* __restrict__ rw, const float* __restrict__ rb){
    int n=blockIdx.x;
    int t=threadIdx.x, e=t>>5, lane=t&31;
    __shared__ float ms[DD];
    __shared__ float pe[EE];
    for(int i=t;i<DD;i+=256) ms[i]=g_m[(size_t)n*DD+i];
    // zero this token's moe accumulator row
    g_moe[(size_t)n*DD+t]=0.f;
    g_moe[(size_t)n*DD+t+256]=0.f;
    __syncthreads();
    float s=0.f;
    for(int k=lane;k<DD;k+=32) s+=ms[k]*rw[k*EE+e];
    #pragma unroll
    for(int off=16;off>0;off>>=1) s+=__shfl_xor_sync(0xffffffffu,s,off);
    if(lane==0) pe[e]=s+rb[e];
    __syncthreads();
    if(t==0){
        float p[EE]; float mx=-1e30f;
        #pragma unroll
        for(int i=0;i<EE;i++){ p[i]=pe[i]; mx=fmaxf(mx,p[i]); }
        #pragma unroll
        for(int i=0;i<EE;i++) p[i]=__expf(p[i]-mx);
        int e1=0;
        for(int i=1;i<EE;i++) if(p[i]>p[e1]) e1=i;
        int e2=-1;
        for(int i=0;i<EE;i++) if(i!=e1 && (e2<0 || p[i]>p[e2])) e2=i;
        float den=p[e1]+p[e2];
        int pos=atomicAdd(&g_ecount[e1],1);
        g_elist[e1*NTOK+pos]=n; g_egate[e1*NTOK+pos]=p[e1]/den;
        pos=atomicAdd(&g_ecount[e2],1);
        g_elist[e2*NTOK+pos]=n; g_egate[e2*NTOK+pos]=p[e2]/den;
    }
}

// ===== host =====
extern "C" void kernel_launch(void* const* d_in, const int* in_sizes, int n_in,
                              void* d_out, int out_size){
    (void)in_sizes; (void)n_in; (void)out_size;
    const int*   ids  = (const int*)  d_in[0];
    const float* tok  = (const float*)d_in[1];
    const float* pos  = (const float*)d_in[2];
    const float* ln1g = (const float*)d_in[3];
    const float* ln1b = (const float*)d_in[4];
    const float* iqw  = (const float*)d_in[5];
    const float* iqb  = (const float*)d_in[6];
    const float* ikw  = (const float*)d_in[7];
    const float* ikb  = (const float*)d_in[8];
    const float* ihw  = (const float*)d_in[9];
    const float* wq   = (const float*)d_in[10];
    const float* bq   = (const float*)d_in[11];
    const float* wk   = (const float*)d_in[12];
    const float* bk   = (const float*)d_in[13];
    const float* wv   = (const float*)d_in[14];
    const float* bv   = (const float*)d_in[15];
    const float* wo   = (const float*)d_in[16];
    const float* bo   = (const float*)d_in[17];
    const float* ln2g = (const float*)d_in[18];
    const float* ln2b = (const float*)d_in[19];
    const float* rw   = (const float*)d_in[20];
    const float* rb   = (const float*)d_in[21];
    const float* ew1  = (const float*)d_in[22];
    const float* eb1  = (const float*)d_in[23];
    const float* ew2  = (const float*)d_in[24];
    const float* eb2  = (const float*)d_in[25];
    const float* lnfg = (const float*)d_in[26];
    const float* lnfb = (const float*)d_in[27];
    const float* ow   = (const float*)d_in[28];
    const float* ob   = (const float*)d_in[29];
    float* out = (float*)d_out;

    float *px,*ph,*pm,*pq,*pk,*pv,*pmoe;
    int *pec;
    __nv_bfloat16 *phhi,*phlo,*pmhi,*pmlo,*powThi,*powTlo,*pw1Thi,*pw1Tlo,*pw2Thi,*pw2Tlo;
    __nv_bfloat16 *pwqh,*pwql,*pwkh,*pwkl,*pwvh,*pwvl,*pwoh,*pwol,*piqh,*piql,*pikh,*pikl;
    cudaGetSymbolAddress((void**)&px,g_x);
    cudaGetSymbolAddress((void**)&ph,g_h);
    cudaGetSymbolAddress((void**)&pm,g_m);
    cudaGetSymbolAddress((void**)&pq,g_q);
    cudaGetSymbolAddress((void**)&pk,g_k);
    cudaGetSymbolAddress((void**)&pv,g_v);
    cudaGetSymbolAddress((void**)&pmoe,g_moe);
    cudaGetSymbolAddress((void**)&pec,g_ecount);
    cudaGetSymbolAddress((void**)&phhi,g_hhi);
    cudaGetSymbolAddress((void**)&phlo,g_hlo);
    cudaGetSymbolAddress((void**)&pmhi,g_mhi);
    cudaGetSymbolAddress((void**)&pmlo,g_mlo);
    cudaGetSymbolAddress((void**)&powThi,g_owThi);
    cudaGetSymbolAddress((void**)&powTlo,g_owTlo);
    cudaGetSymbolAddress((void**)&pw1Thi,g_w1Thi);
    cudaGetSymbolAddress((void**)&pw1Tlo,g_w1Tlo);
    cudaGetSymbolAddress((void**)&pw2Thi,g_w2Thi);
    cudaGetSymbolAddress((void**)&pw2Tlo,g_w2Tlo);
    cudaGetSymbolAddress((void**)&pwqh,g_wqThi);
    cudaGetSymbolAddress((void**)&pwql,g_wqTlo);
    cudaGetSymbolAddress((void**)&pwkh,g_wkThi);
    cudaGetSymbolAddress((void**)&pwkl,g_wkTlo);
    cudaGetSymbolAddress((void**)&pwvh,g_wvThi);
    cudaGetSymbolAddress((void**)&pwvl,g_wvTlo);
    cudaGetSymbolAddress((void**)&pwoh,g_woThi);
    cudaGetSymbolAddress((void**)&pwol,g_woTlo);
    cudaGetSymbolAddress((void**)&piqh,g_iqThi);
    cudaGetSymbolAddress((void**)&piql,g_iqTlo);
    cudaGetSymbolAddress((void**)&pikh,g_ikThi);
    cudaGetSymbolAddress((void**)&pikl,g_ikTlo);

    cudaFuncSetAttribute(k_hmma_vocab, cudaFuncAttributeMaxDynamicSharedMemorySize, HS_TOTAL);
    cudaFuncSetAttribute(k_hmma_proj,  cudaFuncAttributeMaxDynamicSharedMemorySize, HS_TOTAL);
    cudaFuncSetAttribute(k_hmma_oproj, cudaFuncAttributeMaxDynamicSharedMemorySize, HS_TOTAL);
    cudaFuncSetAttribute(k_hmma_moe1,  cudaFuncAttributeMaxDynamicSharedMemorySize, HS_TOTAL);
    cudaFuncSetAttribute(k_hmma_moe2,  cudaFuncAttributeMaxDynamicSharedMemorySize, HS_TOTAL);

    // weight transposes + bf16 splits
    k_transcvtB<<<dim3(VV/32, DD/32, 1),256>>>(ow, powThi, powTlo, DD, VV);
    k_transcvtB<<<dim3(FFD/32, DD/32, LLN*EE),256>>>(ew1, pw1Thi, pw1Tlo, DD, FFD);
    k_transcvtB<<<dim3(DD/32, FFD/32, LLN*EE),256>>>(ew2, pw2Thi, pw2Tlo, FFD, DD);
    k_transcvtB<<<dim3(DD/32, DD/32, LLN),256>>>(wq, pwqh, pwql, DD, DD);
    k_transcvtB<<<dim3(DD/32, DD/32, LLN),256>>>(wk, pwkh, pwkl, DD, DD);
    k_transcvtB<<<dim3(DD/32, DD/32, LLN),256>>>(wv, pwvh, pwvl, DD, DD);
    k_transcvtB<<<dim3(DD/32, DD/32, LLN),256>>>(wo, pwoh, pwol, DD, DD);
    k_transcvtB<<<dim3((HHI*DII)/32, DD/32, LLN),256>>>(iqw, piqh, piql, DD, HHI*DII);
    k_transcvtB<<<dim3((HHI*DII)/32, DD/32, LLN),256>>>(ikw, pikh, pikl, DD, HHI*DII);

    k_embed<<<NTOK,512>>>(ids, tok, pos);

    for(int l=0;l<LLN;l++){
        // ln1: fuse previous layer's MoE residual add (l>0)
        k_ln<<<NTOK,256>>>(px, ln1g+l*DD, ln1b+l*DD, ph, phhi, phlo,
                           (l>0)?pmoe:nullptr, nullptr);
        {   H3 p;
            p.h0=piqh+(size_t)l*HHI*DII*DD; p.l0=piql+(size_t)l*HHI*DII*DD; p.c0=iqb+l*HHI*DII; p.o0=g_qi;
            p.h1=pikh+(size_t)l*HHI*DII*DD; p.l1=pikl+(size_t)l*HHI*DII*DD; p.c1=ikb+l*HHI*DII; p.o1=g_ki;
            p.h2=p.h0; p.l2=p.l0; p.c2=p.c0; p.o2=g_qi;
            cudaGetSymbolAddress((void**)&p.o0,g_qi);
            cudaGetSymbolAddress((void**)&p.o1,g_ki);
            p.o2=p.o0;
            k_hmma_proj<<<dim3((HHI*DII)/128, NTOK/128, 2),256,HS_TOTAL>>>(p, HHI*DII);
        }
        k_idxscore<<<dim3(SSL/64,SSL/64,BB),256>>>(ihw+l*HHI);
        k_topk<<<dim3(SSL,BB),512>>>();
        {   H3 p;
            p.h0=pwqh+(size_t)l*DD*DD; p.l0=pwql+(size_t)l*DD*DD; p.c0=bq+l*DD; p.o0=pq;
            p.h1=pwkh+(size_t)l*DD*DD; p.l1=pwkl+(size_t)l*DD*DD; p.c1=bk+l*DD; p.o1=pk;
            p.h2=pwvh+(size_t)l*DD*DD; p.l2=pwvl+(size_t)l*DD*DD; p.c2=bv+l*DD; p.o2=pv;
            k_hmma_proj<<<dim3(DD/128, NTOK/128, 3),256,HS_TOTAL>>>(p, DD);
        }
        k_attn<<<dim3(SSL/16,HHN,BB),256>>>();
        k_hmma_oproj<<<dim3(DD/128, NTOK/128),256,HS_TOTAL>>>(
            pwoh+(size_t)l*DD*DD, pwol+(size_t)l*DD*DD, bo+l*DD, px);

        // ln2: fuse ecount zero
        k_ln<<<NTOK,256>>>(px, ln2g+l*DD, ln2b+l*DD, pm, pmhi, pmlo, nullptr, pec);
        k_router<<<NTOK,256>>>(rw+(size_t)l*DD*EE, rb+l*EE);
        k_hmma_moe1<<<dim3(FFD/128, NTOK/128, EE),256,HS_TOTAL>>>(
            pw1Thi+(size_t)l*EE*FFD*DD, pw1Tlo+(size_t)l*EE*FFD*DD, eb1+(size_t)l*EE*FFD);
        k_hmma_moe2<<<dim3(DD/128, NTOK/128, EE),256,HS_TOTAL>>>(
            pw2Thi+(size_t)l*EE*DD*FFD, pw2Tlo+(size_t)l*EE*DD*FFD, eb2+(size_t)l*EE*DD);
    }

    // final ln: fuse last layer's MoE residual add
    k_ln<<<NTOK,256>>>(px, lnfg, lnfb, ph, phhi, phlo, pmoe, nullptr);
    k_hmma_vocab<<<dim3(VV/128, NTOK/128),256,HS_TOTAL>>>(ob, out);
}

// round 11
// speedup vs baseline: 1.9932x; 1.0708x over previous
#include <cuda_runtime.h>
#include <cuda_bf16.h>
#include <math.h>
#include <stdint.h>

#define BB 2
#define SSL 1024
#define NTOK 2048
#define DD 512
#define HHN 8
#define HHI 4
#define DII 64
#define FFD 2048
#define EE 8
#define VV 32000
#define KTOP 256
#define NEGV (-1e9f)
#define EPSV 1e-5f
#define LLN 2
#define SCALE 0.125f

__device__ float g_x[NTOK*DD];
__device__ float g_h[NTOK*DD];
__device__ float g_m[NTOK*DD];
__device__ float g_q[NTOK*DD];
__device__ float g_k[NTOK*DD];
__device__ float g_v[NTOK*DD];
__device__ float g_moe[NTOK*DD];
__device__ float g_mask[(size_t)BB*SSL*SSL];
__device__ int g_ecount[EE];
__device__ int g_elist[EE*NTOK];
__device__ float g_egate[EE*NTOK];
__device__ alignas(16) __nv_bfloat16 g_hhi[NTOK*DD];
__device__ alignas(16) __nv_bfloat16 g_hlo[NTOK*DD];
__device__ alignas(16) __nv_bfloat16 g_mhi[NTOK*DD];
__device__ alignas(16) __nv_bfloat16 g_mlo[NTOK*DD];
__device__ alignas(16) __nv_bfloat16 g_aohi[NTOK*DD];
__device__ alignas(16) __nv_bfloat16 g_aolo[NTOK*DD];
__device__ alignas(16) float g_qi[NTOK*HHI*DII];
__device__ alignas(16) float g_ki[NTOK*HHI*DII];
__device__ alignas(16) __nv_bfloat16 g_owThi[(size_t)VV*DD];
__device__ alignas(16) __nv_bfloat16 g_owTlo[(size_t)VV*DD];
__device__ alignas(16) __nv_bfloat16 g_w1Thi[(size_t)LLN*EE*FFD*DD];
__device__ alignas(16) __nv_bfloat16 g_w1Tlo[(size_t)LLN*EE*FFD*DD];
__device__ alignas(16) __nv_bfloat16 g_w2Thi[(size_t)LLN*EE*DD*FFD];
__device__ alignas(16) __nv_bfloat16 g_w2Tlo[(size_t)LLN*EE*DD*FFD];
__device__ alignas(16) __nv_bfloat16 g_h1hi[(size_t)EE*NTOK*FFD];
__device__ alignas(16) __nv_bfloat16 g_h1lo[(size_t)EE*NTOK*FFD];
__device__ alignas(16) __nv_bfloat16 g_wqThi[LLN*DD*DD];
__device__ alignas(16) __nv_bfloat16 g_wqTlo[LLN*DD*DD];
__device__ alignas(16) __nv_bfloat16 g_wkThi[LLN*DD*DD];
__device__ alignas(16) __nv_bfloat16 g_wkTlo[LLN*DD*DD];
__device__ alignas(16) __nv_bfloat16 g_wvThi[LLN*DD*DD];
__device__ alignas(16) __nv_bfloat16 g_wvTlo[LLN*DD*DD];
__device__ alignas(16) __nv_bfloat16 g_woThi[LLN*DD*DD];
__device__ alignas(16) __nv_bfloat16 g_woTlo[LLN*DD*DD];
__device__ alignas(16) __nv_bfloat16 g_iqThi[LLN*HHI*DII*DD];
__device__ alignas(16) __nv_bfloat16 g_iqTlo[LLN*HHI*DII*DD];
__device__ alignas(16) __nv_bfloat16 g_ikThi[LLN*HHI*DII*DD];
__device__ alignas(16) __nv_bfloat16 g_ikTlo[LLN*HHI*DII*DD];

__device__ __forceinline__ float gelu_tanh(float x){
    float x3 = x*x*x;
    return 0.5f*x*(1.f + tanhf(0.7978845608028654f*(x + 0.044715f*x3)));
}

__global__ void k_embed(const int* __restrict__ ids, const float* __restrict__ tok, const float* __restrict__ pos){
    int n=blockIdx.x, t=threadIdx.x;
    g_x[(size_t)n*DD+t] = tok[(size_t)ids[n]*DD+t] + pos[(size_t)(n%SSL)*DD+t];
}

// layernorm (shuffle reductions, 2 barriers); optional residual-add write-back, bf16 split, ecount zero
__global__ __launch_bounds__(256) void k_ln(float* __restrict__ in, const float* __restrict__ g,
        const float* __restrict__ b, float* __restrict__ out,
        __nv_bfloat16* __restrict__ hi, __nv_bfloat16* __restrict__ lo,
        const float* __restrict__ radd, int* __restrict__ ecz){
    int r=blockIdx.x, t=threadIdx.x;
    int lane=t&31, wid=t>>5;
    __shared__ float red1[8], red2[8];
    if(ecz && r==0 && t<EE) ecz[t]=0;
    float v0=in[(size_t)r*DD+t], v1=in[(size_t)r*DD+t+256];
    if(radd){
        v0 += radd[(size_t)r*DD+t];
        v1 += radd[(size_t)r*DD+t+256];
        in[(size_t)r*DD+t]=v0;
        in[(size_t)r*DD+t+256]=v1;
    }
    float s=v0+v1;
    #pragma unroll
    for(int off=16;off>0;off>>=1) s+=__shfl_xor_sync(0xffffffffu,s,off);
    if(lane==0) red1[wid]=s;
    __syncthreads();
    float mu=(red1[0]+red1[1]+red1[2]+red1[3]+red1[4]+red1[5]+red1[6]+red1[7])*(1.0f/DD);
    float d0=v0-mu, d1=v1-mu;
    float s2=d0*d0+d1*d1;
    #pragma unroll
    for(int off=16;off>0;off>>=1) s2+=__shfl_xor_sync(0xffffffffu,s2,off);
    if(lane==0) red2[wid]=s2;
    __syncthreads();
    float var=(red2[0]+red2[1]+red2[2]+red2[3]+red2[4]+red2[5]+red2[6]+red2[7])*(1.0f/DD);
    float rs=rsqrtf(var+EPSV);
    float o0=d0*rs*g[t]+b[t];
    float o1=d1*rs*g[t+256]+b[t+256];
    out[(size_t)r*DD+t]=o0;
    out[(size_t)r*DD+t+256]=o1;
    if(hi){
        __nv_bfloat16 h0=__float2bfloat16(o0), h1=__float2bfloat16(o1);
        hi[(size_t)r*DD+t]=h0;
        hi[(size_t)r*DD+t+256]=h1;
        lo[(size_t)r*DD+t]=__float2bfloat16(o0-__bfloat162float(h0));
        lo[(size_t)r*DD+t+256]=__float2bfloat16(o1-__bfloat162float(h1));
    }
}

// batched W[z][K][N] fp32 -> T[z][N][K] bf16 hi/lo; tile 64k x 32n, packed uint32 stores
__global__ __launch_bounds__(256) void k_transcvtB(const float* __restrict__ W,
        __nv_bfloat16* __restrict__ Thi, __nv_bfloat16* __restrict__ Tlo, int K, int N){
    int z=blockIdx.z;
    W   += (size_t)z*K*N;
    Thi += (size_t)z*N*K;
    Tlo += (size_t)z*N*K;
    __shared__ float t[32][66];   // [n][k]
    int n0=blockIdx.x*32, k0=blockIdx.y*64;
    int lane=threadIdx.x&31, wid=threadIdx.x>>5;
    #pragma unroll
    for(int i=0;i<8;i++){
        int kk=wid*8+i;
        t[lane][kk]=W[(size_t)(k0+kk)*N + n0+lane];
    }
    __syncthreads();
    #pragma unroll
    for(int j=0;j<4;j++){
        int n=wid*4+j;
        float2 ab=*(float2*)&t[n][2*lane];
        __nv_bfloat16 ha=__float2bfloat16(ab.x), hb=__float2bfloat16(ab.y);
        uint32_t hw=(uint32_t)__bfloat16_as_ushort(ha) | ((uint32_t)__bfloat16_as_ushort(hb)<<16);
        __nv_bfloat16 la=__float2bfloat16(ab.x-__bfloat162float(ha));
        __nv_bfloat16 lb=__float2bfloat16(ab.y-__bfloat162float(hb));
        uint32_t lw=(uint32_t)__bfloat16_as_ushort(la) | ((uint32_t)__bfloat16_as_ushort(lb)<<16);
        *(uint32_t*)(Thi + (size_t)(n0+n)*K + k0 + 2*lane)=hw;
        *(uint32_t*)(Tlo + (size_t)(n0+n)*K + k0 + 2*lane)=lw;
    }
}

// ================= HMMA bf16-split GEMM core =================
__device__ __forceinline__ uint32_t smem_u32(const void* p){
    uint32_t a;
    asm("{ .reg .u64 t; cvta.to.shared.u64 t, %1; cvt.u32.u64 %0, t; }" : "=r"(a) : "l"(p));
    return a;
}
__device__ __forceinline__ void ldsm4(uint32_t (&r)[4], uint32_t a){
    asm volatile("ldmatrix.sync.aligned.m8n8.x4.shared.b16 {%0,%1,%2,%3}, [%4];"
        : "=r"(r[0]),"=r"(r[1]),"=r"(r[2]),"=r"(r[3]) : "r"(a));
}
__device__ __forceinline__ void ldsm2(uint32_t (&r)[2], uint32_t a){
    asm volatile("ldmatrix.sync.aligned.m8n8.x2.shared.b16 {%0,%1}, [%2];"
        : "=r"(r[0]),"=r"(r[1]) : "r"(a));
}
__device__ __forceinline__ void mma16816(float (&c)[4], const uint32_t (&a)[4], const uint32_t (&b)[2]){
    asm volatile("mma.sync.aligned.m16n8k16.row.col.f32.bf16.bf16.f32 "
        "{%0,%1,%2,%3}, {%4,%5,%6,%7}, {%8,%9}, {%0,%1,%2,%3};"
        : "+f"(c[0]),"+f"(c[1]),"+f"(c[2]),"+f"(c[3])
        : "r"(a[0]),"r"(a[1]),"r"(a[2]),"r"(a[3]), "r"(b[0]),"r"(b[1]));
}
#define HS_BUF 24576
#define HS_TILE 6144
#define HS_TOTAL 49664

__device__ __forceinline__ void hmma_main(char* sm, const int* rowidx,
    const __nv_bfloat16* __restrict__ Ahi, const __nv_bfloat16* __restrict__ Alo, int sA,
    const __nv_bfloat16* __restrict__ Bhi, const __nv_bfloat16* __restrict__ Blo, int sB,
    int col0, int K, float (&acc)[4][4][4])
{
    int tid=threadIdx.x, lane=tid&31, warp=tid>>5;
    int wm=warp>>2, wn=warp&3;
    uint32_t smb = smem_u32(sm);
    #pragma unroll
    for(int i=0;i<4;i++)
        #pragma unroll
        for(int j=0;j<4;j++)
            #pragma unroll
            for(int q=0;q<4;q++) acc[i][j][q]=0.f;

    int ltile[4], lrow[4], lhalf[4];
    #pragma unroll
    for(int t=0;t<4;t++){
        int i = tid + t*256;
        ltile[t]=i>>8; lrow[t]=(i&255)>>1; lhalf[t]=(i&1)*8;
    }
    uint4 pre[4];
    const int NS = K>>4;
    int lb = lane&15;
    uint32_t boff = (uint32_t)((wn*32 + (lb&7))*48 + ((lb&8)?16:0));
    uint32_t aoff = (uint32_t)((wm*64 + (lane&7) + ((lane&8)?8:0))*48 + ((lane&16)?16:0));

    auto ldg = [&](int s){
        int k0 = s<<4;
        #pragma unroll
        for(int t=0;t<4;t++){
            const __nv_bfloat16* src;
            int row=lrow[t];
            if(ltile[t]==0)      src = Ahi + (size_t)rowidx[row]*sA;
            else if(ltile[t]==1) src = Alo + (size_t)rowidx[row]*sA;
            else if(ltile[t]==2) src = Bhi + (size_t)(col0+row)*sB;
            else                 src = Blo + (size_t)(col0+row)*sB;
            pre[t] = *(const uint4*)(src + k0 + lhalf[t]);
        }
    };
    auto sts = [&](int b){
        #pragma unroll
        for(int t=0;t<4;t++)
            *(uint4*)(sm + b*HS_BUF + ltile[t]*HS_TILE + lrow[t]*48 + lhalf[t]*2) = pre[t];
    };
    ldg(0); sts(0);
    __syncthreads();
    for(int s=0;s<NS;s++){
        int b=s&1;
        if(s+1<NS) ldg(s+1);
        uint32_t base = smb + b*HS_BUF;
        uint32_t bh[4][2], bl[4][2];
        #pragma unroll
        for(int j=0;j<4;j++){
            ldsm2(bh[j], base + 2*HS_TILE + boff + j*8*48);
            ldsm2(bl[j], base + 3*HS_TILE + boff + j*8*48);
        }
        #pragma unroll
        for(int i=0;i<4;i++){
            uint32_t a[4];
            ldsm4(a, base + aoff + i*16*48);
            #pragma unroll
            for(int j=0;j<4;j++){ mma16816(acc[i][j], a, bh[j]); mma16816(acc[i][j], a, bl[j]); }
            ldsm4(a, base + HS_TILE + aoff + i*16*48);
            #pragma unroll
            for(int j=0;j<4;j++) mma16816(acc[i][j], a, bh[j]);
        }
        if(s+1<NS) sts(b^1);
        __syncthreads();
    }
}

// ---- vocab: grid (NTOK/128, VV/128); x=rows so concurrent blocks share B strips in L2 ----
__global__ __launch_bounds__(256,1) void k_hmma_vocab(const float* __restrict__ ob, float* __restrict__ out){
    extern __shared__ char sm[];
    int* rowidx = (int*)(sm + 2*HS_BUF);
    int tid=threadIdx.x;
    int row0=blockIdx.x*128, col0=blockIdx.y*128;
    if(tid<128) rowidx[tid]=row0+tid;
    __syncthreads();
    float acc[4][4][4];
    hmma_main(sm, rowidx, g_hhi, g_hlo, DD, g_owThi, g_owTlo, DD, col0, DD, acc);
    int lane=tid&31, warp=tid>>5, wm=warp>>2, wn=warp&3;
    #pragma unroll
    for(int i=0;i<4;i++){
        int r0 = row0 + wm*64 + i*16 + (lane>>2);
        #pragma unroll
        for(int j=0;j<4;j++){
            int c = col0 + wn*32 + j*8 + (lane&3)*2;
            float b0=ob[c], b1=ob[c+1];
            out[(size_t)r0*VV + c]       = acc[i][j][0] + b0;
            out[(size_t)r0*VV + c+1]     = acc[i][j][1] + b1;
            out[(size_t)(r0+8)*VV + c]   = acc[i][j][2] + b0;
            out[(size_t)(r0+8)*VV + c+1] = acc[i][j][3] + b1;
        }
    }
}

// ---- generic projection: fp32 out, 3-way batched ----
struct H3 {
    const __nv_bfloat16 *h0,*l0,*h1,*l1,*h2,*l2;
    const float *c0,*c1,*c2;
    float *o0,*o1,*o2;
};
__global__ __launch_bounds__(256,1) void k_hmma_proj(H3 p, int N){
    extern __shared__ char sm[];
    int* rowidx = (int*)(sm + 2*HS_BUF);
    int tid=threadIdx.x;
    int row0=blockIdx.y*128, col0=blockIdx.x*128;
    const __nv_bfloat16 *Bh,*Bl; const float* bias; float* out;
    if(blockIdx.z==0){Bh=p.h0;Bl=p.l0;bias=p.c0;out=p.o0;}
    else if(blockIdx.z==1){Bh=p.h1;Bl=p.l1;bias=p.c1;out=p.o1;}
    else {Bh=p.h2;Bl=p.l2;bias=p.c2;out=p.o2;}
    if(tid<128) rowidx[tid]=row0+tid;
    __syncthreads();
    float acc[4][4][4];
    hmma_main(sm, rowidx, g_hhi, g_hlo, DD, Bh, Bl, DD, col0, DD, acc);
    int lane=tid&31, warp=tid>>5, wm=warp>>2, wn=warp&3;
    #pragma unroll
    for(int i=0;i<4;i++){
        int r0 = row0 + wm*64 + i*16 + (lane>>2);
        #pragma unroll
        for(int j=0;j<4;j++){
            int c = col0 + wn*32 + j*8 + (lane&3)*2;
            float b0=bias[c], b1=bias[c+1];
            out[(size_t)r0*N + c]       = acc[i][j][0] + b0;
            out[(size_t)r0*N + c+1]     = acc[i][j][1] + b1;
            out[(size_t)(r0+8)*N + c]   = acc[i][j][2] + b0;
            out[(size_t)(r0+8)*N + c+1] = acc[i][j][3] + b1;
        }
    }
}

// ---- O projection with residual ----
__global__ __launch_bounds__(256,1) void k_hmma_oproj(const __nv_bfloat16* __restrict__ Whi,
        const __nv_bfloat16* __restrict__ Wlo, const float* __restrict__ bias, float* __restrict__ x){
    extern __shared__ char sm[];
    int* rowidx = (int*)(sm + 2*HS_BUF);
    int tid=threadIdx.x;
    int row0=blockIdx.y*128, col0=blockIdx.x*128;
    if(tid<128) rowidx[tid]=row0+tid;
    __syncthreads();
    float acc[4][4][4];
    hmma_main(sm, rowidx, g_aohi, g_aolo, DD, Whi, Wlo, DD, col0, DD, acc);
    int lane=tid&31, warp=tid>>5, wm=warp>>2, wn=warp&3;
    #pragma unroll
    for(int i=0;i<4;i++){
        int r0 = row0 + wm*64 + i*16 + (lane>>2);
        #pragma unroll
        for(int j=0;j<4;j++){
            int c = col0 + wn*32 + j*8 + (lane&3)*2;
            float b0=bias[c], b1=bias[c+1];
            x[(size_t)r0*DD + c]       += acc[i][j][0] + b0;
            x[(size_t)r0*DD + c+1]     += acc[i][j][1] + b1;
            x[(size_t)(r0+8)*DD + c]   += acc[i][j][2] + b0;
            x[(size_t)(r0+8)*DD + c+1] += acc[i][j][3] + b1;
        }
    }
}

// ---- MoE1: grid (NTOK/128, FFD/128, EE); x=rows ----
__global__ __launch_bounds__(256,1) void k_hmma_moe1(const __nv_bfloat16* __restrict__ Whi,
        const __nv_bfloat16* __restrict__ Wlo, const float* __restrict__ B1){
    int e=blockIdx.z, cnt=g_ecount[e], row0=blockIdx.x*128;
    if(row0>=cnt) return;
    extern __shared__ char sm[];
    int* rowidx = (int*)(sm + 2*HS_BUF);
    int tid=threadIdx.x;
    int col0=blockIdx.y*128;
    if(tid<128){
        int r=row0+tid;
        rowidx[tid] = (r<cnt)? g_elist[e*NTOK+r] : g_elist[e*NTOK];
    }
    __syncthreads();
    float acc[4][4][4];
    hmma_main(sm, rowidx, g_mhi, g_mlo, DD,
              Whi+(size_t)e*FFD*DD, Wlo+(size_t)e*FFD*DD, DD, col0, DD, acc);
    const float* bia = B1 + (size_t)e*FFD;
    int lane=tid&31, warp=tid>>5, wm=warp>>2, wn=warp&3;
    #pragma unroll
    for(int i=0;i<4;i++){
        int r0 = row0 + wm*64 + i*16 + (lane>>2);
        #pragma unroll
        for(int j=0;j<4;j++){
            int c = col0 + wn*32 + j*8 + (lane&3)*2;
            float b0=bia[c], b1=bia[c+1];
            #pragma unroll
            for(int q=0;q<4;q++){
                int r = r0 + (q>=2?8:0);
                if(r>=cnt) continue;
                int cc = c + (q&1);
                float v = gelu_tanh(acc[i][j][q] + ((q&1)?b1:b0));
                __nv_bfloat16 h=__float2bfloat16(v);
                size_t o = ((size_t)e*NTOK + r)*FFD + cc;
                g_h1hi[o]=h; g_h1lo[o]=__float2bfloat16(v-__bfloat162float(h));
            }
        }
    }
}

// ---- MoE2: grid (NTOK/128, DD/128, EE); x=rows ----
__global__ __launch_bounds__(256,1) void k_hmma_moe2(const __nv_bfloat16* __restrict__ Whi,
        const __nv_bfloat16* __restrict__ Wlo, const float* __restrict__ B2){
    int e=blockIdx.z, cnt=g_ecount[e], row0=blockIdx.x*128;
    if(row0>=cnt) return;
    extern __shared__ char sm[];
    int* rowidx = (int*)(sm + 2*HS_BUF);
    int tid=threadIdx.x;
    int col0=blockIdx.y*128;
    if(tid<128) rowidx[tid] = e*NTOK + row0 + tid;
    __syncthreads();
    float acc[4][4][4];
    hmma_main(sm, rowidx, g_h1hi, g_h1lo, FFD,
              Whi+(size_t)e*DD*FFD, Wlo+(size_t)e*DD*FFD, FFD, col0, FFD, acc);
    const float* bia = B2 + (size_t)e*DD;
    int lane=tid&31, warp=tid>>5, wm=warp>>2, wn=warp&3;
    #pragma unroll
    for(int i=0;i<4;i++){
        int r0 = row0 + wm*64 + i*16 + (lane>>2);
        #pragma unroll
        for(int j=0;j<4;j++){
            int c = col0 + wn*32 + j*8 + (lane&3)*2;
            float b0=bia[c], b1=bia[c+1];
            #pragma unroll
            for(int q=0;q<4;q++){
                int r = r0 + (q>=2?8:0);
                if(r>=cnt) continue;
                int tok=g_elist[e*NTOK+r];
                float gv=g_egate[e*NTOK+r];
                int cc = c + (q&1);
                atomicAdd(&g_moe[(size_t)tok*DD+cc], gv*(acc[i][j][q] + ((q&1)?b1:b0)));
            }
        }
    }
}

// ===== indexer scores (causal tile-skip) =====
__global__ __launch_bounds__(256) void k_idxscore(const float* __restrict__ hw){
    int kt=blockIdx.x, qt=blockIdx.y, b=blockIdx.z;
    int tx=threadIdx.x&15, ty=threadIdx.x>>4;
    if(kt>qt){
        #pragma unroll
        for(int i=0;i<4;i++){
            int q=qt*64+ty*4+i;
            float4 nv={NEGV,NEGV,NEGV,NEGV};
            *(float4*)&g_mask[((size_t)b*SSL+q)*SSL + kt*64+tx*4]=nv;
        }
        return;
    }
    __shared__ float Qs[64][68];
    __shared__ float Ks[64][68];
    float acc[4][4]={};
    for(int h=0;h<HHI;h++){
        for(int i=threadIdx.x;i<4096;i+=256){
            int r=i>>6, d=i&63;
            Qs[d][r]=g_qi[(size_t)(b*SSL+qt*64+r)*(HHI*DII)+h*64+d];
            Ks[d][r]=g_ki[(size_t)(b*SSL+kt*64+r)*(HHI*DII)+h*64+d];
        }
        __syncthreads();
        float w=hw[h];
        float dot[4][4]={};
        #pragma unroll 8
        for(int d=0;d<64;d++){
            float4 a4=*(const float4*)&Qs[d][ty*4];
            float4 b4=*(const float4*)&Ks[d][tx*4];
            float a[4]={a4.x,a4.y,a4.z,a4.w};
            float bb[4]={b4.x,b4.y,b4.z,b4.w};
            #pragma unroll
            for(int i=0;i<4;i++)
                #pragma unroll
                for(int j=0;j<4;j++) dot[i][j]+=a[i]*bb[j];
        }
        #pragma unroll
        for(int i=0;i<4;i++)
            #pragma unroll
            for(int j=0;j<4;j++) acc[i][j]+=fmaxf(dot[i][j],0.f)*w;
        __syncthreads();
    }
    #pragma unroll
    for(int i=0;i<4;i++){
        int q=qt*64+ty*4+i;
        #pragma unroll
        for(int j=0;j<4;j++){
            int k=kt*64+tx*4+j;
            g_mask[((size_t)b*SSL+q)*SSL+k]=acc[i][j]+((k<=q)?0.f:NEGV);
        }
    }
}

// ===== top-K bitonic =====
__global__ __launch_bounds__(512) void k_topk(){
    int q=blockIdx.x, b=blockIdx.y, t=threadIdx.x;
    __shared__ float s[1024];
    size_t base=((size_t)b*SSL+q)*SSL;
    s[t]=g_mask[base+t];
    s[t+512]=g_mask[base+t+512];
    __syncthreads();
    for(int size=2;size<=1024;size<<=1){
        for(int stride=size>>1;stride>0;stride>>=1){
            int lo=2*stride*(t/stride)+(t%stride);
            int hi=lo+stride;
            bool desc=((lo&size)==0);
            float a=s[lo], bv=s[hi];
            if((a<bv)==desc){ s[lo]=bv; s[hi]=a; }
            __syncthreads();
        }
    }
    float thr=s[KTOP-1];
    for(int k=t;k<SSL;k+=512){
        float v=g_mask[base+k];
        g_mask[base+k]=(k<=q && v>=thr)?0.f:NEGV;
    }
}

// ===== attention: conflict-free float4 + causal tile-skip; emits bf16-split output =====
__global__ __launch_bounds__(256) void k_attn(){
    int qt=blockIdx.x, h=blockIdx.y, b=blockIdx.z;
    int t=threadIdx.x, row=t>>4, cg=t&15;
    __shared__ float qs[16][68];
    __shared__ float Ks[64][68];
    __shared__ float Vs[64][68];
    __shared__ float Sc[16][68];
    __shared__ float mrow[16], lrow[16];
    int q0=qt*16;
    for(int i=t;i<16*64;i+=256){
        int r=i>>6, d=i&63;
        qs[r][d]=g_q[(size_t)(b*SSL+q0+r)*DD+h*64+d];
    }
    if(t<16){ mrow[t]=-1e30f; lrow[t]=0.f; }
    float oacc[4]={0.f,0.f,0.f,0.f};
    __syncthreads();
    const float* maskrow=g_mask+((size_t)b*SSL+(q0+row))*SSL;
    int kmax = q0 + 16;
    for(int k0=0;k0<kmax;k0+=64){
        for(int i=t;i<4096;i+=256){
            int r=i>>6, d=i&63;
            Ks[r][d]=g_k[(size_t)(b*SSL+k0+r)*DD+h*64+d];
            Vs[r][d]=g_v[(size_t)(b*SSL+k0+r)*DD+h*64+d];
        }
        __syncthreads();
        float sv[4]={0.f,0.f,0.f,0.f};
        #pragma unroll
        for(int d0=0;d0<64;d0+=4){
            float4 q4=*(const float4*)&qs[row][d0];
            #pragma unroll
            for(int j=0;j<4;j++){
                float4 k4=*(const float4*)&Ks[j*16+cg][d0];
                sv[j]+=q4.x*k4.x+q4.y*k4.y+q4.z*k4.z+q4.w*k4.w;
            }
        }
        #pragma unroll
        for(int j=0;j<4;j++) sv[j]=sv[j]*SCALE+maskrow[k0+j*16+cg];
        float mold=mrow[row], lold=lrow[row];
        float tmax=fmaxf(fmaxf(sv[0],sv[1]),fmaxf(sv[2],sv[3]));
        tmax=fmaxf(tmax,mold);
        #pragma unroll
        for(int off=8;off>0;off>>=1) tmax=fmaxf(tmax,__shfl_xor_sync(0xffffffffu,tmax,off,16));
        float c=__expf(mold-tmax);
        float lsum=0.f;
        #pragma unroll
        for(int j=0;j<4;j++){
            float p=__expf(sv[j]-tmax);
            Sc[row][j*16+cg]=p;
            lsum+=p;
        }
        #pragma unroll
        for(int off=8;off>0;off>>=1) lsum+=__shfl_xor_sync(0xffffffffu,lsum,off,16);
        if(cg==0){ mrow[row]=tmax; lrow[row]=lold*c+lsum; }
        __syncwarp();
        #pragma unroll
        for(int j=0;j<4;j++) oacc[j]*=c;
        #pragma unroll
        for(int k=0;k<64;k++){
            float s=Sc[row][k];
            float4 v4=*(const float4*)&Vs[k][cg*4];
            oacc[0]+=s*v4.x; oacc[1]+=s*v4.y; oacc[2]+=s*v4.z; oacc[3]+=s*v4.w;
        }
        __syncthreads();
    }
    float linv=1.0f/lrow[row];
    size_t ob = (size_t)(b*SSL+q0+row)*DD + h*64 + cg*4;
    #pragma unroll
    for(int j=0;j<4;j++){
        float v = oacc[j]*linv;
        __nv_bfloat16 hh=__float2bfloat16(v);
        g_aohi[ob+j]=hh;
        g_aolo[ob+j]=__float2bfloat16(v-__bfloat162float(hh));
    }
}

// ===== fused router =====
__global__ __launch_bounds__(256) void k_router(const float* __restrict__ rw, const float* __restrict__ rb){
    int n=blockIdx.x;
    int t=threadIdx.x, e=t>>5, lane=t&31;
    __shared__ float ms[DD];
    __shared__ float pe[EE];
    for(int i=t;i<DD;i+=256) ms[i]=g_m[(size_t)n*DD+i];
    g_moe[(size_t)n*DD+t]=0.f;
    g_moe[(size_t)n*DD+t+256]=0.f;
    __syncthreads();
    float s=0.f;
    for(int k=lane;k<DD;k+=32) s+=ms[k]*rw[k*EE+e];
    #pragma unroll
    for(int off=16;off>0;off>>=1) s+=__shfl_xor_sync(0xffffffffu,s,off);
    if(lane==0) pe[e]=s+rb[e];
    __syncthreads();
    if(t==0){
        float p[EE]; float mx=-1e30f;
        #pragma unroll
        for(int i=0;i<EE;i++){ p[i]=pe[i]; mx=fmaxf(mx,p[i]); }
        #pragma unroll
        for(int i=0;i<EE;i++) p[i]=__expf(p[i]-mx);
        int e1=0;
        for(int i=1;i<EE;i++) if(p[i]>p[e1]) e1=i;
        int e2=-1;
        for(int i=0;i<EE;i++) if(i!=e1 && (e2<0 || p[i]>p[e2])) e2=i;
        float den=p[e1]+p[e2];
        int pos=atomicAdd(&g_ecount[e1],1);
        g_elist[e1*NTOK+pos]=n; g_egate[e1*NTOK+pos]=p[e1]/den;
        pos=atomicAdd(&g_ecount[e2],1);
        g_elist[e2*NTOK+pos]=n; g_egate[e2*NTOK+pos]=p[e2]/den;
    }
}

// ===== host =====
extern "C" void kernel_launch(void* const* d_in, const int* in_sizes, int n_in,
                              void* d_out, int out_size){
    (void)in_sizes; (void)n_in; (void)out_size;
    const int*   ids  = (const int*)  d_in[0];
    const float* tok  = (const float*)d_in[1];
    const float* pos  = (const float*)d_in[2];
    const float* ln1g = (const float*)d_in[3];
    const float* ln1b = (const float*)d_in[4];
    const float* iqw  = (const float*)d_in[5];
    const float* iqb  = (const float*)d_in[6];
    const float* ikw  = (const float*)d_in[7];
    const float* ikb  = (const float*)d_in[8];
    const float* ihw  = (const float*)d_in[9];
    const float* wq   = (const float*)d_in[10];
    const float* bq   = (const float*)d_in[11];
    const float* wk   = (const float*)d_in[12];
    const float* bk   = (const float*)d_in[13];
    const float* wv   = (const float*)d_in[14];
    const float* bv   = (const float*)d_in[15];
    const float* wo   = (const float*)d_in[16];
    const float* bo   = (const float*)d_in[17];
    const float* ln2g = (const float*)d_in[18];
    const float* ln2b = (const float*)d_in[19];
    const float* rw   = (const float*)d_in[20];
    const float* rb   = (const float*)d_in[21];
    const float* ew1  = (const float*)d_in[22];
    const float* eb1  = (const float*)d_in[23];
    const float* ew2  = (const float*)d_in[24];
    const float* eb2  = (const float*)d_in[25];
    const float* lnfg = (const float*)d_in[26];
    const float* lnfb = (const float*)d_in[27];
    const float* ow   = (const float*)d_in[28];
    const float* ob   = (const float*)d_in[29];
    float* out = (float*)d_out;

    float *px,*ph,*pm,*pq,*pk,*pv,*pmoe,*pqi,*pki;
    int *pec;
    __nv_bfloat16 *phhi,*phlo,*pmhi,*pmlo,*powThi,*powTlo,*pw1Thi,*pw1Tlo,*pw2Thi,*pw2Tlo;
    __nv_bfloat16 *pwqh,*pwql,*pwkh,*pwkl,*pwvh,*pwvl,*pwoh,*pwol,*piqh,*piql,*pikh,*pikl;
    cudaGetSymbolAddress((void**)&px,g_x);
    cudaGetSymbolAddress((void**)&ph,g_h);
    cudaGetSymbolAddress((void**)&pm,g_m);
    cudaGetSymbolAddress((void**)&pq,g_q);
    cudaGetSymbolAddress((void**)&pk,g_k);
    cudaGetSymbolAddress((void**)&pv,g_v);
    cudaGetSymbolAddress((void**)&pmoe,g_moe);
    cudaGetSymbolAddress((void**)&pqi,g_qi);
    cudaGetSymbolAddress((void**)&pki,g_ki);
    cudaGetSymbolAddress((void**)&pec,g_ecount);
    cudaGetSymbolAddress((void**)&phhi,g_hhi);
    cudaGetSymbolAddress((void**)&phlo,g_hlo);
    cudaGetSymbolAddress((void**)&pmhi,g_mhi);
    cudaGetSymbolAddress((void**)&pmlo,g_mlo);
    cudaGetSymbolAddress((void**)&powThi,g_owThi);
    cudaGetSymbolAddress((void**)&powTlo,g_owTlo);
    cudaGetSymbolAddress((void**)&pw1Thi,g_w1Thi);
    cudaGetSymbolAddress((void**)&pw1Tlo,g_w1Tlo);
    cudaGetSymbolAddress((void**)&pw2Thi,g_w2Thi);
    cudaGetSymbolAddress((void**)&pw2Tlo,g_w2Tlo);
    cudaGetSymbolAddress((void**)&pwqh,g_wqThi);
    cudaGetSymbolAddress((void**)&pwql,g_wqTlo);
    cudaGetSymbolAddress((void**)&pwkh,g_wkThi);
    cudaGetSymbolAddress((void**)&pwkl,g_wkTlo);
    cudaGetSymbolAddress((void**)&pwvh,g_wvThi);
    cudaGetSymbolAddress((void**)&pwvl,g_wvTlo);
    cudaGetSymbolAddress((void**)&pwoh,g_woThi);
    cudaGetSymbolAddress((void**)&pwol,g_woTlo);
    cudaGetSymbolAddress((void**)&piqh,g_iqThi);
    cudaGetSymbolAddress((void**)&piql,g_iqTlo);
    cudaGetSymbolAddress((void**)&pikh,g_ikThi);
    cudaGetSymbolAddress((void**)&pikl,g_ikTlo);

    cudaFuncSetAttribute(k_hmma_vocab, cudaFuncAttributeMaxDynamicSharedMemorySize, HS_TOTAL);
    cudaFuncSetAttribute(k_hmma_proj,  cudaFuncAttributeMaxDynamicSharedMemorySize, HS_TOTAL);
    cudaFuncSetAttribute(k_hmma_oproj, cudaFuncAttributeMaxDynamicSharedMemorySize, HS_TOTAL);
    cudaFuncSetAttribute(k_hmma_moe1,  cudaFuncAttributeMaxDynamicSharedMemorySize, HS_TOTAL);
    cudaFuncSetAttribute(k_hmma_moe2,  cudaFuncAttributeMaxDynamicSharedMemorySize, HS_TOTAL);

    // weight transposes + bf16 splits (tile 64k x 32n)
    k_transcvtB<<<dim3(VV/32, DD/64, 1),256>>>(ow, powThi, powTlo, DD, VV);
    k_transcvtB<<<dim3(FFD/32, DD/64, LLN*EE),256>>>(ew1, pw1Thi, pw1Tlo, DD, FFD);
    k_transcvtB<<<dim3(DD/32, FFD/64, LLN*EE),256>>>(ew2, pw2Thi, pw2Tlo, FFD, DD);
    k_transcvtB<<<dim3(DD/32, DD/64, LLN),256>>>(wq, pwqh, pwql, DD, DD);
    k_transcvtB<<<dim3(DD/32, DD/64, LLN),256>>>(wk, pwkh, pwkl, DD, DD);
    k_transcvtB<<<dim3(DD/32, DD/64, LLN),256>>>(wv, pwvh, pwvl, DD, DD);
    k_transcvtB<<<dim3(DD/32, DD/64, LLN),256>>>(wo, pwoh, pwol, DD, DD);
    k_transcvtB<<<dim3((HHI*DII)/32, DD/64, LLN),256>>>(iqw, piqh, piql, DD, HHI*DII);
    k_transcvtB<<<dim3((HHI*DII)/32, DD/64, LLN),256>>>(ikw, pikh, pikl, DD, HHI*DII);

    k_embed<<<NTOK,512>>>(ids, tok, pos);

    for(int l=0;l<LLN;l++){
        k_ln<<<NTOK,256>>>(px, ln1g+l*DD, ln1b+l*DD, ph, phhi, phlo,
                           (l>0)?pmoe:nullptr, nullptr);
        {   H3 p;
            p.h0=piqh+(size_t)l*HHI*DII*DD; p.l0=piql+(size_t)l*HHI*DII*DD; p.c0=iqb+l*HHI*DII; p.o0=pqi;
            p.h1=pikh+(size_t)l*HHI*DII*DD; p.l1=pikl+(size_t)l*HHI*DII*DD; p.c1=ikb+l*HHI*DII; p.o1=pki;
            p.h2=p.h0; p.l2=p.l0; p.c2=p.c0; p.o2=pqi;
            k_hmma_proj<<<dim3((HHI*DII)/128, NTOK/128, 2),256,HS_TOTAL>>>(p, HHI*DII);
        }
        k_idxscore<<<dim3(SSL/64,SSL/64,BB),256>>>(ihw+l*HHI);
        k_topk<<<dim3(SSL,BB),512>>>();
        {   H3 p;
            p.h0=pwqh+(size_t)l*DD*DD; p.l0=pwql+(size_t)l*DD*DD; p.c0=bq+l*DD; p.o0=pq;
            p.h1=pwkh+(size_t)l*DD*DD; p.l1=pwkl+(size_t)l*DD*DD; p.c1=bk+l*DD; p.o1=pk;
            p.h2=pwvh+(size_t)l*DD*DD; p.l2=pwvl+(size_t)l*DD*DD; p.c2=bv+l*DD; p.o2=pv;
            k_hmma_proj<<<dim3(DD/128, NTOK/128, 3),256,HS_TOTAL>>>(p, DD);
        }
        k_attn<<<dim3(SSL/16,HHN,BB),256>>>();
        k_hmma_oproj<<<dim3(DD/128, NTOK/128),256,HS_TOTAL>>>(
            pwoh+(size_t)l*DD*DD, pwol+(size_t)l*DD*DD, bo+l*DD, px);

        k_ln<<<NTOK,256>>>(px, ln2g+l*DD, ln2b+l*DD, pm, pmhi, pmlo, nullptr, pec);
        k_router<<<NTOK,256>>>(rw+(size_t)l*DD*EE, rb+l*EE);
        k_hmma_moe1<<<dim3(NTOK/128, FFD/128, EE),256,HS_TOTAL>>>(
            pw1Thi+(size_t)l*EE*FFD*DD, pw1Tlo+(size_t)l*EE*FFD*DD, eb1+(size_t)l*EE*FFD);
        k_hmma_moe2<<<dim3(NTOK/128, DD/128, EE),256,HS_TOTAL>>>(
            pw2Thi+(size_t)l*EE*DD*FFD, pw2Tlo+(size_t)l*EE*DD*FFD, eb2+(size_t)l*EE*DD);
    }

    k_ln<<<NTOK,256>>>(px, lnfg, lnfb, ph, phhi, phlo, pmoe, nullptr);
    k_hmma_vocab<<<dim3(NTOK/128, VV/128),256,HS_TOTAL>>>(ob, out);
}

// round 12
// speedup vs baseline: 2.0917x; 1.0494x over previous
#include <cuda_runtime.h>
#include <cuda_bf16.h>
#include <math.h>
#include <stdint.h>

#define BB 2
#define SSL 1024
#define NTOK 2048
#define DD 512
#define HHN 8
#define HHI 4
#define DII 64
#define FFD 2048
#define EE 8
#define VV 32000
#define KTOP 256
#define NEGV (-1e9f)
#define EPSV 1e-5f
#define LLN 2
#define SCALE 0.125f

__device__ float g_x[NTOK*DD];
__device__ float g_h[NTOK*DD];
__device__ float g_m[NTOK*DD];
__device__ float g_q[NTOK*DD];
__device__ float g_k[NTOK*DD];
__device__ float g_v[NTOK*DD];
__device__ float g_moe[NTOK*DD];
__device__ float g_mask[(size_t)BB*SSL*SSL];
__device__ int g_ecount[EE];
__device__ int g_elist[EE*NTOK];
__device__ float g_egate[EE*NTOK];
__device__ alignas(16) __nv_bfloat16 g_hhi[NTOK*DD];
__device__ alignas(16) __nv_bfloat16 g_hlo[NTOK*DD];
__device__ alignas(16) __nv_bfloat16 g_mhi[NTOK*DD];
__device__ alignas(16) __nv_bfloat16 g_mlo[NTOK*DD];
__device__ alignas(16) __nv_bfloat16 g_aohi[NTOK*DD];
__device__ alignas(16) __nv_bfloat16 g_aolo[NTOK*DD];
__device__ alignas(16) float g_qi[NTOK*HHI*DII];
__device__ alignas(16) float g_ki[NTOK*HHI*DII];
__device__ alignas(16) __nv_bfloat16 g_owThi[(size_t)VV*DD];
__device__ alignas(16) __nv_bfloat16 g_owTlo[(size_t)VV*DD];
__device__ alignas(16) __nv_bfloat16 g_w1Thi[(size_t)LLN*EE*FFD*DD];
__device__ alignas(16) __nv_bfloat16 g_w1Tlo[(size_t)LLN*EE*FFD*DD];
__device__ alignas(16) __nv_bfloat16 g_w2Thi[(size_t)LLN*EE*DD*FFD];
__device__ alignas(16) __nv_bfloat16 g_w2Tlo[(size_t)LLN*EE*DD*FFD];
__device__ alignas(16) __nv_bfloat16 g_h1hi[(size_t)EE*NTOK*FFD];
__device__ alignas(16) __nv_bfloat16 g_h1lo[(size_t)EE*NTOK*FFD];
__device__ alignas(16) __nv_bfloat16 g_wqThi[LLN*DD*DD];
__device__ alignas(16) __nv_bfloat16 g_wqTlo[LLN*DD*DD];
__device__ alignas(16) __nv_bfloat16 g_wkThi[LLN*DD*DD];
__device__ alignas(16) __nv_bfloat16 g_wkTlo[LLN*DD*DD];
__device__ alignas(16) __nv_bfloat16 g_wvThi[LLN*DD*DD];
__device__ alignas(16) __nv_bfloat16 g_wvTlo[LLN*DD*DD];
__device__ alignas(16) __nv_bfloat16 g_woThi[LLN*DD*DD];
__device__ alignas(16) __nv_bfloat16 g_woTlo[LLN*DD*DD];
__device__ alignas(16) __nv_bfloat16 g_iqThi[LLN*HHI*DII*DD];
__device__ alignas(16) __nv_bfloat16 g_iqTlo[LLN*HHI*DII*DD];
__device__ alignas(16) __nv_bfloat16 g_ikThi[LLN*HHI*DII*DD];
__device__ alignas(16) __nv_bfloat16 g_ikTlo[LLN*HHI*DII*DD];

__device__ __forceinline__ float gelu_tanh(float x){
    float x3 = x*x*x;
    return 0.5f*x*(1.f + tanhf(0.7978845608028654f*(x + 0.044715f*x3)));
}

__global__ void k_embed(const int* __restrict__ ids, const float* __restrict__ tok, const float* __restrict__ pos){
    int n=blockIdx.x, t=threadIdx.x;
    g_x[(size_t)n*DD+t] = tok[(size_t)ids[n]*DD+t] + pos[(size_t)(n%SSL)*DD+t];
}

__global__ __launch_bounds__(256) void k_ln(float* __restrict__ in, const float* __restrict__ g,
        const float* __restrict__ b, float* __restrict__ out,
        __nv_bfloat16* __restrict__ hi, __nv_bfloat16* __restrict__ lo,
        const float* __restrict__ radd, int* __restrict__ ecz){
    int r=blockIdx.x, t=threadIdx.x;
    int lane=t&31, wid=t>>5;
    __shared__ float red1[8], red2[8];
    if(ecz && r==0 && t<EE) ecz[t]=0;
    float v0=in[(size_t)r*DD+t], v1=in[(size_t)r*DD+t+256];
    if(radd){
        v0 += radd[(size_t)r*DD+t];
        v1 += radd[(size_t)r*DD+t+256];
        in[(size_t)r*DD+t]=v0;
        in[(size_t)r*DD+t+256]=v1;
    }
    float s=v0+v1;
    #pragma unroll
    for(int off=16;off>0;off>>=1) s+=__shfl_xor_sync(0xffffffffu,s,off);
    if(lane==0) red1[wid]=s;
    __syncthreads();
    float mu=(red1[0]+red1[1]+red1[2]+red1[3]+red1[4]+red1[5]+red1[6]+red1[7])*(1.0f/DD);
    float d0=v0-mu, d1=v1-mu;
    float s2=d0*d0+d1*d1;
    #pragma unroll
    for(int off=16;off>0;off>>=1) s2+=__shfl_xor_sync(0xffffffffu,s2,off);
    if(lane==0) red2[wid]=s2;
    __syncthreads();
    float var=(red2[0]+red2[1]+red2[2]+red2[3]+red2[4]+red2[5]+red2[6]+red2[7])*(1.0f/DD);
    float rs=rsqrtf(var+EPSV);
    float o0=d0*rs*g[t]+b[t];
    float o1=d1*rs*g[t+256]+b[t+256];
    out[(size_t)r*DD+t]=o0;
    out[(size_t)r*DD+t+256]=o1;
    if(hi){
        __nv_bfloat16 h0=__float2bfloat16(o0), h1=__float2bfloat16(o1);
        hi[(size_t)r*DD+t]=h0;
        hi[(size_t)r*DD+t+256]=h1;
        lo[(size_t)r*DD+t]=__float2bfloat16(o0-__bfloat162float(h0));
        lo[(size_t)r*DD+t+256]=__float2bfloat16(o1-__bfloat162float(h1));
    }
}

// batched W[z][K][N] fp32 -> T[z][N][K] bf16 hi/lo
__global__ __launch_bounds__(256) void k_transcvtB(const float* __restrict__ W,
        __nv_bfloat16* __restrict__ Thi, __nv_bfloat16* __restrict__ Tlo, int K, int N){
    int z=blockIdx.z;
    W   += (size_t)z*K*N;
    Thi += (size_t)z*N*K;
    Tlo += (size_t)z*N*K;
    __shared__ float t[32][66];
    int n0=blockIdx.x*32, k0=blockIdx.y*64;
    int lane=threadIdx.x&31, wid=threadIdx.x>>5;
    #pragma unroll
    for(int i=0;i<8;i++){
        int kk=wid*8+i;
        t[lane][kk]=W[(size_t)(k0+kk)*N + n0+lane];
    }
    __syncthreads();
    #pragma unroll
    for(int j=0;j<4;j++){
        int n=wid*4+j;
        float2 ab=*(float2*)&t[n][2*lane];
        __nv_bfloat16 ha=__float2bfloat16(ab.x), hb=__float2bfloat16(ab.y);
        uint32_t hw=(uint32_t)__bfloat16_as_ushort(ha) | ((uint32_t)__bfloat16_as_ushort(hb)<<16);
        __nv_bfloat16 la=__float2bfloat16(ab.x-__bfloat162float(ha));
        __nv_bfloat16 lb=__float2bfloat16(ab.y-__bfloat162float(hb));
        uint32_t lw=(uint32_t)__bfloat16_as_ushort(la) | ((uint32_t)__bfloat16_as_ushort(lb)<<16);
        *(uint32_t*)(Thi + (size_t)(n0+n)*K + k0 + 2*lane)=hw;
        *(uint32_t*)(Tlo + (size_t)(n0+n)*K + k0 + 2*lane)=lw;
    }
}

// ================= HMMA primitives =================
__device__ __forceinline__ uint32_t smem_u32(const void* p){
    uint32_t a;
    asm("{ .reg .u64 t; cvta.to.shared.u64 t, %1; cvt.u32.u64 %0, t; }" : "=r"(a) : "l"(p));
    return a;
}
__device__ __forceinline__ void ldsm4(uint32_t (&r)[4], uint32_t a){
    asm volatile("ldmatrix.sync.aligned.m8n8.x4.shared.b16 {%0,%1,%2,%3}, [%4];"
        : "=r"(r[0]),"=r"(r[1]),"=r"(r[2]),"=r"(r[3]) : "r"(a));
}
__device__ __forceinline__ void ldsm2(uint32_t (&r)[2], uint32_t a){
    asm volatile("ldmatrix.sync.aligned.m8n8.x2.shared.b16 {%0,%1}, [%2];"
        : "=r"(r[0]),"=r"(r[1]) : "r"(a));
}
__device__ __forceinline__ void mma16816(float (&c)[4], const uint32_t (&a)[4], const uint32_t (&b)[2]){
    asm volatile("mma.sync.aligned.m16n8k16.row.col.f32.bf16.bf16.f32 "
        "{%0,%1,%2,%3}, {%4,%5,%6,%7}, {%8,%9}, {%0,%1,%2,%3};"
        : "+f"(c[0]),"+f"(c[1]),"+f"(c[2]),"+f"(c[3])
        : "r"(a[0]),"r"(a[1]),"r"(a[2]),"r"(a[3]), "r"(b[0]),"r"(b[1]));
}
__device__ __forceinline__ void cpasync16(uint32_t dst, const void* src){
    asm volatile("{ .reg .u64 g; cvta.to.global.u64 g, %1; cp.async.ca.shared.global [%0], [g], 16; }"
        :: "r"(dst), "l"(src));
}
#define HS_BUF 24576
#define HS_TILE 6144
#define HS_TOTAL 49664

__device__ __forceinline__ void hmma_main(char* sm, const int* rowidx,
    const __nv_bfloat16* __restrict__ Ahi, const __nv_bfloat16* __restrict__ Alo, int sA,
    const __nv_bfloat16* __restrict__ Bhi, const __nv_bfloat16* __restrict__ Blo, int sB,
    int col0, int K, float (&acc)[4][4][4])
{
    int tid=threadIdx.x, lane=tid&31, warp=tid>>5;
    int wm=warp>>2, wn=warp&3;
    uint32_t smb = smem_u32(sm);
    #pragma unroll
    for(int i=0;i<4;i++)
        #pragma unroll
        for(int j=0;j<4;j++)
            #pragma unroll
            for(int q=0;q<4;q++) acc[i][j][q]=0.f;

    int ltile[4], lrow[4], lhalf[4];
    #pragma unroll
    for(int t=0;t<4;t++){
        int i = tid + t*256;
        ltile[t]=i>>8; lrow[t]=(i&255)>>1; lhalf[t]=(i&1)*8;
    }
    uint4 pre[4];
    const int NS = K>>4;
    int lb = lane&15;
    uint32_t boff = (uint32_t)((wn*32 + (lb&7))*48 + ((lb&8)?16:0));
    uint32_t aoff = (uint32_t)((wm*64 + (lane&7) + ((lane&8)?8:0))*48 + ((lane&16)?16:0));

    auto ldg = [&](int s){
        int k0 = s<<4;
        #pragma unroll
        for(int t=0;t<4;t++){
            const __nv_bfloat16* src;
            int row=lrow[t];
            if(ltile[t]==0)      src = Ahi + (size_t)rowidx[row]*sA;
            else if(ltile[t]==1) src = Alo + (size_t)rowidx[row]*sA;
            else if(ltile[t]==2) src = Bhi + (size_t)(col0+row)*sB;
            else                 src = Blo + (size_t)(col0+row)*sB;
            pre[t] = *(const uint4*)(src + k0 + lhalf[t]);
        }
    };
    auto sts = [&](int b){
        #pragma unroll
        for(int t=0;t<4;t++)
            *(uint4*)(sm + b*HS_BUF + ltile[t]*HS_TILE + lrow[t]*48 + lhalf[t]*2) = pre[t];
    };
    ldg(0); sts(0);
    __syncthreads();
    for(int s=0;s<NS;s++){
        int b=s&1;
        if(s+1<NS) ldg(s+1);
        uint32_t base = smb + b*HS_BUF;
        uint32_t bh[4][2], bl[4][2];
        #pragma unroll
        for(int j=0;j<4;j++){
            ldsm2(bh[j], base + 2*HS_TILE + boff + j*8*48);
            ldsm2(bl[j], base + 3*HS_TILE + boff + j*8*48);
        }
        #pragma unroll
        for(int i=0;i<4;i++){
            uint32_t a[4];
            ldsm4(a, base + aoff + i*16*48);
            #pragma unroll
            for(int j=0;j<4;j++){ mma16816(acc[i][j], a, bh[j]); mma16816(acc[i][j], a, bl[j]); }
            ldsm4(a, base + HS_TILE + aoff + i*16*48);
            #pragma unroll
            for(int j=0;j<4;j++) mma16816(acc[i][j], a, bh[j]);
        }
        if(s+1<NS) sts(b^1);
        __syncthreads();
    }
}

// ---- vocab: 128x256 tile, cp.async pipeline; grid (NTOK/128, VV/256) ----
#define V_BUF 36864
#define V_TOTAL 73728
__global__ __launch_bounds__(256,1) void k_hmma_vocab(const float* __restrict__ ob, float* __restrict__ out){
    extern __shared__ char sm[];
    int tid=threadIdx.x, lane=tid&31, warp=tid>>5;
    int wm=warp>>2, wn=warp&3;
    int row0=blockIdx.x*128, col0=blockIdx.y*256;
    uint32_t smb = smem_u32(sm);
    float acc[4][8][4];
    #pragma unroll
    for(int i=0;i<4;i++)
        #pragma unroll
        for(int j=0;j<8;j++)
            #pragma unroll
            for(int q=0;q<4;q++) acc[i][j][q]=0.f;

    auto load_stage = [&](int s, int b){
        int k0 = s<<4;
        #pragma unroll
        for(int c=0;c<6;c++){
            int i = tid + c*256;
            const __nv_bfloat16* src; uint32_t dst;
            if(i<512){
                int tile=i>>8, rem=i&255, row=rem>>1, half=(rem&1)*8;
                src = (tile? g_hlo : g_hhi) + (size_t)(row0+row)*DD + k0 + half;
                dst = smb + b*V_BUF + tile*6144 + row*48 + half*2;
            }else{
                int ii=i-512, tile=ii>>9, rem=ii&511, row=rem>>1, half=(rem&1)*8;
                src = (tile? g_owTlo : g_owThi) + (size_t)(col0+row)*DD + k0 + half;
                dst = smb + b*V_BUF + 12288 + tile*12288 + row*48 + half*2;
            }
            cpasync16(dst, src);
        }
        asm volatile("cp.async.commit_group;" ::: "memory");
    };
    load_stage(0,0);
    asm volatile("cp.async.wait_group 0;" ::: "memory");
    __syncthreads();

    int lb = lane&15;
    uint32_t boff = (uint32_t)((wn*64 + (lb&7))*48 + ((lb&8)?16:0));
    uint32_t aoff = (uint32_t)((wm*64 + (lane&7) + ((lane&8)?8:0))*48 + ((lane&16)?16:0));
    const int NS = DD>>4;
    for(int s=0;s<NS;s++){
        int b=s&1;
        if(s+1<NS) load_stage(s+1, b^1);
        uint32_t base = smb + b*V_BUF;
        uint32_t bh[8][2], bl[8][2];
        #pragma unroll
        for(int j=0;j<8;j++){
            ldsm2(bh[j], base + 12288 + boff + j*8*48);
            ldsm2(bl[j], base + 24576 + boff + j*8*48);
        }
        #pragma unroll
        for(int i=0;i<4;i++){
            uint32_t a[4];
            ldsm4(a, base + aoff + i*16*48);
            #pragma unroll
            for(int j=0;j<8;j++){ mma16816(acc[i][j], a, bh[j]); mma16816(acc[i][j], a, bl[j]); }
            ldsm4(a, base + 6144 + aoff + i*16*48);
            #pragma unroll
            for(int j=0;j<8;j++) mma16816(acc[i][j], a, bh[j]);
        }
        if(s+1<NS) asm volatile("cp.async.wait_group 0;" ::: "memory");
        __syncthreads();
    }
    #pragma unroll
    for(int i=0;i<4;i++){
        int r0 = row0 + wm*64 + i*16 + (lane>>2);
        #pragma unroll
        for(int j=0;j<8;j++){
            int c = col0 + wn*64 + j*8 + (lane&3)*2;
            float b0=ob[c], b1=ob[c+1];
            out[(size_t)r0*VV + c]       = acc[i][j][0] + b0;
            out[(size_t)r0*VV + c+1]     = acc[i][j][1] + b1;
            out[(size_t)(r0+8)*VV + c]   = acc[i][j][2] + b0;
            out[(size_t)(r0+8)*VV + c+1] = acc[i][j][3] + b1;
        }
    }
}

// ---- generic projection: fp32 out, 3-way batched ----
struct H3 {
    const __nv_bfloat16 *h0,*l0,*h1,*l1,*h2,*l2;
    const float *c0,*c1,*c2;
    float *o0,*o1,*o2;
};
__global__ __launch_bounds__(256,1) void k_hmma_proj(H3 p, int N){
    extern __shared__ char sm[];
    int* rowidx = (int*)(sm + 2*HS_BUF);
    int tid=threadIdx.x;
    int row0=blockIdx.y*128, col0=blockIdx.x*128;
    const __nv_bfloat16 *Bh,*Bl; const float* bias; float* out;
    if(blockIdx.z==0){Bh=p.h0;Bl=p.l0;bias=p.c0;out=p.o0;}
    else if(blockIdx.z==1){Bh=p.h1;Bl=p.l1;bias=p.c1;out=p.o1;}
    else {Bh=p.h2;Bl=p.l2;bias=p.c2;out=p.o2;}
    if(tid<128) rowidx[tid]=row0+tid;
    __syncthreads();
    float acc[4][4][4];
    hmma_main(sm, rowidx, g_hhi, g_hlo, DD, Bh, Bl, DD, col0, DD, acc);
    int lane=tid&31, warp=tid>>5, wm=warp>>2, wn=warp&3;
    #pragma unroll
    for(int i=0;i<4;i++){
        int r0 = row0 + wm*64 + i*16 + (lane>>2);
        #pragma unroll
        for(int j=0;j<4;j++){
            int c = col0 + wn*32 + j*8 + (lane&3)*2;
            float b0=bias[c], b1=bias[c+1];
            out[(size_t)r0*N + c]       = acc[i][j][0] + b0;
            out[(size_t)r0*N + c+1]     = acc[i][j][1] + b1;
            out[(size_t)(r0+8)*N + c]   = acc[i][j][2] + b0;
            out[(size_t)(r0+8)*N + c+1] = acc[i][j][3] + b1;
        }
    }
}

// ---- O projection with residual ----
__global__ __launch_bounds__(256,1) void k_hmma_oproj(const __nv_bfloat16* __restrict__ Whi,
        const __nv_bfloat16* __restrict__ Wlo, const float* __restrict__ bias, float* __restrict__ x){
    extern __shared__ char sm[];
    int* rowidx = (int*)(sm + 2*HS_BUF);
    int tid=threadIdx.x;
    int row0=blockIdx.y*128, col0=blockIdx.x*128;
    if(tid<128) rowidx[tid]=row0+tid;
    __syncthreads();
    float acc[4][4][4];
    hmma_main(sm, rowidx, g_aohi, g_aolo, DD, Whi, Wlo, DD, col0, DD, acc);
    int lane=tid&31, warp=tid>>5, wm=warp>>2, wn=warp&3;
    #pragma unroll
    for(int i=0;i<4;i++){
        int r0 = row0 + wm*64 + i*16 + (lane>>2);
        #pragma unroll
        for(int j=0;j<4;j++){
            int c = col0 + wn*32 + j*8 + (lane&3)*2;
            float b0=bias[c], b1=bias[c+1];
            x[(size_t)r0*DD + c]       += acc[i][j][0] + b0;
            x[(size_t)r0*DD + c+1]     += acc[i][j][1] + b1;
            x[(size_t)(r0+8)*DD + c]   += acc[i][j][2] + b0;
            x[(size_t)(r0+8)*DD + c+1] += acc[i][j][3] + b1;
        }
    }
}

// ---- MoE1 ----
__global__ __launch_bounds__(256,1) void k_hmma_moe1(const __nv_bfloat16* __restrict__ Whi,
        const __nv_bfloat16* __restrict__ Wlo, const float* __restrict__ B1){
    int e=blockIdx.z, cnt=g_ecount[e], row0=blockIdx.x*128;
    if(row0>=cnt) return;
    extern __shared__ char sm[];
    int* rowidx = (int*)(sm + 2*HS_BUF);
    int tid=threadIdx.x;
    int col0=blockIdx.y*128;
    if(tid<128){
        int r=row0+tid;
        rowidx[tid] = (r<cnt)? g_elist[e*NTOK+r] : g_elist[e*NTOK];
    }
    __syncthreads();
    float acc[4][4][4];
    hmma_main(sm, rowidx, g_mhi, g_mlo, DD,
              Whi+(size_t)e*FFD*DD, Wlo+(size_t)e*FFD*DD, DD, col0, DD, acc);
    const float* bia = B1 + (size_t)e*FFD;
    int lane=tid&31, warp=tid>>5, wm=warp>>2, wn=warp&3;
    #pragma unroll
    for(int i=0;i<4;i++){
        int r0 = row0 + wm*64 + i*16 + (lane>>2);
        #pragma unroll
        for(int j=0;j<4;j++){
            int c = col0 + wn*32 + j*8 + (lane&3)*2;
            float b0=bia[c], b1=bia[c+1];
            #pragma unroll
            for(int q=0;q<4;q++){
                int r = r0 + (q>=2?8:0);
                if(r>=cnt) continue;
                int cc = c + (q&1);
                float v = gelu_tanh(acc[i][j][q] + ((q&1)?b1:b0));
                __nv_bfloat16 h=__float2bfloat16(v);
                size_t o = ((size_t)e*NTOK + r)*FFD + cc;
                g_h1hi[o]=h; g_h1lo[o]=__float2bfloat16(v-__bfloat162float(h));
            }
        }
    }
}

// ---- MoE2 ----
__global__ __launch_bounds__(256,1) void k_hmma_moe2(const __nv_bfloat16* __restrict__ Whi,
        const __nv_bfloat16* __restrict__ Wlo, const float* __restrict__ B2){
    int e=blockIdx.z, cnt=g_ecount[e], row0=blockIdx.x*128;
    if(row0>=cnt) return;
    extern __shared__ char sm[];
    int* rowidx = (int*)(sm + 2*HS_BUF);
    int tid=threadIdx.x;
    int col0=blockIdx.y*128;
    if(tid<128) rowidx[tid] = e*NTOK + row0 + tid;
    __syncthreads();
    float acc[4][4][4];
    hmma_main(sm, rowidx, g_h1hi, g_h1lo, FFD,
              Whi+(size_t)e*DD*FFD, Wlo+(size_t)e*DD*FFD, FFD, col0, FFD, acc);
    const float* bia = B2 + (size_t)e*DD;
    int lane=tid&31, warp=tid>>5, wm=warp>>2, wn=warp&3;
    #pragma unroll
    for(int i=0;i<4;i++){
        int r0 = row0 + wm*64 + i*16 + (lane>>2);
        #pragma unroll
        for(int j=0;j<4;j++){
            int c = col0 + wn*32 + j*8 + (lane&3)*2;
            float b0=bia[c], b1=bia[c+1];
            #pragma unroll
            for(int q=0;q<4;q++){
                int r = r0 + (q>=2?8:0);
                if(r>=cnt) continue;
                int tok=g_elist[e*NTOK+r];
                float gv=g_egate[e*NTOK+r];
                int cc = c + (q&1);
                atomicAdd(&g_moe[(size_t)tok*DD+cc], gv*(acc[i][j][q] + ((q&1)?b1:b0)));
            }
        }
    }
}

// ===== indexer scores (causal tile-skip) =====
__global__ __launch_bounds__(256) void k_idxscore(const float* __restrict__ hw){
    int kt=blockIdx.x, qt=blockIdx.y, b=blockIdx.z;
    int tx=threadIdx.x&15, ty=threadIdx.x>>4;
    if(kt>qt){
        #pragma unroll
        for(int i=0;i<4;i++){
            int q=qt*64+ty*4+i;
            float4 nv={NEGV,NEGV,NEGV,NEGV};
            *(float4*)&g_mask[((size_t)b*SSL+q)*SSL + kt*64+tx*4]=nv;
        }
        return;
    }
    __shared__ float Qs[64][68];
    __shared__ float Ks[64][68];
    float acc[4][4]={};
    for(int h=0;h<HHI;h++){
        for(int i=threadIdx.x;i<4096;i+=256){
            int r=i>>6, d=i&63;
            Qs[d][r]=g_qi[(size_t)(b*SSL+qt*64+r)*(HHI*DII)+h*64+d];
            Ks[d][r]=g_ki[(size_t)(b*SSL+kt*64+r)*(HHI*DII)+h*64+d];
        }
        __syncthreads();
        float w=hw[h];
        float dot[4][4]={};
        #pragma unroll 8
        for(int d=0;d<64;d++){
            float4 a4=*(const float4*)&Qs[d][ty*4];
            float4 b4=*(const float4*)&Ks[d][tx*4];
            float a[4]={a4.x,a4.y,a4.z,a4.w};
            float bb[4]={b4.x,b4.y,b4.z,b4.w};
            #pragma unroll
            for(int i=0;i<4;i++)
                #pragma unroll
                for(int j=0;j<4;j++) dot[i][j]+=a[i]*bb[j];
        }
        #pragma unroll
        for(int i=0;i<4;i++)
            #pragma unroll
            for(int j=0;j<4;j++) acc[i][j]+=fmaxf(dot[i][j],0.f)*w;
        __syncthreads();
    }
    #pragma unroll
    for(int i=0;i<4;i++){
        int q=qt*64+ty*4+i;
        #pragma unroll
        for(int j=0;j<4;j++){
            int k=kt*64+tx*4+j;
            g_mask[((size_t)b*SSL+q)*SSL+k]=acc[i][j]+((k<=q)?0.f:NEGV);
        }
    }
}

// ===== top-K: rows with <=K causal candidates skip the sort entirely =====
__global__ __launch_bounds__(512) void k_topk(){
    int q=blockIdx.x, b=blockIdx.y, t=threadIdx.x;
    size_t base=((size_t)b*SSL+q)*SSL;
    if(q < KTOP){
        // all causal candidates are within top-K: mask = causal
        for(int k=t;k<SSL;k+=512)
            g_mask[base+k]=(k<=q)?0.f:NEGV;
        return;
    }
    __shared__ float s[1024];
    s[t]=g_mask[base+t];
    s[t+512]=g_mask[base+t+512];
    __syncthreads();
    for(int size=2;size<=1024;size<<=1){
        for(int stride=size>>1;stride>0;stride>>=1){
            int lo=2*stride*(t/stride)+(t%stride);
            int hi=lo+stride;
            bool desc=((lo&size)==0);
            float a=s[lo], bv=s[hi];
            if((a<bv)==desc){ s[lo]=bv; s[hi]=a; }
            __syncthreads();
        }
    }
    float thr=s[KTOP-1];
    for(int k=t;k<SSL;k+=512){
        float v=g_mask[base+k];
        g_mask[base+k]=(k<=q && v>=thr)?0.f:NEGV;
    }
}

// ===== attention =====
__global__ __launch_bounds__(256) void k_attn(){
    int qt=blockIdx.x, h=blockIdx.y, b=blockIdx.z;
    int t=threadIdx.x, row=t>>4, cg=t&15;
    __shared__ float qs[16][68];
    __shared__ float Ks[64][68];
    __shared__ float Vs[64][68];
    __shared__ float Sc[16][68];
    __shared__ float mrow[16], lrow[16];
    int q0=qt*16;
    for(int i=t;i<16*64;i+=256){
        int r=i>>6, d=i&63;
        qs[r][d]=g_q[(size_t)(b*SSL+q0+r)*DD+h*64+d];
    }
    if(t<16){ mrow[t]=-1e30f; lrow[t]=0.f; }
    float oacc[4]={0.f,0.f,0.f,0.f};
    __syncthreads();
    const float* maskrow=g_mask+((size_t)b*SSL+(q0+row))*SSL;
    int kmax = q0 + 16;
    for(int k0=0;k0<kmax;k0+=64){
        for(int i=t;i<4096;i+=256){
            int r=i>>6, d=i&63;
            Ks[r][d]=g_k[(size_t)(b*SSL+k0+r)*DD+h*64+d];
            Vs[r][d]=g_v[(size_t)(b*SSL+k0+r)*DD+h*64+d];
        }
        __syncthreads();
        float sv[4]={0.f,0.f,0.f,0.f};
        #pragma unroll
        for(int d0=0;d0<64;d0+=4){
            float4 q4=*(const float4*)&qs[row][d0];
            #pragma unroll
            for(int j=0;j<4;j++){
                float4 k4=*(const float4*)&Ks[j*16+cg][d0];
                sv[j]+=q4.x*k4.x+q4.y*k4.y+q4.z*k4.z+q4.w*k4.w;
            }
        }
        #pragma unroll
        for(int j=0;j<4;j++) sv[j]=sv[j]*SCALE+maskrow[k0+j*16+cg];
        float mold=mrow[row], lold=lrow[row];
        float tmax=fmaxf(fmaxf(sv[0],sv[1]),fmaxf(sv[2],sv[3]));
        tmax=fmaxf(tmax,mold);
        #pragma unroll
        for(int off=8;off>0;off>>=1) tmax=fmaxf(tmax,__shfl_xor_sync(0xffffffffu,tmax,off,16));
        float c=__expf(mold-tmax);
        float lsum=0.f;
        #pragma unroll
        for(int j=0;j<4;j++){
            float p=__expf(sv[j]-tmax);
            Sc[row][j*16+cg]=p;
            lsum+=p;
        }
        #pragma unroll
        for(int off=8;off>0;off>>=1) lsum+=__shfl_xor_sync(0xffffffffu,lsum,off,16);
        if(cg==0){ mrow[row]=tmax; lrow[row]=lold*c+lsum; }
        __syncwarp();
        #pragma unroll
        for(int j=0;j<4;j++) oacc[j]*=c;
        #pragma unroll
        for(int k=0;k<64;k++){
            float s=Sc[row][k];
            float4 v4=*(const float4*)&Vs[k][cg*4];
            oacc[0]+=s*v4.x; oacc[1]+=s*v4.y; oacc[2]+=s*v4.z; oacc[3]+=s*v4.w;
        }
        __syncthreads();
    }
    float linv=1.0f/lrow[row];
    size_t ob = (size_t)(b*SSL+q0+row)*DD + h*64 + cg*4;
    #pragma unroll
    for(int j=0;j<4;j++){
        float v = oacc[j]*linv;
        __nv_bfloat16 hh=__float2bfloat16(v);
        g_aohi[ob+j]=hh;
        g_aolo[ob+j]=__float2bfloat16(v-__bfloat162float(hh));
    }
}

// ===== fused router =====
__global__ __launch_bounds__(256) void k_router(const float* __restrict__ rw, const float* __restrict__ rb){
    int n=blockIdx.x;
    int t=threadIdx.x, e=t>>5, lane=t&31;
    __shared__ float ms[DD];
    __shared__ float pe[EE];
    for(int i=t;i<DD;i+=256) ms[i]=g_m[(size_t)n*DD+i];
    g_moe[(size_t)n*DD+t]=0.f;
    g_moe[(size_t)n*DD+t+256]=0.f;
    __syncthreads();
    float s=0.f;
    for(int k=lane;k<DD;k+=32) s+=ms[k]*rw[k*EE+e];
    #pragma unroll
    for(int off=16;off>0;off>>=1) s+=__shfl_xor_sync(0xffffffffu,s,off);
    if(lane==0) pe[e]=s+rb[e];
    __syncthreads();
    if(t==0){
        float p[EE]; float mx=-1e30f;
        #pragma unroll
        for(int i=0;i<EE;i++){ p[i]=pe[i]; mx=fmaxf(mx,p[i]); }
        #pragma unroll
        for(int i=0;i<EE;i++) p[i]=__expf(p[i]-mx);
        int e1=0;
        for(int i=1;i<EE;i++) if(p[i]>p[e1]) e1=i;
        int e2=-1;
        for(int i=0;i<EE;i++) if(i!=e1 && (e2<0 || p[i]>p[e2])) e2=i;
        float den=p[e1]+p[e2];
        int pos=atomicAdd(&g_ecount[e1],1);
        g_elist[e1*NTOK+pos]=n; g_egate[e1*NTOK+pos]=p[e1]/den;
        pos=atomicAdd(&g_ecount[e2],1);
        g_elist[e2*NTOK+pos]=n; g_egate[e2*NTOK+pos]=p[e2]/den;
    }
}

// ===== host =====
extern "C" void kernel_launch(void* const* d_in, const int* in_sizes, int n_in,
                              void* d_out, int out_size){
    (void)in_sizes; (void)n_in; (void)out_size;
    const int*   ids  = (const int*)  d_in[0];
    const float* tok  = (const float*)d_in[1];
    const float* pos  = (const float*)d_in[2];
    const float* ln1g = (const float*)d_in[3];
    const float* ln1b = (const float*)d_in[4];
    const float* iqw  = (const float*)d_in[5];
    const float* iqb  = (const float*)d_in[6];
    const float* ikw  = (const float*)d_in[7];
    const float* ikb  = (const float*)d_in[8];
    const float* ihw  = (const float*)d_in[9];
    const float* wq   = (const float*)d_in[10];
    const float* bq   = (const float*)d_in[11];
    const float* wk   = (const float*)d_in[12];
    const float* bk   = (const float*)d_in[13];
    const float* wv   = (const float*)d_in[14];
    const float* bv   = (const float*)d_in[15];
    const float* wo   = (const float*)d_in[16];
    const float* bo   = (const float*)d_in[17];
    const float* ln2g = (const float*)d_in[18];
    const float* ln2b = (const float*)d_in[19];
    const float* rw   = (const float*)d_in[20];
    const float* rb   = (const float*)d_in[21];
    const float* ew1  = (const float*)d_in[22];
    const float* eb1  = (const float*)d_in[23];
    const float* ew2  = (const float*)d_in[24];
    const float* eb2  = (const float*)d_in[25];
    const float* lnfg = (const float*)d_in[26];
    const float* lnfb = (const float*)d_in[27];
    const float* ow   = (const float*)d_in[28];
    const float* ob   = (const float*)d_in[29];
    float* out = (float*)d_out;

    float *px,*ph,*pm,*pq,*pk,*pv,*pmoe,*pqi,*pki;
    int *pec;
    __nv_bfloat16 *phhi,*phlo,*pmhi,*pmlo,*powThi,*powTlo,*pw1Thi,*pw1Tlo,*pw2Thi,*pw2Tlo;
    __nv_bfloat16 *pwqh,*pwql,*pwkh,*pwkl,*pwvh,*pwvl,*pwoh,*pwol,*piqh,*piql,*pikh,*pikl;
    cudaGetSymbolAddress((void**)&px,g_x);
    cudaGetSymbolAddress((void**)&ph,g_h);
    cudaGetSymbolAddress((void**)&pm,g_m);
    cudaGetSymbolAddress((void**)&pq,g_q);
    cudaGetSymbolAddress((void**)&pk,g_k);
    cudaGetSymbolAddress((void**)&pv,g_v);
    cudaGetSymbolAddress((void**)&pmoe,g_moe);
    cudaGetSymbolAddress((void**)&pqi,g_qi);
    cudaGetSymbolAddress((void**)&pki,g_ki);
    cudaGetSymbolAddress((void**)&pec,g_ecount);
    cudaGetSymbolAddress((void**)&phhi,g_hhi);
    cudaGetSymbolAddress((void**)&phlo,g_hlo);
    cudaGetSymbolAddress((void**)&pmhi,g_mhi);
    cudaGetSymbolAddress((void**)&pmlo,g_mlo);
    cudaGetSymbolAddress((void**)&powThi,g_owThi);
    cudaGetSymbolAddress((void**)&powTlo,g_owTlo);
    cudaGetSymbolAddress((void**)&pw1Thi,g_w1Thi);
    cudaGetSymbolAddress((void**)&pw1Tlo,g_w1Tlo);
    cudaGetSymbolAddress((void**)&pw2Thi,g_w2Thi);
    cudaGetSymbolAddress((void**)&pw2Tlo,g_w2Tlo);
    cudaGetSymbolAddress((void**)&pwqh,g_wqThi);
    cudaGetSymbolAddress((void**)&pwql,g_wqTlo);
    cudaGetSymbolAddress((void**)&pwkh,g_wkThi);
    cudaGetSymbolAddress((void**)&pwkl,g_wkTlo);
    cudaGetSymbolAddress((void**)&pwvh,g_wvThi);
    cudaGetSymbolAddress((void**)&pwvl,g_wvTlo);
    cudaGetSymbolAddress((void**)&pwoh,g_woThi);
    cudaGetSymbolAddress((void**)&pwol,g_woTlo);
    cudaGetSymbolAddress((void**)&piqh,g_iqThi);
    cudaGetSymbolAddress((void**)&piql,g_iqTlo);
    cudaGetSymbolAddress((void**)&pikh,g_ikThi);
    cudaGetSymbolAddress((void**)&pikl,g_ikTlo);

    cudaFuncSetAttribute(k_hmma_vocab, cudaFuncAttributeMaxDynamicSharedMemorySize, V_TOTAL);
    cudaFuncSetAttribute(k_hmma_proj,  cudaFuncAttributeMaxDynamicSharedMemorySize, HS_TOTAL);
    cudaFuncSetAttribute(k_hmma_oproj, cudaFuncAttributeMaxDynamicSharedMemorySize, HS_TOTAL);
    cudaFuncSetAttribute(k_hmma_moe1,  cudaFuncAttributeMaxDynamicSharedMemorySize, HS_TOTAL);
    cudaFuncSetAttribute(k_hmma_moe2,  cudaFuncAttributeMaxDynamicSharedMemorySize, HS_TOTAL);

    // weight transposes + bf16 splits
    k_transcvtB<<<dim3(VV/32, DD/64, 1),256>>>(ow, powThi, powTlo, DD, VV);
    k_transcvtB<<<dim3(FFD/32, DD/64, LLN*EE),256>>>(ew1, pw1Thi, pw1Tlo, DD, FFD);
    k_transcvtB<<<dim3(DD/32, FFD/64, LLN*EE),256>>>(ew2, pw2Thi, pw2Tlo, FFD, DD);
    k_transcvtB<<<dim3(DD/32, DD/64, LLN),256>>>(wq, pwqh, pwql, DD, DD);
    k_transcvtB<<<dim3(DD/32, DD/64, LLN),256>>>(wk, pwkh, pwkl, DD, DD);
    k_transcvtB<<<dim3(DD/32, DD/64, LLN),256>>>(wv, pwvh, pwvl, DD, DD);
    k_transcvtB<<<dim3(DD/32, DD/64, LLN),256>>>(wo, pwoh, pwol, DD, DD);
    k_transcvtB<<<dim3((HHI*DII)/32, DD/64, LLN),256>>>(iqw, piqh, piql, DD, HHI*DII);
    k_transcvtB<<<dim3((HHI*DII)/32, DD/64, LLN),256>>>(ikw, pikh, pikl, DD, HHI*DII);

    k_embed<<<NTOK,512>>>(ids, tok, pos);

    for(int l=0;l<LLN;l++){
        k_ln<<<NTOK,256>>>(px, ln1g+l*DD, ln1b+l*DD, ph, phhi, phlo,
                           (l>0)?pmoe:nullptr, nullptr);
        {   H3 p;
            p.h0=piqh+(size_t)l*HHI*DII*DD; p.l0=piql+(size_t)l*HHI*DII*DD; p.c0=iqb+l*HHI*DII; p.o0=pqi;
            p.h1=pikh+(size_t)l*HHI*DII*DD; p.l1=pikl+(size_t)l*HHI*DII*DD; p.c1=ikb+l*HHI*DII; p.o1=pki;
            p.h2=p.h0; p.l2=p.l0; p.c2=p.c0; p.o2=pqi;
            k_hmma_proj<<<dim3((HHI*DII)/128, NTOK/128, 2),256,HS_TOTAL>>>(p, HHI*DII);
        }
        k_idxscore<<<dim3(SSL/64,SSL/64,BB),256>>>(ihw+l*HHI);
        k_topk<<<dim3(SSL,BB),512>>>();
        {   H3 p;
            p.h0=pwqh+(size_t)l*DD*DD; p.l0=pwql+(size_t)l*DD*DD; p.c0=bq+l*DD; p.o0=pq;
            p.h1=pwkh+(size_t)l*DD*DD; p.l1=pwkl+(size_t)l*DD*DD; p.c1=bk+l*DD; p.o1=pk;
            p.h2=pwvh+(size_t)l*DD*DD; p.l2=pwvl+(size_t)l*DD*DD; p.c2=bv+l*DD; p.o2=pv;
            k_hmma_proj<<<dim3(DD/128, NTOK/128, 3),256,HS_TOTAL>>>(p, DD);
        }
        k_attn<<<dim3(SSL/16,HHN,BB),256>>>();
        k_hmma_oproj<<<dim3(DD/128, NTOK/128),256,HS_TOTAL>>>(
            pwoh+(size_t)l*DD*DD, pwol+(size_t)l*DD*DD, bo+l*DD, px);

        k_ln<<<NTOK,256>>>(px, ln2g+l*DD, ln2b+l*DD, pm, pmhi, pmlo, nullptr, pec);
        k_router<<<NTOK,256>>>(rw+(size_t)l*DD*EE, rb+l*EE);
        k_hmma_moe1<<<dim3(NTOK/128, FFD/128, EE),256,HS_TOTAL>>>(
            pw1Thi+(size_t)l*EE*FFD*DD, pw1Tlo+(size_t)l*EE*FFD*DD, eb1+(size_t)l*EE*FFD);
        k_hmma_moe2<<<dim3(NTOK/128, DD/128, EE),256,HS_TOTAL>>>(
            pw2Thi+(size_t)l*EE*DD*FFD, pw2Tlo+(size_t)l*EE*DD*FFD, eb2+(size_t)l*EE*DD);
    }

    k_ln<<<NTOK,256>>>(px, lnfg, lnfb, ph, phhi, phlo, pmoe, nullptr);
    k_hmma_vocab<<<dim3(NTOK/128, VV/256),256,V_TOTAL>>>(ob, out);
}